// round 12
// baseline (speedup 1.0000x reference)
#include <cuda_runtime.h>
#include <cuda_fp16.h>
#include <cstdint>

#define N_NODES 50000
#define N_EDGES 800000
#define D 256
#define T_REP 4
#define NS 64
#define N_TOT (5 * N_NODES)                 /* 250000 */
#define NE_TOT (2 * N_EDGES + 3 * N_NODES)  /* 1750000 */
#define SCAN_BLK 1024
#define NPAD 250112

typedef unsigned long long u64;

__device__ __forceinline__ uint32_t smem_to_u32(const void* p) {
    uint32_t a;
    asm("{ .reg .u64 t; cvta.to.shared.u64 t, %1; cvt.u32.u64 %0, t; }" : "=r"(a) : "l"(p));
    return a;
}

#define LDMATRIX_X4(r0, r1, r2, r3, addr) \
    asm volatile("ldmatrix.sync.aligned.m8n8.x4.shared.b16 {%0,%1,%2,%3}, [%4];" \
                 : "=r"(r0), "=r"(r1), "=r"(r2), "=r"(r3) : "r"(addr))

#define MMAF16(c, a, b0, b1) \
    asm volatile("mma.sync.aligned.m16n8k16.row.col.f32.f16.f16.f32 " \
                 "{%0,%1,%2,%3}, {%4,%5,%6,%7}, {%8,%9}, {%0,%1,%2,%3};" \
                 : "+f"((c)[0]), "+f"((c)[1]), "+f"((c)[2]), "+f"((c)[3]) \
                 : "r"((a)[0]), "r"((a)[1]), "r"((a)[2]), "r"((a)[3]), "r"(b0), "r"(b1))

#define CP16(dst, src, sz) \
    asm volatile("cp.async.cg.shared.global [%0], [%1], 16, %2;" \
                 :: "r"(dst), "l"(src), "r"(sz))
#define CP_COMMIT() asm volatile("cp.async.commit_group;" ::: "memory")
#define CP_WAIT1()  asm volatile("cp.async.wait_group 1;" ::: "memory")
#define CP_WAIT0()  asm volatile("cp.async.wait_group 0;" ::: "memory")

__device__ __forceinline__ void split2(float x, __half& h, __half& l) {
    h = __float2half_rn(x);
    l = __float2half_rn(x - __half2float(h));
}
__device__ __forceinline__ uint32_t hpack2(__half a, __half b) {
    return (uint32_t)__half_as_ushort(a) | ((uint32_t)__half_as_ushort(b) << 16);
}

// ---------------- scratch (device globals) ----------------
__device__ float g_AF[(size_t)N_TOT * D];
__device__ float g_X[(size_t)N_TOT * D];
__device__ float g_B[(size_t)N_TOT * D];
__device__ float g_invn[T_REP * N_NODES];
__device__ int   g_deg[N_TOT];              // in-edge count (no self loop)
__device__ float g_dinv[N_TOT];
__device__ int   g_best[N_EDGES];
__device__ int   g_cls[N_TOT];
__device__ float g_zerobias[D];
__device__ int   g_rowptr[N_TOT];
__device__ int   g_blocksum[256];
__device__ int   g_cursor[N_TOT];
__device__ int   g_csr_src[NE_TOT];
__device__ float g_csr_w[NE_TOT];
__device__ int   g_odeg[N_NODES];
__device__ int   g_orow[N_NODES];
__device__ int   g_ocur[N_NODES];
__device__ int   g_oedge[N_EDGES];
// fp16 split buffers: buf1 = GEMM activations (relu), buf2 = raw AF (for dots)
__device__ __half g_Ahi[(size_t)NPAD * D];
__device__ __half g_Alo[(size_t)NPAD * D];
__device__ __half g_Ahi2[(size_t)NPAD * D];
__device__ __half g_Alo2[(size_t)NPAD * D];
__device__ __half g_Whi[8 * 65536];
__device__ __half g_Wlo[8 * 65536];

// ---------------- small kernels ----------------

template<int RELU, int COPY, int B2>
__global__ void k_split(const float4* __restrict__ X, int n4) {
    int i = blockIdx.x * blockDim.x + threadIdx.x;
    if (i >= n4) return;
    float4 v = X[i];
    if (COPY) ((float4*)g_AF)[i] = v;
    if (B2) {
        __half h0,l0,h1,l1,h2,l2,h3,l3;
        split2(v.x,h0,l0); split2(v.y,h1,l1); split2(v.z,h2,l2); split2(v.w,h3,l3);
        ((uint2*)g_Ahi2)[i] = make_uint2(hpack2(h0,h1), hpack2(h2,h3));
        ((uint2*)g_Alo2)[i] = make_uint2(hpack2(l0,l1), hpack2(l2,l3));
    }
    float x0 = v.x, x1 = v.y, x2 = v.z, x3 = v.w;
    if (RELU) {
        x0 = fmaxf(x0, 0.f); x1 = fmaxf(x1, 0.f);
        x2 = fmaxf(x2, 0.f); x3 = fmaxf(x3, 0.f);
    }
    __half h0,l0,h1,l1,h2,l2,h3,l3;
    split2(x0,h0,l0); split2(x1,h1,l1); split2(x2,h2,l2); split2(x3,h3,l3);
    ((uint2*)g_Ahi)[i] = make_uint2(hpack2(h0,h1), hpack2(h2,h3));
    ((uint2*)g_Alo)[i] = make_uint2(hpack2(l0,l1), hpack2(l2,l3));
}

// split + transpose a [256 x ncols] weight into slot widxBase + blockIdx.y
__global__ void k_wsplit(const float* __restrict__ W, int widxBase, int ncols, int wstride) {
    int widx = widxBase + blockIdx.y;
    const float* Wz = W + (size_t)blockIdx.y * wstride;
    int i = blockIdx.x * 256 + threadIdx.x;
    int n = i >> 8, k = i & 255;
    float x = Wz[k * ncols + n];
    __half h, l;
    split2(x, h, l);
    g_Whi[widx * 65536 + i] = h;
    g_Wlo[widx * 65536 + i] = l;
}

__global__ void k_wsplit_dir(const float* __restrict__ src, int widx, int nelem) {
    int i = blockIdx.x * 256 + threadIdx.x;
    if (i >= nelem) return;
    __half h, l;
    split2(src[i], h, l);
    g_Whi[widx * 65536 + i] = h;
    g_Wlo[widx * 65536 + i] = l;
}

// ---- fp16x3 pipelined GEMM (N=256): C[M,256] = A @ W + bias ----
// K in 8 chunks of 32, double-buffered cp.async stages. Each loader thread
// copies TWO rows per buffer (rows lrow and lrow+64).
#define KSTR 40                                /* halves per row per stage */
#define ABUF (128 * KSTR)                      /* 5120 halves */
#define STAGE_H (4 * ABUF)                     /* 20480 halves = 40960 B */
#define SMG_BYTES (2 * STAGE_H * 2)            /* 81920 B */
template<int WS>
__global__ __launch_bounds__(256, 2) void k_mmagemm(
    const __half* Ahi, const __half* Alo,
    const __half* __restrict__ Whi, const __half* __restrict__ Wlo,
    const float* __restrict__ bias, float* __restrict__ C,
    int M, int wz, int cz, int bzs, int splitBase, int splitZ)
{
    extern __shared__ __half smh[];
    const int tid = threadIdx.x;
    const int warp = tid >> 5, lane = tid & 31;
    const int wm = warp & 1, wn = warp >> 1;
    const int z = blockIdx.z;
    const int rBase = blockIdx.y << 7;
    const int colBase = blockIdx.x << 7;

    const __half* Wh = Whi + (size_t)z * wz;
    const __half* Wl = Wlo + (size_t)z * wz;
    const __half* Asrc[2] = {Ahi, Alo};
    const __half* Bsrc[2] = {Wh, Wl};

    float acc[4][4][4];
#pragma unroll
    for (int i = 0; i < 4; i++)
#pragma unroll
        for (int j = 0; j < 4; j++)
#pragma unroll
            for (int q = 0; q < 4; q++) acc[i][j][q] = 0.f;

    const uint32_t u0 = smem_to_u32(smh);
    const int a_row_l = lane & 15;
    const int a_kh = (lane >> 4) << 3;
    const int b_n_off = (lane & 7) + ((lane >> 4) << 3);
    const int b_k_off = ((lane >> 3) & 1) << 3;
    const int lrow = tid >> 2, lseg = tid & 3;
    const int row0 = lrow, row1 = lrow + 64;
    const int gr0 = rBase + row0, gr1 = rBase + row1;
    const int gc0 = gr0 < M ? gr0 : 0, gc1 = gr1 < M ? gr1 : 0;
    const unsigned sz0 = gr0 < M ? 16u : 0u, sz1 = gr1 < M ? 16u : 0u;

    // prefetch chunk 0 -> stage 0
#pragma unroll
    for (int s = 0; s < 2; s++) {
        CP16(u0 + (uint32_t)(s * ABUF + row0 * KSTR + lseg * 8) * 2,
             Asrc[s] + (size_t)gc0 * 256 + lseg * 8, sz0);
        CP16(u0 + (uint32_t)(s * ABUF + row1 * KSTR + lseg * 8) * 2,
             Asrc[s] + (size_t)gc1 * 256 + lseg * 8, sz1);
        CP16(u0 + (uint32_t)((2 + s) * ABUF + row0 * KSTR + lseg * 8) * 2,
             Bsrc[s] + (size_t)(colBase + row0) * 256 + lseg * 8, 16u);
        CP16(u0 + (uint32_t)((2 + s) * ABUF + row1 * KSTR + lseg * 8) * 2,
             Bsrc[s] + (size_t)(colBase + row1) * 256 + lseg * 8, 16u);
    }
    CP_COMMIT();

#pragma unroll 1
    for (int c = 0; c < 8; c++) {
        if (c < 7) {
            const uint32_t stB = (uint32_t)(((c + 1) & 1) * STAGE_H) * 2;
            const int koff = (c + 1) * 32 + lseg * 8;
#pragma unroll
            for (int s = 0; s < 2; s++) {
                CP16(u0 + stB + (uint32_t)(s * ABUF + row0 * KSTR + lseg * 8) * 2,
                     Asrc[s] + (size_t)gc0 * 256 + koff, sz0);
                CP16(u0 + stB + (uint32_t)(s * ABUF + row1 * KSTR + lseg * 8) * 2,
                     Asrc[s] + (size_t)gc1 * 256 + koff, sz1);
                CP16(u0 + stB + (uint32_t)((2 + s) * ABUF + row0 * KSTR + lseg * 8) * 2,
                     Bsrc[s] + (size_t)(colBase + row0) * 256 + koff, 16u);
                CP16(u0 + stB + (uint32_t)((2 + s) * ABUF + row1 * KSTR + lseg * 8) * 2,
                     Bsrc[s] + (size_t)(colBase + row1) * 256 + koff, 16u);
            }
            CP_COMMIT();
            CP_WAIT1();
        } else {
            CP_WAIT0();
        }
        __syncthreads();
        const uint32_t st = (uint32_t)((c & 1) * STAGE_H) * 2;
        const uint32_t uAh = u0 + st;
        const uint32_t uAl = u0 + st + (uint32_t)ABUF * 2;
        const uint32_t uBh = u0 + st + (uint32_t)(2 * ABUF) * 2;
        const uint32_t uBl = u0 + st + (uint32_t)(3 * ABUF) * 2;
#pragma unroll
        for (int k = 0; k < 2; k++) {
            const int k0 = k << 4;
            const uint32_t aoff = (uint32_t)(((wm << 6) + a_row_l) * KSTR + k0 + a_kh) * 2;
            const uint32_t boff0 = (uint32_t)(((wn << 5) + b_n_off) * KSTR + k0 + b_k_off) * 2;
            const uint32_t boff1 = boff0 + (uint32_t)(16 * KSTR) * 2;
            uint32_t ah[4][4], al[4][4], bh[2][4], bl[2][4];
#pragma unroll
            for (int mi = 0; mi < 4; mi++) {
                LDMATRIX_X4(ah[mi][0], ah[mi][1], ah[mi][2], ah[mi][3],
                            uAh + aoff + (uint32_t)((mi << 4) * KSTR) * 2);
                LDMATRIX_X4(al[mi][0], al[mi][1], al[mi][2], al[mi][3],
                            uAl + aoff + (uint32_t)((mi << 4) * KSTR) * 2);
            }
            LDMATRIX_X4(bh[0][0], bh[0][1], bh[0][2], bh[0][3], uBh + boff0);
            LDMATRIX_X4(bh[1][0], bh[1][1], bh[1][2], bh[1][3], uBh + boff1);
            LDMATRIX_X4(bl[0][0], bl[0][1], bl[0][2], bl[0][3], uBl + boff0);
            LDMATRIX_X4(bl[1][0], bl[1][1], bl[1][2], bl[1][3], uBl + boff1);
#pragma unroll
            for (int mi = 0; mi < 4; mi++)
#pragma unroll
                for (int ni = 0; ni < 4; ni++) {
                    uint32_t b0h = bh[ni >> 1][(ni & 1) * 2], b1h = bh[ni >> 1][(ni & 1) * 2 + 1];
                    uint32_t b0l = bl[ni >> 1][(ni & 1) * 2], b1l = bl[ni >> 1][(ni & 1) * 2 + 1];
                    MMAF16(acc[mi][ni], ah[mi], b0h, b1h);
                    MMAF16(acc[mi][ni], ah[mi], b0l, b1l);
                    MMAF16(acc[mi][ni], al[mi], b0h, b1h);
                }
        }
        __syncthreads();
    }

    const float* bp = bias + (size_t)z * bzs;
    float* Cz = C + (size_t)z * cz;
#pragma unroll
    for (int mi = 0; mi < 4; mi++) {
#pragma unroll
        for (int hf2 = 0; hf2 < 2; hf2++) {
            int gr = rBase + (wm << 6) + (mi << 4) + (lane >> 2) + hf2 * 8;
            if (gr >= M) continue;
#pragma unroll
            for (int ni = 0; ni < 4; ni++) {
                int col = colBase + (wn << 5) + (ni << 3) + (lane & 3) * 2;
                float o0 = acc[mi][ni][hf2 * 2] + bp[col];
                float o1 = acc[mi][ni][hf2 * 2 + 1] + bp[col + 1];
                *(float2*)&Cz[(size_t)gr * 256 + col] = make_float2(o0, o1);
                if (WS) {
                    size_t so = (size_t)(splitBase + z * splitZ + gr) * 256 + col;
                    __half h0, l0, h1, l1;
                    split2(fmaxf(o0, 0.f), h0, l0);
                    split2(fmaxf(o1, 0.f), h1, l1);
                    *(uint32_t*)(g_Ahi + so) = hpack2(h0, h1);
                    *(uint32_t*)(g_Alo + so) = hpack2(l0, l1);
                    split2(o0, h0, l0);
                    split2(o1, h1, l1);
                    *(uint32_t*)(g_Ahi2 + so) = hpack2(h0, h1);
                    *(uint32_t*)(g_Alo2 + so) = hpack2(l0, l1);
                }
            }
        }
    }
}

// ---- fp16x3 pipelined GEMM (N=64): MODE 0 logits+fused argmax; MODE 1 *scale ----
#define BBUF64 (64 * KSTR)                    /* 2560 halves */
#define STAGE64_H (2 * ABUF + 2 * BBUF64)     /* 15360 halves */
#define SM64_BYTES (2 * STAGE64_H * 2)        /* 61440 B */
template<int MODE>
__global__ __launch_bounds__(256, 2) void k_mmagemm64(
    const __half* Ahi, const __half* Alo,
    const __half* __restrict__ Wh, const __half* __restrict__ Wl,
    const float* __restrict__ bias, float* __restrict__ C, int M, float scale)
{
    extern __shared__ __half smh[];
    __shared__ float sval[128];
    __shared__ int   sidx[128];
    const int tid = threadIdx.x;
    const int warp = tid >> 5, lane = tid & 31;
    const int wm = warp >> 1, wn = warp & 1;
    const int rBase = blockIdx.x << 7;

    const __half* Asrc[2] = {Ahi, Alo};
    const __half* Bsrc[2] = {Wh, Wl};

    float acc[2][4][4];
#pragma unroll
    for (int i = 0; i < 2; i++)
#pragma unroll
        for (int j = 0; j < 4; j++)
#pragma unroll
            for (int q = 0; q < 4; q++) acc[i][j][q] = 0.f;

    const uint32_t u0 = smem_to_u32(smh);
    const int a_row_l = lane & 15;
    const int a_kh = (lane >> 4) << 3;
    const int b_n_off = (lane & 7) + ((lane >> 4) << 3);
    const int b_k_off = ((lane >> 3) & 1) << 3;
    const int lrow = tid >> 2, lseg = tid & 3;
    const int row0 = lrow, row1 = lrow + 64;
    const int gr0 = rBase + row0, gr1 = rBase + row1;
    const int gc0 = gr0 < M ? gr0 : 0, gc1 = gr1 < M ? gr1 : 0;
    const unsigned sz0 = gr0 < M ? 16u : 0u, sz1 = gr1 < M ? 16u : 0u;

#pragma unroll
    for (int s = 0; s < 2; s++) {
        CP16(u0 + (uint32_t)(s * ABUF + row0 * KSTR + lseg * 8) * 2,
             Asrc[s] + (size_t)gc0 * 256 + lseg * 8, sz0);
        CP16(u0 + (uint32_t)(s * ABUF + row1 * KSTR + lseg * 8) * 2,
             Asrc[s] + (size_t)gc1 * 256 + lseg * 8, sz1);
        CP16(u0 + (uint32_t)(2 * ABUF + s * BBUF64 + row0 * KSTR + lseg * 8) * 2,
             Bsrc[s] + (size_t)row0 * 256 + lseg * 8, 16u);
    }
    CP_COMMIT();

#pragma unroll 1
    for (int c = 0; c < 8; c++) {
        if (c < 7) {
            const uint32_t stB = (uint32_t)(((c + 1) & 1) * STAGE64_H) * 2;
            const int koff = (c + 1) * 32 + lseg * 8;
#pragma unroll
            for (int s = 0; s < 2; s++) {
                CP16(u0 + stB + (uint32_t)(s * ABUF + row0 * KSTR + lseg * 8) * 2,
                     Asrc[s] + (size_t)gc0 * 256 + koff, sz0);
                CP16(u0 + stB + (uint32_t)(s * ABUF + row1 * KSTR + lseg * 8) * 2,
                     Asrc[s] + (size_t)gc1 * 256 + koff, sz1);
                CP16(u0 + stB + (uint32_t)(2 * ABUF + s * BBUF64 + row0 * KSTR + lseg * 8) * 2,
                     Bsrc[s] + (size_t)row0 * 256 + koff, 16u);
            }
            CP_COMMIT();
            CP_WAIT1();
        } else {
            CP_WAIT0();
        }
        __syncthreads();
        const uint32_t st = (uint32_t)((c & 1) * STAGE64_H) * 2;
        const uint32_t uAh = u0 + st;
        const uint32_t uAl = u0 + st + (uint32_t)ABUF * 2;
        const uint32_t uBh = u0 + st + (uint32_t)(2 * ABUF) * 2;
        const uint32_t uBl = u0 + st + (uint32_t)(2 * ABUF + BBUF64) * 2;
#pragma unroll
        for (int k = 0; k < 2; k++) {
            const int k0 = k << 4;
            const uint32_t aoff = (uint32_t)(((wm << 5) + a_row_l) * KSTR + k0 + a_kh) * 2;
            const uint32_t boff0 = (uint32_t)(((wn << 5) + b_n_off) * KSTR + k0 + b_k_off) * 2;
            const uint32_t boff1 = boff0 + (uint32_t)(16 * KSTR) * 2;
            uint32_t ah[2][4], al[2][4], bh[2][4], bl[2][4];
#pragma unroll
            for (int mi = 0; mi < 2; mi++) {
                LDMATRIX_X4(ah[mi][0], ah[mi][1], ah[mi][2], ah[mi][3],
                            uAh + aoff + (uint32_t)((mi << 4) * KSTR) * 2);
                LDMATRIX_X4(al[mi][0], al[mi][1], al[mi][2], al[mi][3],
                            uAl + aoff + (uint32_t)((mi << 4) * KSTR) * 2);
            }
            LDMATRIX_X4(bh[0][0], bh[0][1], bh[0][2], bh[0][3], uBh + boff0);
            LDMATRIX_X4(bh[1][0], bh[1][1], bh[1][2], bh[1][3], uBh + boff1);
            LDMATRIX_X4(bl[0][0], bl[0][1], bl[0][2], bl[0][3], uBl + boff0);
            LDMATRIX_X4(bl[1][0], bl[1][1], bl[1][2], bl[1][3], uBl + boff1);
#pragma unroll
            for (int mi = 0; mi < 2; mi++)
#pragma unroll
                for (int ni = 0; ni < 4; ni++) {
                    uint32_t b0h = bh[ni >> 1][(ni & 1) * 2], b1h = bh[ni >> 1][(ni & 1) * 2 + 1];
                    uint32_t b0l = bl[ni >> 1][(ni & 1) * 2], b1l = bl[ni >> 1][(ni & 1) * 2 + 1];
                    MMAF16(acc[mi][ni], ah[mi], b0h, b1h);
                    MMAF16(acc[mi][ni], ah[mi], b0l, b1l);
                    MMAF16(acc[mi][ni], al[mi], b0h, b1h);
                }
        }
        __syncthreads();
    }

    if (MODE == 1) {
#pragma unroll
        for (int mi = 0; mi < 2; mi++)
#pragma unroll
            for (int hf2 = 0; hf2 < 2; hf2++) {
                int gr = rBase + (wm << 5) + (mi << 4) + (lane >> 2) + hf2 * 8;
                if (gr >= M) continue;
#pragma unroll
                for (int ni = 0; ni < 4; ni++) {
                    int col = (wn << 5) + (ni << 3) + (lane & 3) * 2;
                    float o0 = acc[mi][ni][hf2 * 2] * scale;
                    float o1 = acc[mi][ni][hf2 * 2 + 1] * scale;
                    *(float2*)&C[(size_t)gr * 64 + col] = make_float2(o0, o1);
                }
            }
    } else {
        float rv[4]; int ridx[4];
#pragma unroll
        for (int mi = 0; mi < 2; mi++)
#pragma unroll
            for (int hf2 = 0; hf2 < 2; hf2++) {
                float v = -3.4e38f; int idx = 0;
#pragma unroll
                for (int ni = 0; ni < 4; ni++) {
                    int col = (wn << 5) + (ni << 3) + (lane & 3) * 2;
                    float o0 = acc[mi][ni][hf2 * 2] + bias[col];
                    float o1 = acc[mi][ni][hf2 * 2 + 1] + bias[col + 1];
                    if (o0 > v) { v = o0; idx = col; }
                    if (o1 > v) { v = o1; idx = col + 1; }
                }
#pragma unroll
                for (int o = 1; o <= 2; o <<= 1) {
                    float ov = __shfl_xor_sync(0xffffffffu, v, o);
                    int oi = __shfl_xor_sync(0xffffffffu, idx, o);
                    if (ov > v || (ov == v && oi < idx)) { v = ov; idx = oi; }
                }
                int lr = (wm << 5) + (mi << 4) + hf2 * 8 + (lane >> 2);
                if (wn == 0 && (lane & 3) == 0) { sval[lr] = v; sidx[lr] = idx; }
                rv[mi * 2 + hf2] = v; ridx[mi * 2 + hf2] = idx;
            }
        __syncthreads();
        if (wn == 1 && (lane & 3) == 0) {
#pragma unroll
            for (int mi = 0; mi < 2; mi++)
#pragma unroll
                for (int hf2 = 0; hf2 < 2; hf2++) {
                    int lr = (wm << 5) + (mi << 4) + hf2 * 8 + (lane >> 2);
                    int gr = rBase + lr;
                    if (gr >= M) continue;
                    float v0 = sval[lr]; int i0 = sidx[lr];
                    float v1 = rv[mi * 2 + hf2]; int i1 = ridx[mi * 2 + hf2];
                    g_cls[gr] = (v1 > v0) ? i1 : i0;
                }
        }
    }
}

__global__ void k_invnorm() {
    int warp = (blockIdx.x * blockDim.x + threadIdx.x) >> 5;
    int lane = threadIdx.x & 31;
    if (warp >= T_REP * N_NODES) return;
    const float4* r = (const float4*)(g_AF + ((size_t)N_NODES + warp) * 256);
    float4 a = r[lane * 2], b = r[lane * 2 + 1];
    float s = a.x * a.x + a.y * a.y + a.z * a.z + a.w * a.w +
              b.x * b.x + b.y * b.y + b.z * b.z + b.w * b.w;
#pragma unroll
    for (int o = 16; o; o >>= 1) s += __shfl_xor_sync(0xffffffffu, s, o);
    if (lane == 0) g_invn[warp] = 1.f / fmaxf(sqrtf(s), 1e-8f);
}

__device__ __forceinline__ float dot8(float4 f0, float4 f1, float4 a, float4 b) {
    return f0.x * a.x + f0.y * a.y + f0.z * a.z + f0.w * a.w +
           f1.x * b.x + f1.y * b.y + f1.z * b.z + f1.w * b.w;
}

__global__ void k_ocount(const int* __restrict__ ei) {
    int i = blockIdx.x * blockDim.x + threadIdx.x;
    if (i < N_EDGES) atomicAdd(&g_odeg[ei[N_EDGES + i]], 1);
}

__global__ void k_ofill(const int* __restrict__ ei) {
    int i = blockIdx.x * blockDim.x + threadIdx.x;
    if (i >= N_EDGES) return;
    int d = ei[N_EDGES + i];
    int pos = g_orow[d] + atomicAdd(&g_ocur[d], 1);
    g_oedge[pos] = i;
}

__global__ void k_edge_sim2(const int* __restrict__ ei) {
    int d = (blockIdx.x * blockDim.x + threadIdx.x) >> 5;
    if (d >= N_NODES) return;
    int lane = threadIdx.x & 31;
    int len = g_odeg[d];
    if (len == 0) return;
    int start = g_orow[d];
    const float4* t0 = (const float4*)(g_AF + ((size_t)1 * N_NODES + d) * 256);
    const float4* t1 = (const float4*)(g_AF + ((size_t)2 * N_NODES + d) * 256);
    const float4* t2 = (const float4*)(g_AF + ((size_t)3 * N_NODES + d) * 256);
    const float4* t3 = (const float4*)(g_AF + ((size_t)4 * N_NODES + d) * 256);
    float4 a0 = t0[lane * 2], b0 = t0[lane * 2 + 1];
    float4 a1 = t1[lane * 2], b1 = t1[lane * 2 + 1];
    float4 a2 = t2[lane * 2], b2 = t2[lane * 2 + 1];
    float4 a3 = t3[lane * 2], b3 = t3[lane * 2 + 1];
    float i0 = g_invn[d];
    float i1 = g_invn[N_NODES + d];
    float i2 = g_invn[2 * N_NODES + d];
    float i3 = g_invn[3 * N_NODES + d];
    int j = 0;
    for (; j + 2 <= len; j += 2) {
        int e0 = g_oedge[start + j], e1 = g_oedge[start + j + 1];
        int s0 = ei[e0], s1 = ei[e1];
        const float4* fr0 = (const float4*)(g_AF + (size_t)s0 * 256);
        const float4* fr1 = (const float4*)(g_AF + (size_t)s1 * 256);
        float4 fA = fr0[lane * 2], fB = fr0[lane * 2 + 1];
        float4 gA = fr1[lane * 2], gB = fr1[lane * 2 + 1];
        float p0 = dot8(fA, fB, a0, b0), q0 = dot8(gA, gB, a0, b0);
        float p1 = dot8(fA, fB, a1, b1), q1 = dot8(gA, gB, a1, b1);
        float p2 = dot8(fA, fB, a2, b2), q2 = dot8(gA, gB, a2, b2);
        float p3 = dot8(fA, fB, a3, b3), q3 = dot8(gA, gB, a3, b3);
#pragma unroll
        for (int o = 16; o; o >>= 1) {
            p0 += __shfl_xor_sync(0xffffffffu, p0, o);
            p1 += __shfl_xor_sync(0xffffffffu, p1, o);
            p2 += __shfl_xor_sync(0xffffffffu, p2, o);
            p3 += __shfl_xor_sync(0xffffffffu, p3, o);
            q0 += __shfl_xor_sync(0xffffffffu, q0, o);
            q1 += __shfl_xor_sync(0xffffffffu, q1, o);
            q2 += __shfl_xor_sync(0xffffffffu, q2, o);
            q3 += __shfl_xor_sync(0xffffffffu, q3, o);
        }
        if (lane == 0) {
            float s0v = p0 * i0, s1v = p1 * i1, s2v = p2 * i2, s3v = p3 * i3;
            float bv = s0v; int bi = 0;
            if (s1v > bv) { bv = s1v; bi = 1; }
            if (s2v > bv) { bv = s2v; bi = 2; }
            if (s3v > bv) { bv = s3v; bi = 3; }
            g_best[e0] = bi;
            float u0v = q0 * i0, u1v = q1 * i1, u2v = q2 * i2, u3v = q3 * i3;
            float cv = u0v; int ci = 0;
            if (u1v > cv) { cv = u1v; ci = 1; }
            if (u2v > cv) { cv = u2v; ci = 2; }
            if (u3v > cv) { cv = u3v; ci = 3; }
            g_best[e1] = ci;
        }
    }
    if (j < len) {
        int e = g_oedge[start + j];
        int s = ei[e];
        const float4* fr = (const float4*)(g_AF + (size_t)s * 256);
        float4 f0 = fr[lane * 2], f1 = fr[lane * 2 + 1];
        float p0 = dot8(f0, f1, a0, b0);
        float p1 = dot8(f0, f1, a1, b1);
        float p2 = dot8(f0, f1, a2, b2);
        float p3 = dot8(f0, f1, a3, b3);
#pragma unroll
        for (int o = 16; o; o >>= 1) {
            p0 += __shfl_xor_sync(0xffffffffu, p0, o);
            p1 += __shfl_xor_sync(0xffffffffu, p1, o);
            p2 += __shfl_xor_sync(0xffffffffu, p2, o);
            p3 += __shfl_xor_sync(0xffffffffu, p3, o);
        }
        if (lane == 0) {
            float s0v = p0 * i0, s1v = p1 * i1, s2v = p2 * i2, s3v = p3 * i3;
            float bv = s0v; int bi = 0;
            if (s1v > bv) { bv = s1v; bi = 1; }
            if (s2v > bv) { bv = s2v; bi = 2; }
            if (s3v > bv) { bv = s3v; bi = 3; }
            g_best[e] = bi;
        }
    }
}

__device__ __forceinline__ void decode_edge(const int* __restrict__ ei, int i, int& s, int& d) {
    if (i < N_EDGES) {
        s = ei[i]; d = ei[N_EDGES + i];
    } else if (i < 2 * N_EDGES) {
        int e = i - N_EDGES;
        s = ei[e]; d = ei[N_EDGES + e] + g_best[e] * N_NODES;
    } else {
        int r = i - 2 * N_EDGES;
        int rep = r / N_NODES + 1;
        int n = r - (rep - 1) * N_NODES;
        s = n; d = n + rep * N_NODES;
    }
}

__global__ void k_count(const int* __restrict__ ei) {
    int i = blockIdx.x * blockDim.x + threadIdx.x;
    if (i >= NE_TOT) return;
    int s, d;
    decode_edge(ei, i, s, d);
    if (s != d) atomicAdd(&g_deg[d], 1);
}

__global__ void k_dinv() {
    int i = blockIdx.x * blockDim.x + threadIdx.x;
    if (i < N_TOT) g_dinv[i] = rsqrtf((float)(g_deg[i] + 1));
}

__global__ void k_scan1(const int* __restrict__ in, int* __restrict__ out, int n, int minus) {
    __shared__ int sm[256];
    int tid = threadIdx.x;
    int base = blockIdx.x * SCAN_BLK;
    int loc[4]; int sum = 0;
#pragma unroll
    for (int u = 0; u < 4; u++) {
        int i = base + tid * 4 + u;
        int v = (i < n) ? (in[i] - minus) : 0;
        loc[u] = sum; sum += v;
    }
    sm[tid] = sum;
    __syncthreads();
    for (int o = 1; o < 256; o <<= 1) {
        int t = (tid >= o) ? sm[tid - o] : 0;
        __syncthreads();
        sm[tid] += t;
        __syncthreads();
    }
    int pre = tid ? sm[tid - 1] : 0;
#pragma unroll
    for (int u = 0; u < 4; u++) {
        int i = base + tid * 4 + u;
        if (i < n) out[i] = pre + loc[u];
    }
    if (tid == 255) g_blocksum[blockIdx.x] = sm[255];
}

__global__ void k_scan2(int nb) {
    __shared__ int sm[256];
    int tid = threadIdx.x;
    sm[tid] = (tid < nb) ? g_blocksum[tid] : 0;
    __syncthreads();
    for (int o = 1; o < 256; o <<= 1) {
        int t = (tid >= o) ? sm[tid - o] : 0;
        __syncthreads();
        sm[tid] += t;
        __syncthreads();
    }
    if (tid < nb) g_blocksum[tid] = tid ? sm[tid - 1] : 0;
}

__global__ void k_scan3(int* __restrict__ out, int n) {
    int i = blockIdx.x * blockDim.x + threadIdx.x;
    if (i < n) out[i] += g_blocksum[i >> 10];
}

__global__ void k_fill(const int* __restrict__ ei) {
    int i = blockIdx.x * blockDim.x + threadIdx.x;
    if (i >= NE_TOT) return;
    int s, d;
    decode_edge(ei, i, s, d);
    if (s == d) return;
    int pos = g_rowptr[d] + atomicAdd(&g_cursor[d], 1);
    g_csr_src[pos] = s;
    g_csr_w[pos] = g_dinv[s] * g_dinv[d];
}

template<int WS>
__global__ void k_aggregate(const float* __restrict__ X, const float* __restrict__ bias,
                            float* __restrict__ Out) {
    int w = (blockIdx.x * blockDim.x + threadIdx.x) >> 5;
    if (w >= N_TOT) return;
    int lane = threadIdx.x & 31;
    int start = g_rowptr[w];
    int len = g_deg[w];
    float dv = g_dinv[w];
    float ws = dv * dv;
    const float4* xd = (const float4*)(X + (size_t)w * 256);
    float4 sa = xd[lane * 2], sb = xd[lane * 2 + 1];
    float acc0 = ws * sa.x, acc1 = ws * sa.y, acc2 = ws * sa.z, acc3 = ws * sa.w;
    float acc4 = ws * sb.x, acc5 = ws * sb.y, acc6 = ws * sb.z, acc7 = ws * sb.w;
    int j = 0;
    for (; j + 2 <= len; j += 2) {
        int s0 = g_csr_src[start + j];
        int s1 = g_csr_src[start + j + 1];
        float w0 = g_csr_w[start + j];
        float w1 = g_csr_w[start + j + 1];
        const float4* x0 = (const float4*)(X + (size_t)s0 * 256);
        const float4* x1 = (const float4*)(X + (size_t)s1 * 256);
        float4 u0 = x0[lane * 2], v0 = x0[lane * 2 + 1];
        float4 u1 = x1[lane * 2], v1 = x1[lane * 2 + 1];
        acc0 = fmaf(w0, u0.x, acc0); acc1 = fmaf(w0, u0.y, acc1);
        acc2 = fmaf(w0, u0.z, acc2); acc3 = fmaf(w0, u0.w, acc3);
        acc4 = fmaf(w0, v0.x, acc4); acc5 = fmaf(w0, v0.y, acc5);
        acc6 = fmaf(w0, v0.z, acc6); acc7 = fmaf(w0, v0.w, acc7);
        acc0 = fmaf(w1, u1.x, acc0); acc1 = fmaf(w1, u1.y, acc1);
        acc2 = fmaf(w1, u1.z, acc2); acc3 = fmaf(w1, u1.w, acc3);
        acc4 = fmaf(w1, v1.x, acc4); acc5 = fmaf(w1, v1.y, acc5);
        acc6 = fmaf(w1, v1.z, acc6); acc7 = fmaf(w1, v1.w, acc7);
    }
    if (j < len) {
        int s0 = g_csr_src[start + j];
        float w0 = g_csr_w[start + j];
        const float4* x0 = (const float4*)(X + (size_t)s0 * 256);
        float4 u0 = x0[lane * 2], v0 = x0[lane * 2 + 1];
        acc0 = fmaf(w0, u0.x, acc0); acc1 = fmaf(w0, u0.y, acc1);
        acc2 = fmaf(w0, u0.z, acc2); acc3 = fmaf(w0, u0.w, acc3);
        acc4 = fmaf(w0, v0.x, acc4); acc5 = fmaf(w0, v0.y, acc5);
        acc6 = fmaf(w0, v0.z, acc6); acc7 = fmaf(w0, v0.w, acc7);
    }
    const float4* b4 = (const float4*)bias;
    float4 bb0 = b4[lane * 2], bb1 = b4[lane * 2 + 1];
    float o[8] = {acc0 + bb0.x, acc1 + bb0.y, acc2 + bb0.z, acc3 + bb0.w,
                  acc4 + bb1.x, acc5 + bb1.y, acc6 + bb1.z, acc7 + bb1.w};
    float4* od = (float4*)(Out + (size_t)w * 256);
    od[lane * 2] = make_float4(o[0], o[1], o[2], o[3]);
    od[lane * 2 + 1] = make_float4(o[4], o[5], o[6], o[7]);
    if (WS) {
        uint32_t hw[4], lw[4];
#pragma unroll
        for (int q = 0; q < 4; q++) {
            __half h0, l0, h1, l1;
            split2(fmaxf(o[q * 2], 0.f), h0, l0);
            split2(fmaxf(o[q * 2 + 1], 0.f), h1, l1);
            hw[q] = hpack2(h0, h1); lw[q] = hpack2(l0, l1);
        }
        size_t so = (size_t)w * 256 + lane * 8;
        *(uint4*)(g_Ahi + so) = make_uint4(hw[0], hw[1], hw[2], hw[3]);
        *(uint4*)(g_Alo + so) = make_uint4(lw[0], lw[1], lw[2], lw[3]);
    }
}

__global__ void k_H(float* __restrict__ Hout) {
    int n = blockIdx.x * blockDim.x + threadIdx.x;
    if (n >= N_NODES) return;
    int c0 = g_cls[n];
    int c1 = g_cls[N_NODES + n];
    int c2 = g_cls[2 * N_NODES + n];
    int c3 = g_cls[3 * N_NODES + n];
    int c4 = g_cls[4 * N_NODES + n];
    float* o = Hout + (size_t)n * 64;
#pragma unroll
    for (int j = 0; j < 64; j++)
        o[j] = (float)((c0 == j) + (c1 == j) + (c2 == j) + (c3 == j) + (c4 == j));
}

__global__ void k_hyperedge(const float* __restrict__ Hout, float* __restrict__ hf) {
    extern __shared__ float acc[];
    int tid = threadIdx.x;
    for (int i = tid; i < 16384; i += 256) acc[i] = 0.f;
    __syncthreads();
    int warp = tid >> 5, lane = tid & 31;
    for (int n = blockIdx.x * 8 + warp; n < N_NODES; n += gridDim.x * 8) {
        float h0 = Hout[(size_t)n * 64 + lane];
        float h1 = Hout[(size_t)n * 64 + lane + 32];
        unsigned m0 = __ballot_sync(0xffffffffu, h0 > 0.f);
        unsigned m1 = __ballot_sync(0xffffffffu, h1 > 0.f);
        const float4* xr = (const float4*)(g_B + (size_t)n * 256);
        float4 a = xr[lane * 2], b = xr[lane * 2 + 1];
        unsigned mm = m0;
        while (mm) {
            int c = __ffs(mm) - 1; mm &= mm - 1;
            float* p = acc + c * 256 + lane * 8;
            atomicAdd(p + 0, a.x); atomicAdd(p + 1, a.y); atomicAdd(p + 2, a.z); atomicAdd(p + 3, a.w);
            atomicAdd(p + 4, b.x); atomicAdd(p + 5, b.y); atomicAdd(p + 6, b.z); atomicAdd(p + 7, b.w);
        }
        mm = m1;
        while (mm) {
            int c = (__ffs(mm) - 1) + 32; mm &= mm - 1;
            float* p = acc + c * 256 + lane * 8;
            atomicAdd(p + 0, a.x); atomicAdd(p + 1, a.y); atomicAdd(p + 2, a.z); atomicAdd(p + 3, a.w);
            atomicAdd(p + 4, b.x); atomicAdd(p + 5, b.y); atomicAdd(p + 6, b.z); atomicAdd(p + 7, b.w);
        }
    }
    __syncthreads();
    for (int i = tid; i < 16384; i += 256) atomicAdd(&hf[i], acc[i]);
}

// ---------------- launch ----------------
extern "C" void kernel_launch(void* const* d_in, const int* in_sizes, int n_in,
                              void* d_out, int out_size) {
    const int*   ei       = (const int*)d_in[0];
    const float* features = (const float*)d_in[1];
    const float* lin_w    = (const float*)d_in[2];
    const float* lin_b    = (const float*)d_in[3];
    const float* gcn0_w   = (const float*)d_in[4];
    const float* gcn0_b   = (const float*)d_in[5];
    const float* gcn1_w   = (const float*)d_in[6];
    const float* gcn1_b   = (const float*)d_in[7];
    const float* lin1_w   = (const float*)d_in[8];
    const float* lin1_b   = (const float*)d_in[9];

    float* out      = (float*)d_out;
    float* H_out    = out;
    float* hf_out   = out + (size_t)N_NODES * NS;
    float* dots_out = hf_out + NS * D;

    float *AF, *X, *B, *ZB;
    int *CUR, *DEG, *ROWPTR, *ODEG, *OROW, *OCUR;
    __half *AH, *AL, *AH2, *AL2, *WH, *WL;
    cudaGetSymbolAddress((void**)&AF, g_AF);
    cudaGetSymbolAddress((void**)&X,  g_X);
    cudaGetSymbolAddress((void**)&B,  g_B);
    cudaGetSymbolAddress((void**)&ZB, g_zerobias);
    cudaGetSymbolAddress((void**)&CUR, g_cursor);
    cudaGetSymbolAddress((void**)&DEG, g_deg);
    cudaGetSymbolAddress((void**)&ROWPTR, g_rowptr);
    cudaGetSymbolAddress((void**)&ODEG, g_odeg);
    cudaGetSymbolAddress((void**)&OROW, g_orow);
    cudaGetSymbolAddress((void**)&OCUR, g_ocur);
    cudaGetSymbolAddress((void**)&AH, g_Ahi);
    cudaGetSymbolAddress((void**)&AL, g_Alo);
    cudaGetSymbolAddress((void**)&AH2, g_Ahi2);
    cudaGetSymbolAddress((void**)&AL2, g_Alo2);
    cudaGetSymbolAddress((void**)&WH, g_Whi);
    cudaGetSymbolAddress((void**)&WL, g_Wlo);

    cudaFuncSetAttribute(k_hyperedge,  cudaFuncAttributeMaxDynamicSharedMemorySize, 65536);
    cudaFuncSetAttribute(k_mmagemm<0>, cudaFuncAttributeMaxDynamicSharedMemorySize, SMG_BYTES);
    cudaFuncSetAttribute(k_mmagemm<1>, cudaFuncAttributeMaxDynamicSharedMemorySize, SMG_BYTES);
    cudaFuncSetAttribute(k_mmagemm64<0>, cudaFuncAttributeMaxDynamicSharedMemorySize, SM64_BYTES);
    cudaFuncSetAttribute(k_mmagemm64<1>, cudaFuncAttributeMaxDynamicSharedMemorySize, SM64_BYTES);

    const int nb_tot  = (N_TOT + SCAN_BLK - 1) / SCAN_BLK;
    const int nb_node = (N_NODES + SCAN_BLK - 1) / SCAN_BLK;

    // weight splits (heads fused via gridDim.y) + raw feature split (buf1+buf2+AF copy)
    k_wsplit<<<dim3(256, 4), 256>>>(lin_w, 0, 256, 65536);
    k_split<0, 1, 1><<<(N_NODES * 64 + 255) / 256, 256>>>((const float4*)features, N_NODES * 64);

    // heads GEMM on raw features; epilogue: split(relu)->buf1, split(raw)->buf2, rows N..5N
    k_mmagemm<1><<<dim3(2, (N_NODES + 127) / 128, 4), 256, SMG_BYTES>>>(
        AH, AL, WH, WL, lin_b, AF + (size_t)N_NODES * 256,
        N_NODES, 65536, N_NODES * 256, 256, N_NODES, N_NODES);

    k_wsplit<<<dim3(256, 1), 256>>>(gcn0_w, 4, 256, 0);
    k_wsplit<<<dim3(256, 1), 256>>>(gcn1_w, 5, 256, 0);
    k_wsplit<<<dim3(64, 1), 256>>>(lin1_w, 6, 64, 0);
    k_split<1, 0, 0><<<(N_NODES * 64 + 255) / 256, 256>>>((const float4*)features, N_NODES * 64);

    // original-edge CSR
    cudaMemsetAsync(ODEG, 0, N_NODES * sizeof(int));
    cudaMemsetAsync(OCUR, 0, N_NODES * sizeof(int));
    k_ocount<<<(N_EDGES + 255) / 256, 256>>>(ei);
    k_scan1<<<nb_node, 256>>>(ODEG, OROW, N_NODES, 0);
    k_scan2<<<1, 256>>>(nb_node);
    k_scan3<<<(N_NODES + 255) / 256, 256>>>(OROW, N_NODES);
    k_ofill<<<(N_EDGES + 255) / 256, 256>>>(ei);

    // per-edge best replica
    k_invnorm<<<(T_REP * N_NODES * 32 + 255) / 256, 256>>>();
    k_edge_sim2<<<(N_NODES * 32 + 255) / 256, 256>>>(ei);

    // augmented-graph CSR (deg = in-edge count, self loop folded into dinv)
    cudaMemsetAsync(DEG, 0, N_TOT * sizeof(int));
    k_count<<<(NE_TOT + 255) / 256, 256>>>(ei);
    k_dinv<<<(N_TOT + 255) / 256, 256>>>();
    k_scan1<<<nb_tot, 256>>>(DEG, ROWPTR, N_TOT, 0);
    k_scan2<<<1, 256>>>(nb_tot);
    k_scan3<<<(N_TOT + 255) / 256, 256>>>(ROWPTR, N_TOT);
    cudaMemsetAsync(CUR, 0, N_TOT * sizeof(int));
    k_fill<<<(NE_TOT + 255) / 256, 256>>>(ei);

    // GCN layer 0
    k_mmagemm<0><<<dim3(2, (N_TOT + 127) / 128, 1), 256, SMG_BYTES>>>(
        AH, AL, WH + 4 * 65536, WL + 4 * 65536, ZB, X, N_TOT, 0, 0, 0, 0, 0);
    k_aggregate<1><<<(N_TOT * 32 + 255) / 256, 256>>>(X, gcn0_b, B);

    // GCN layer 1
    k_mmagemm<0><<<dim3(2, (N_TOT + 127) / 128, 1), 256, SMG_BYTES>>>(
        AH, AL, WH + 5 * 65536, WL + 5 * 65536, ZB, X, N_TOT, 0, 0, 0, 0, 0);
    k_aggregate<1><<<(N_TOT * 32 + 255) / 256, 256>>>(X, gcn1_b, B);

    // logits mma with fused argmax -> g_cls; then H
    k_mmagemm64<0><<<(N_TOT + 127) / 128, 256, SM64_BYTES>>>(
        AH, AL, WH + 6 * 65536, WL + 6 * 65536, lin1_b, X, N_TOT, 0.f);
    k_H<<<(N_NODES + 255) / 256, 256>>>(H_out);

    // hyperedge features, split hf into slot 7
    cudaMemsetAsync(hf_out, 0, (size_t)NS * D * sizeof(float));
    k_hyperedge<<<160, 256, 65536>>>(H_out, hf_out);
    k_wsplit_dir<<<64, 256>>>(hf_out, 7, NS * D);

    // dots via mma on raw-AF splits (buf2)
    k_mmagemm64<1><<<(N_TOT + 127) / 128, 256, SM64_BYTES>>>(
        AH2, AL2, WH + 7 * 65536, WL + 7 * 65536, ZB, dots_out, N_TOT, 0.0625f);
}

// round 13
// speedup vs baseline: 1.0173x; 1.0173x over previous
#include <cuda_runtime.h>
#include <cuda_fp16.h>
#include <cstdint>

#define N_NODES 50000
#define N_EDGES 800000
#define D 256
#define T_REP 4
#define NS 64
#define N_TOT (5 * N_NODES)                 /* 250000 */
#define NE_TOT (2 * N_EDGES + 3 * N_NODES)  /* 1750000 */
#define SCAN_BLK 1024
#define NPAD 250112

typedef unsigned long long u64;

__device__ __forceinline__ uint32_t smem_to_u32(const void* p) {
    uint32_t a;
    asm("{ .reg .u64 t; cvta.to.shared.u64 t, %1; cvt.u32.u64 %0, t; }" : "=r"(a) : "l"(p));
    return a;
}

#define LDMATRIX_X4(r0, r1, r2, r3, addr) \
    asm volatile("ldmatrix.sync.aligned.m8n8.x4.shared.b16 {%0,%1,%2,%3}, [%4];" \
                 : "=r"(r0), "=r"(r1), "=r"(r2), "=r"(r3) : "r"(addr))

#define MMAF16(c, a, b0, b1) \
    asm volatile("mma.sync.aligned.m16n8k16.row.col.f32.f16.f16.f32 " \
                 "{%0,%1,%2,%3}, {%4,%5,%6,%7}, {%8,%9}, {%0,%1,%2,%3};" \
                 : "+f"((c)[0]), "+f"((c)[1]), "+f"((c)[2]), "+f"((c)[3]) \
                 : "r"((a)[0]), "r"((a)[1]), "r"((a)[2]), "r"((a)[3]), "r"(b0), "r"(b1))

#define CP16(dst, src, sz) \
    asm volatile("cp.async.cg.shared.global [%0], [%1], 16, %2;" \
                 :: "r"(dst), "l"(src), "r"(sz))
#define CP_COMMIT() asm volatile("cp.async.commit_group;" ::: "memory")
#define CP_WAIT0()  asm volatile("cp.async.wait_group 0;" ::: "memory")

__device__ __forceinline__ void split2(float x, __half& h, __half& l) {
    h = __float2half_rn(x);
    l = __float2half_rn(x - __half2float(h));
}
__device__ __forceinline__ uint32_t hpack2(__half a, __half b) {
    return (uint32_t)__half_as_ushort(a) | ((uint32_t)__half_as_ushort(b) << 16);
}

// ---------------- scratch (device globals) ----------------
__device__ float g_AF[(size_t)N_TOT * D];
__device__ float g_X[(size_t)N_TOT * D];
__device__ float g_B[(size_t)N_TOT * D];
__device__ float g_invn[T_REP * N_NODES];
__device__ int   g_deg[N_TOT];              // in-edge count (no self loop)
__device__ float g_dinv[N_TOT];
__device__ int   g_best[N_EDGES];
__device__ int   g_cls[N_TOT];
__device__ float g_zerobias[D];
__device__ int   g_rowptr[N_TOT];
__device__ int   g_blocksum[256];
__device__ int   g_cursor[N_TOT];
__device__ int   g_csr_src[NE_TOT];
__device__ float g_csr_w[NE_TOT];
__device__ int   g_odeg[N_NODES];
__device__ int   g_orow[N_NODES];
__device__ int   g_ocur[N_NODES];
__device__ int   g_oedge[N_EDGES];
// fp16 split buffers: buf1 = GEMM activations (relu), buf2 = raw AF (for dots)
__device__ __half g_Ahi[(size_t)NPAD * D];
__device__ __half g_Alo[(size_t)NPAD * D];
__device__ __half g_Ahi2[(size_t)NPAD * D];
__device__ __half g_Alo2[(size_t)NPAD * D];
__device__ __half g_Whi[8 * 65536];
__device__ __half g_Wlo[8 * 65536];

// ---------------- small kernels ----------------

template<int RELU, int COPY, int B2>
__global__ void k_split(const float4* __restrict__ X, int n4) {
    int i = blockIdx.x * blockDim.x + threadIdx.x;
    if (i >= n4) return;
    float4 v = X[i];
    if (COPY) ((float4*)g_AF)[i] = v;
    if (B2) {
        __half h0,l0,h1,l1,h2,l2,h3,l3;
        split2(v.x,h0,l0); split2(v.y,h1,l1); split2(v.z,h2,l2); split2(v.w,h3,l3);
        ((uint2*)g_Ahi2)[i] = make_uint2(hpack2(h0,h1), hpack2(h2,h3));
        ((uint2*)g_Alo2)[i] = make_uint2(hpack2(l0,l1), hpack2(l2,l3));
    }
    float x0 = v.x, x1 = v.y, x2 = v.z, x3 = v.w;
    if (RELU) {
        x0 = fmaxf(x0, 0.f); x1 = fmaxf(x1, 0.f);
        x2 = fmaxf(x2, 0.f); x3 = fmaxf(x3, 0.f);
    }
    __half h0,l0,h1,l1,h2,l2,h3,l3;
    split2(x0,h0,l0); split2(x1,h1,l1); split2(x2,h2,l2); split2(x3,h3,l3);
    ((uint2*)g_Ahi)[i] = make_uint2(hpack2(h0,h1), hpack2(h2,h3));
    ((uint2*)g_Alo)[i] = make_uint2(hpack2(l0,l1), hpack2(l2,l3));
}

// split + transpose a [256 x ncols] weight into slot widxBase + blockIdx.y
__global__ void k_wsplit(const float* __restrict__ W, int widxBase, int ncols, int wstride) {
    int widx = widxBase + blockIdx.y;
    const float* Wz = W + (size_t)blockIdx.y * wstride;
    int i = blockIdx.x * 256 + threadIdx.x;
    int n = i >> 8, k = i & 255;
    float x = Wz[k * ncols + n];
    __half h, l;
    split2(x, h, l);
    g_Whi[widx * 65536 + i] = h;
    g_Wlo[widx * 65536 + i] = l;
}

__global__ void k_wsplit_dir(const float* __restrict__ src, int widx, int nelem) {
    int i = blockIdx.x * 256 + threadIdx.x;
    if (i >= nelem) return;
    __half h, l;
    split2(src[i], h, l);
    g_Whi[widx * 65536 + i] = h;
    g_Wlo[widx * 65536 + i] = l;
}

// ---- fp16x3 GEMM (N=256): C[M,256] = A @ W + bias (round-10 structure) ----
#define ASTRIDE 72
#define SMBUF (128 * ASTRIDE)
#define SMG_BYTES (4 * SMBUF * 2)
template<int WS>
__global__ __launch_bounds__(256, 2) void k_mmagemm(
    const __half* Ahi, const __half* Alo,
    const __half* __restrict__ Whi, const __half* __restrict__ Wlo,
    const float* __restrict__ bias, float* __restrict__ C,
    int M, int wz, int cz, int bzs, int splitBase, int splitZ)
{
    extern __shared__ __half smh[];
    __half* sAh = smh;
    __half* sAl = smh + SMBUF;
    __half* sBh = smh + 2 * SMBUF;
    __half* sBl = smh + 3 * SMBUF;

    const int tid = threadIdx.x;
    const int warp = tid >> 5, lane = tid & 31;
    const int wm = warp & 1, wn = warp >> 1;
    const int z = blockIdx.z;
    const int rBase = blockIdx.y << 7;
    const int colBase = blockIdx.x << 7;

    const __half* Wh = Whi + (size_t)z * wz;
    const __half* Wl = Wlo + (size_t)z * wz;

    float acc[4][4][4];
#pragma unroll
    for (int i = 0; i < 4; i++)
#pragma unroll
        for (int j = 0; j < 4; j++)
#pragma unroll
            for (int q = 0; q < 4; q++) acc[i][j][q] = 0.f;

    const uint32_t uAh = smem_to_u32(sAh);
    const uint32_t uAl = smem_to_u32(sAl);
    const uint32_t uBh = smem_to_u32(sBh);
    const uint32_t uBl = smem_to_u32(sBl);
    const int a_row_l = lane & 15;
    const int a_kh = (lane >> 4) << 3;
    const int b_n_off = (lane & 7) + ((lane >> 4) << 3);
    const int b_k_off = ((lane >> 3) & 1) << 3;

#pragma unroll 1
    for (int c = 0; c < 4; c++) {
#pragma unroll
        for (int s = 0; s < 2; s++) {
            const __half* ap = s ? Alo : Ahi;
            uint32_t ud = s ? uAl : uAh;
#pragma unroll
            for (int j = 0; j < 4; j++) {
                int i = tid + j * 256;
                int row = i >> 3, seg = i & 7;
                int gr = rBase + row;
                int grc = gr < M ? gr : 0;
                unsigned sz = gr < M ? 16u : 0u;
                CP16(ud + (uint32_t)(row * ASTRIDE + seg * 8) * 2,
                     ap + (size_t)grc * 256 + c * 64 + seg * 8, sz);
            }
            const __half* wp = s ? Wl : Wh;
            uint32_t wd = s ? uBl : uBh;
#pragma unroll
            for (int j = 0; j < 4; j++) {
                int i = tid + j * 256;
                int row = i >> 3, seg = i & 7;
                CP16(wd + (uint32_t)(row * ASTRIDE + seg * 8) * 2,
                     wp + (size_t)(colBase + row) * 256 + c * 64 + seg * 8, 16u);
            }
        }
        CP_COMMIT();
        CP_WAIT0();
        __syncthreads();
#pragma unroll
        for (int k = 0; k < 4; k++) {
            const int k0 = k << 4;
            const uint32_t aoff = (uint32_t)(((wm << 6) + a_row_l) * ASTRIDE + k0 + a_kh) * 2;
            const uint32_t boff0 = (uint32_t)(((wn << 5) + b_n_off) * ASTRIDE + k0 + b_k_off) * 2;
            const uint32_t boff1 = boff0 + (uint32_t)(16 * ASTRIDE) * 2;
            uint32_t ah[4][4], al[4][4], bh[2][4], bl[2][4];
#pragma unroll
            for (int mi = 0; mi < 4; mi++) {
                LDMATRIX_X4(ah[mi][0], ah[mi][1], ah[mi][2], ah[mi][3],
                            uAh + aoff + (uint32_t)((mi << 4) * ASTRIDE) * 2);
                LDMATRIX_X4(al[mi][0], al[mi][1], al[mi][2], al[mi][3],
                            uAl + aoff + (uint32_t)((mi << 4) * ASTRIDE) * 2);
            }
            LDMATRIX_X4(bh[0][0], bh[0][1], bh[0][2], bh[0][3], uBh + boff0);
            LDMATRIX_X4(bh[1][0], bh[1][1], bh[1][2], bh[1][3], uBh + boff1);
            LDMATRIX_X4(bl[0][0], bl[0][1], bl[0][2], bl[0][3], uBl + boff0);
            LDMATRIX_X4(bl[1][0], bl[1][1], bl[1][2], bl[1][3], uBl + boff1);
#pragma unroll
            for (int mi = 0; mi < 4; mi++)
#pragma unroll
                for (int ni = 0; ni < 4; ni++) {
                    uint32_t b0h = bh[ni >> 1][(ni & 1) * 2], b1h = bh[ni >> 1][(ni & 1) * 2 + 1];
                    uint32_t b0l = bl[ni >> 1][(ni & 1) * 2], b1l = bl[ni >> 1][(ni & 1) * 2 + 1];
                    MMAF16(acc[mi][ni], ah[mi], b0h, b1h);
                    MMAF16(acc[mi][ni], ah[mi], b0l, b1l);
                    MMAF16(acc[mi][ni], al[mi], b0h, b1h);
                }
        }
        __syncthreads();
    }

    const float* bp = bias + (size_t)z * bzs;
    float* Cz = C + (size_t)z * cz;
#pragma unroll
    for (int mi = 0; mi < 4; mi++) {
#pragma unroll
        for (int hf2 = 0; hf2 < 2; hf2++) {
            int gr = rBase + (wm << 6) + (mi << 4) + (lane >> 2) + hf2 * 8;
            if (gr >= M) continue;
#pragma unroll
            for (int ni = 0; ni < 4; ni++) {
                int col = colBase + (wn << 5) + (ni << 3) + (lane & 3) * 2;
                float o0 = acc[mi][ni][hf2 * 2] + bp[col];
                float o1 = acc[mi][ni][hf2 * 2 + 1] + bp[col + 1];
                *(float2*)&Cz[(size_t)gr * 256 + col] = make_float2(o0, o1);
                if (WS) {
                    size_t so = (size_t)(splitBase + z * splitZ + gr) * 256 + col;
                    __half h0, l0, h1, l1;
                    split2(fmaxf(o0, 0.f), h0, l0);
                    split2(fmaxf(o1, 0.f), h1, l1);
                    *(uint32_t*)(g_Ahi + so) = hpack2(h0, h1);
                    *(uint32_t*)(g_Alo + so) = hpack2(l0, l1);
                    split2(o0, h0, l0);
                    split2(o1, h1, l1);
                    *(uint32_t*)(g_Ahi2 + so) = hpack2(h0, h1);
                    *(uint32_t*)(g_Alo2 + so) = hpack2(l0, l1);
                }
            }
        }
    }
}

// ---- fp16x3 GEMM (N=64): MODE 0 logits+fused argmax; MODE 1 *scale ----
#define SM64_A (128 * ASTRIDE)
#define SM64_B (64 * ASTRIDE)
#define SM64_BYTES ((2 * SM64_A + 2 * SM64_B) * 2)
template<int MODE>
__global__ __launch_bounds__(256, 2) void k_mmagemm64(
    const __half* Ahi, const __half* Alo,
    const __half* __restrict__ Wh, const __half* __restrict__ Wl,
    const float* __restrict__ bias, float* __restrict__ C, int M, float scale)
{
    extern __shared__ __half smh[];
    __half* sAh = smh;
    __half* sAl = smh + SM64_A;
    __half* sBh = smh + 2 * SM64_A;
    __half* sBl = smh + 2 * SM64_A + SM64_B;
    __shared__ float sval[128];
    __shared__ int   sidx[128];

    const int tid = threadIdx.x;
    const int warp = tid >> 5, lane = tid & 31;
    const int wm = warp >> 1, wn = warp & 1;
    const int rBase = blockIdx.x << 7;

    float acc[2][4][4];
#pragma unroll
    for (int i = 0; i < 2; i++)
#pragma unroll
        for (int j = 0; j < 4; j++)
#pragma unroll
            for (int q = 0; q < 4; q++) acc[i][j][q] = 0.f;

    const uint32_t uAh = smem_to_u32(sAh);
    const uint32_t uAl = smem_to_u32(sAl);
    const uint32_t uBh = smem_to_u32(sBh);
    const uint32_t uBl = smem_to_u32(sBl);
    const int a_row_l = lane & 15;
    const int a_kh = (lane >> 4) << 3;
    const int b_n_off = (lane & 7) + ((lane >> 4) << 3);
    const int b_k_off = ((lane >> 3) & 1) << 3;

#pragma unroll 1
    for (int c = 0; c < 4; c++) {
#pragma unroll
        for (int s = 0; s < 2; s++) {
            const __half* ap = s ? Alo : Ahi;
            uint32_t ud = s ? uAl : uAh;
#pragma unroll
            for (int j = 0; j < 4; j++) {
                int i = tid + j * 256;
                int row = i >> 3, seg = i & 7;
                int gr = rBase + row;
                int grc = gr < M ? gr : 0;
                unsigned sz = gr < M ? 16u : 0u;
                CP16(ud + (uint32_t)(row * ASTRIDE + seg * 8) * 2,
                     ap + (size_t)grc * 256 + c * 64 + seg * 8, sz);
            }
            const __half* wp = s ? Wl : Wh;
            uint32_t wd = s ? uBl : uBh;
#pragma unroll
            for (int j = 0; j < 2; j++) {
                int i = tid + j * 256;
                int row = i >> 3, seg = i & 7;
                CP16(wd + (uint32_t)(row * ASTRIDE + seg * 8) * 2,
                     wp + (size_t)row * 256 + c * 64 + seg * 8, 16u);
            }
        }
        CP_COMMIT();
        CP_WAIT0();
        __syncthreads();
#pragma unroll
        for (int k = 0; k < 4; k++) {
            const int k0 = k << 4;
            const uint32_t aoff = (uint32_t)(((wm << 5) + a_row_l) * ASTRIDE + k0 + a_kh) * 2;
            const uint32_t boff0 = (uint32_t)(((wn << 5) + b_n_off) * ASTRIDE + k0 + b_k_off) * 2;
            const uint32_t boff1 = boff0 + (uint32_t)(16 * ASTRIDE) * 2;
            uint32_t ah[2][4], al[2][4], bh[2][4], bl[2][4];
#pragma unroll
            for (int mi = 0; mi < 2; mi++) {
                LDMATRIX_X4(ah[mi][0], ah[mi][1], ah[mi][2], ah[mi][3],
                            uAh + aoff + (uint32_t)((mi << 4) * ASTRIDE) * 2);
                LDMATRIX_X4(al[mi][0], al[mi][1], al[mi][2], al[mi][3],
                            uAl + aoff + (uint32_t)((mi << 4) * ASTRIDE) * 2);
            }
            LDMATRIX_X4(bh[0][0], bh[0][1], bh[0][2], bh[0][3], uBh + boff0);
            LDMATRIX_X4(bh[1][0], bh[1][1], bh[1][2], bh[1][3], uBh + boff1);
            LDMATRIX_X4(bl[0][0], bl[0][1], bl[0][2], bl[0][3], uBl + boff0);
            LDMATRIX_X4(bl[1][0], bl[1][1], bl[1][2], bl[1][3], uBl + boff1);
#pragma unroll
            for (int mi = 0; mi < 2; mi++)
#pragma unroll
                for (int ni = 0; ni < 4; ni++) {
                    uint32_t b0h = bh[ni >> 1][(ni & 1) * 2], b1h = bh[ni >> 1][(ni & 1) * 2 + 1];
                    uint32_t b0l = bl[ni >> 1][(ni & 1) * 2], b1l = bl[ni >> 1][(ni & 1) * 2 + 1];
                    MMAF16(acc[mi][ni], ah[mi], b0h, b1h);
                    MMAF16(acc[mi][ni], ah[mi], b0l, b1l);
                    MMAF16(acc[mi][ni], al[mi], b0h, b1h);
                }
        }
        __syncthreads();
    }

    if (MODE == 1) {
#pragma unroll
        for (int mi = 0; mi < 2; mi++)
#pragma unroll
            for (int hf2 = 0; hf2 < 2; hf2++) {
                int gr = rBase + (wm << 5) + (mi << 4) + (lane >> 2) + hf2 * 8;
                if (gr >= M) continue;
#pragma unroll
                for (int ni = 0; ni < 4; ni++) {
                    int col = (wn << 5) + (ni << 3) + (lane & 3) * 2;
                    float o0 = acc[mi][ni][hf2 * 2] * scale;
                    float o1 = acc[mi][ni][hf2 * 2 + 1] * scale;
                    *(float2*)&C[(size_t)gr * 64 + col] = make_float2(o0, o1);
                }
            }
    } else {
        float rv[4]; int ridx[4];
#pragma unroll
        for (int mi = 0; mi < 2; mi++)
#pragma unroll
            for (int hf2 = 0; hf2 < 2; hf2++) {
                float v = -3.4e38f; int idx = 0;
#pragma unroll
                for (int ni = 0; ni < 4; ni++) {
                    int col = (wn << 5) + (ni << 3) + (lane & 3) * 2;
                    float o0 = acc[mi][ni][hf2 * 2] + bias[col];
                    float o1 = acc[mi][ni][hf2 * 2 + 1] + bias[col + 1];
                    if (o0 > v) { v = o0; idx = col; }
                    if (o1 > v) { v = o1; idx = col + 1; }
                }
#pragma unroll
                for (int o = 1; o <= 2; o <<= 1) {
                    float ov = __shfl_xor_sync(0xffffffffu, v, o);
                    int oi = __shfl_xor_sync(0xffffffffu, idx, o);
                    if (ov > v || (ov == v && oi < idx)) { v = ov; idx = oi; }
                }
                int lr = (wm << 5) + (mi << 4) + hf2 * 8 + (lane >> 2);
                if (wn == 0 && (lane & 3) == 0) { sval[lr] = v; sidx[lr] = idx; }
                rv[mi * 2 + hf2] = v; ridx[mi * 2 + hf2] = idx;
            }
        __syncthreads();
        if (wn == 1 && (lane & 3) == 0) {
#pragma unroll
            for (int mi = 0; mi < 2; mi++)
#pragma unroll
                for (int hf2 = 0; hf2 < 2; hf2++) {
                    int lr = (wm << 5) + (mi << 4) + hf2 * 8 + (lane >> 2);
                    int gr = rBase + lr;
                    if (gr >= M) continue;
                    float v0 = sval[lr]; int i0 = sidx[lr];
                    float v1 = rv[mi * 2 + hf2]; int i1 = ridx[mi * 2 + hf2];
                    g_cls[gr] = (v1 > v0) ? i1 : i0;
                }
        }
    }
}

__global__ void k_invnorm() {
    int warp = (blockIdx.x * blockDim.x + threadIdx.x) >> 5;
    int lane = threadIdx.x & 31;
    if (warp >= T_REP * N_NODES) return;
    const float4* r = (const float4*)(g_AF + ((size_t)N_NODES + warp) * 256);
    float4 a = r[lane * 2], b = r[lane * 2 + 1];
    float s = a.x * a.x + a.y * a.y + a.z * a.z + a.w * a.w +
              b.x * b.x + b.y * b.y + b.z * b.z + b.w * b.w;
#pragma unroll
    for (int o = 16; o; o >>= 1) s += __shfl_xor_sync(0xffffffffu, s, o);
    if (lane == 0) g_invn[warp] = 1.f / fmaxf(sqrtf(s), 1e-8f);
}

__device__ __forceinline__ float dot8(float4 f0, float4 f1, float4 a, float4 b) {
    return f0.x * a.x + f0.y * a.y + f0.z * a.z + f0.w * a.w +
           f1.x * b.x + f1.y * b.y + f1.z * b.z + f1.w * b.w;
}

__global__ void k_ocount(const int* __restrict__ ei) {
    int i = blockIdx.x * blockDim.x + threadIdx.x;
    if (i < N_EDGES) atomicAdd(&g_odeg[ei[N_EDGES + i]], 1);
}

__global__ void k_ofill(const int* __restrict__ ei) {
    int i = blockIdx.x * blockDim.x + threadIdx.x;
    if (i >= N_EDGES) return;
    int d = ei[N_EDGES + i];
    int pos = g_orow[d] + atomicAdd(&g_ocur[d], 1);
    g_oedge[pos] = i;
}

__global__ void k_edge_sim2(const int* __restrict__ ei) {
    int d = (blockIdx.x * blockDim.x + threadIdx.x) >> 5;
    if (d >= N_NODES) return;
    int lane = threadIdx.x & 31;
    int len = g_odeg[d];
    if (len == 0) return;
    int start = g_orow[d];
    const float4* t0 = (const float4*)(g_AF + ((size_t)1 * N_NODES + d) * 256);
    const float4* t1 = (const float4*)(g_AF + ((size_t)2 * N_NODES + d) * 256);
    const float4* t2 = (const float4*)(g_AF + ((size_t)3 * N_NODES + d) * 256);
    const float4* t3 = (const float4*)(g_AF + ((size_t)4 * N_NODES + d) * 256);
    float4 a0 = t0[lane * 2], b0 = t0[lane * 2 + 1];
    float4 a1 = t1[lane * 2], b1 = t1[lane * 2 + 1];
    float4 a2 = t2[lane * 2], b2 = t2[lane * 2 + 1];
    float4 a3 = t3[lane * 2], b3 = t3[lane * 2 + 1];
    float i0 = g_invn[d];
    float i1 = g_invn[N_NODES + d];
    float i2 = g_invn[2 * N_NODES + d];
    float i3 = g_invn[3 * N_NODES + d];
    int j = 0;
    for (; j + 2 <= len; j += 2) {
        int e0 = g_oedge[start + j], e1 = g_oedge[start + j + 1];
        int s0 = __ldg(ei + e0), s1 = __ldg(ei + e1);
        const float4* fr0 = (const float4*)(g_AF + (size_t)s0 * 256);
        const float4* fr1 = (const float4*)(g_AF + (size_t)s1 * 256);
        float4 fA = __ldg(fr0 + lane * 2), fB = __ldg(fr0 + lane * 2 + 1);
        float4 gA = __ldg(fr1 + lane * 2), gB = __ldg(fr1 + lane * 2 + 1);
        float p0 = dot8(fA, fB, a0, b0), q0 = dot8(gA, gB, a0, b0);
        float p1 = dot8(fA, fB, a1, b1), q1 = dot8(gA, gB, a1, b1);
        float p2 = dot8(fA, fB, a2, b2), q2 = dot8(gA, gB, a2, b2);
        float p3 = dot8(fA, fB, a3, b3), q3 = dot8(gA, gB, a3, b3);
#pragma unroll
        for (int o = 16; o; o >>= 1) {
            p0 += __shfl_xor_sync(0xffffffffu, p0, o);
            p1 += __shfl_xor_sync(0xffffffffu, p1, o);
            p2 += __shfl_xor_sync(0xffffffffu, p2, o);
            p3 += __shfl_xor_sync(0xffffffffu, p3, o);
            q0 += __shfl_xor_sync(0xffffffffu, q0, o);
            q1 += __shfl_xor_sync(0xffffffffu, q1, o);
            q2 += __shfl_xor_sync(0xffffffffu, q2, o);
            q3 += __shfl_xor_sync(0xffffffffu, q3, o);
        }
        if (lane == 0) {
            float s0v = p0 * i0, s1v = p1 * i1, s2v = p2 * i2, s3v = p3 * i3;
            float bv = s0v; int bi = 0;
            if (s1v > bv) { bv = s1v; bi = 1; }
            if (s2v > bv) { bv = s2v; bi = 2; }
            if (s3v > bv) { bv = s3v; bi = 3; }
            g_best[e0] = bi;
            float u0v = q0 * i0, u1v = q1 * i1, u2v = q2 * i2, u3v = q3 * i3;
            float cv = u0v; int ci = 0;
            if (u1v > cv) { cv = u1v; ci = 1; }
            if (u2v > cv) { cv = u2v; ci = 2; }
            if (u3v > cv) { cv = u3v; ci = 3; }
            g_best[e1] = ci;
        }
    }
    if (j < len) {
        int e = g_oedge[start + j];
        int s = __ldg(ei + e);
        const float4* fr = (const float4*)(g_AF + (size_t)s * 256);
        float4 f0 = __ldg(fr + lane * 2), f1 = __ldg(fr + lane * 2 + 1);
        float p0 = dot8(f0, f1, a0, b0);
        float p1 = dot8(f0, f1, a1, b1);
        float p2 = dot8(f0, f1, a2, b2);
        float p3 = dot8(f0, f1, a3, b3);
#pragma unroll
        for (int o = 16; o; o >>= 1) {
            p0 += __shfl_xor_sync(0xffffffffu, p0, o);
            p1 += __shfl_xor_sync(0xffffffffu, p1, o);
            p2 += __shfl_xor_sync(0xffffffffu, p2, o);
            p3 += __shfl_xor_sync(0xffffffffu, p3, o);
        }
        if (lane == 0) {
            float s0v = p0 * i0, s1v = p1 * i1, s2v = p2 * i2, s3v = p3 * i3;
            float bv = s0v; int bi = 0;
            if (s1v > bv) { bv = s1v; bi = 1; }
            if (s2v > bv) { bv = s2v; bi = 2; }
            if (s3v > bv) { bv = s3v; bi = 3; }
            g_best[e] = bi;
        }
    }
}

__device__ __forceinline__ void decode_edge(const int* __restrict__ ei, int i, int& s, int& d) {
    if (i < N_EDGES) {
        s = ei[i]; d = ei[N_EDGES + i];
    } else if (i < 2 * N_EDGES) {
        int e = i - N_EDGES;
        s = ei[e]; d = ei[N_EDGES + e] + g_best[e] * N_NODES;
    } else {
        int r = i - 2 * N_EDGES;
        int rep = r / N_NODES + 1;
        int n = r - (rep - 1) * N_NODES;
        s = n; d = n + rep * N_NODES;
    }
}

__global__ void k_count(const int* __restrict__ ei) {
    int i = blockIdx.x * blockDim.x + threadIdx.x;
    if (i >= NE_TOT) return;
    int s, d;
    decode_edge(ei, i, s, d);
    if (s != d) atomicAdd(&g_deg[d], 1);
}

__global__ void k_dinv() {
    int i = blockIdx.x * blockDim.x + threadIdx.x;
    if (i < N_TOT) g_dinv[i] = rsqrtf((float)(g_deg[i] + 1));
}

__global__ void k_scan1(const int* __restrict__ in, int* __restrict__ out, int n, int minus) {
    __shared__ int sm[256];
    int tid = threadIdx.x;
    int base = blockIdx.x * SCAN_BLK;
    int loc[4]; int sum = 0;
#pragma unroll
    for (int u = 0; u < 4; u++) {
        int i = base + tid * 4 + u;
        int v = (i < n) ? (in[i] - minus) : 0;
        loc[u] = sum; sum += v;
    }
    sm[tid] = sum;
    __syncthreads();
    for (int o = 1; o < 256; o <<= 1) {
        int t = (tid >= o) ? sm[tid - o] : 0;
        __syncthreads();
        sm[tid] += t;
        __syncthreads();
    }
    int pre = tid ? sm[tid - 1] : 0;
#pragma unroll
    for (int u = 0; u < 4; u++) {
        int i = base + tid * 4 + u;
        if (i < n) out[i] = pre + loc[u];
    }
    if (tid == 255) g_blocksum[blockIdx.x] = sm[255];
}

__global__ void k_scan2(int nb) {
    __shared__ int sm[256];
    int tid = threadIdx.x;
    sm[tid] = (tid < nb) ? g_blocksum[tid] : 0;
    __syncthreads();
    for (int o = 1; o < 256; o <<= 1) {
        int t = (tid >= o) ? sm[tid - o] : 0;
        __syncthreads();
        sm[tid] += t;
        __syncthreads();
    }
    if (tid < nb) g_blocksum[tid] = tid ? sm[tid - 1] : 0;
}

__global__ void k_scan3(int* __restrict__ out, int n) {
    int i = blockIdx.x * blockDim.x + threadIdx.x;
    if (i < n) out[i] += g_blocksum[i >> 10];
}

__global__ void k_fill(const int* __restrict__ ei) {
    int i = blockIdx.x * blockDim.x + threadIdx.x;
    if (i >= NE_TOT) return;
    int s, d;
    decode_edge(ei, i, s, d);
    if (s == d) return;
    int pos = g_rowptr[d] + atomicAdd(&g_cursor[d], 1);
    g_csr_src[pos] = s;
    g_csr_w[pos] = g_dinv[s] * g_dinv[d];
}

template<int WS>
__global__ void k_aggregate(const float* __restrict__ X, const float* __restrict__ bias,
                            float* __restrict__ Out) {
    int w = (blockIdx.x * blockDim.x + threadIdx.x) >> 5;
    if (w >= N_TOT) return;
    int lane = threadIdx.x & 31;
    int start = g_rowptr[w];
    int len = g_deg[w];
    float dv = g_dinv[w];
    float ws = dv * dv;
    const float4* xd = (const float4*)(X + (size_t)w * 256);
    float4 sa = xd[lane * 2], sb = xd[lane * 2 + 1];
    float acc0 = ws * sa.x, acc1 = ws * sa.y, acc2 = ws * sa.z, acc3 = ws * sa.w;
    float acc4 = ws * sb.x, acc5 = ws * sb.y, acc6 = ws * sb.z, acc7 = ws * sb.w;
    int j = 0;
    for (; j + 4 <= len; j += 4) {
        int s0 = g_csr_src[start + j];
        int s1 = g_csr_src[start + j + 1];
        int s2 = g_csr_src[start + j + 2];
        int s3 = g_csr_src[start + j + 3];
        float w0 = g_csr_w[start + j];
        float w1 = g_csr_w[start + j + 1];
        float w2 = g_csr_w[start + j + 2];
        float w3 = g_csr_w[start + j + 3];
        const float4* x0 = (const float4*)(X + (size_t)s0 * 256);
        const float4* x1 = (const float4*)(X + (size_t)s1 * 256);
        const float4* x2 = (const float4*)(X + (size_t)s2 * 256);
        const float4* x3 = (const float4*)(X + (size_t)s3 * 256);
        float4 u0 = x0[lane * 2], v0 = x0[lane * 2 + 1];
        float4 u1 = x1[lane * 2], v1 = x1[lane * 2 + 1];
        float4 u2 = x2[lane * 2], v2 = x2[lane * 2 + 1];
        float4 u3 = x3[lane * 2], v3 = x3[lane * 2 + 1];
        acc0 = fmaf(w0, u0.x, acc0); acc1 = fmaf(w0, u0.y, acc1);
        acc2 = fmaf(w0, u0.z, acc2); acc3 = fmaf(w0, u0.w, acc3);
        acc4 = fmaf(w0, v0.x, acc4); acc5 = fmaf(w0, v0.y, acc5);
        acc6 = fmaf(w0, v0.z, acc6); acc7 = fmaf(w0, v0.w, acc7);
        acc0 = fmaf(w1, u1.x, acc0); acc1 = fmaf(w1, u1.y, acc1);
        acc2 = fmaf(w1, u1.z, acc2); acc3 = fmaf(w1, u1.w, acc3);
        acc4 = fmaf(w1, v1.x, acc4); acc5 = fmaf(w1, v1.y, acc5);
        acc6 = fmaf(w1, v1.z, acc6); acc7 = fmaf(w1, v1.w, acc7);
        acc0 = fmaf(w2, u2.x, acc0); acc1 = fmaf(w2, u2.y, acc1);
        acc2 = fmaf(w2, u2.z, acc2); acc3 = fmaf(w2, u2.w, acc3);
        acc4 = fmaf(w2, v2.x, acc4); acc5 = fmaf(w2, v2.y, acc5);
        acc6 = fmaf(w2, v2.z, acc6); acc7 = fmaf(w2, v2.w, acc7);
        acc0 = fmaf(w3, u3.x, acc0); acc1 = fmaf(w3, u3.y, acc1);
        acc2 = fmaf(w3, u3.z, acc2); acc3 = fmaf(w3, u3.w, acc3);
        acc4 = fmaf(w3, v3.x, acc4); acc5 = fmaf(w3, v3.y, acc5);
        acc6 = fmaf(w3, v3.z, acc6); acc7 = fmaf(w3, v3.w, acc7);
    }
    for (; j < len; j++) {
        int s0 = g_csr_src[start + j];
        float w0 = g_csr_w[start + j];
        const float4* x0 = (const float4*)(X + (size_t)s0 * 256);
        float4 u0 = x0[lane * 2], v0 = x0[lane * 2 + 1];
        acc0 = fmaf(w0, u0.x, acc0); acc1 = fmaf(w0, u0.y, acc1);
        acc2 = fmaf(w0, u0.z, acc2); acc3 = fmaf(w0, u0.w, acc3);
        acc4 = fmaf(w0, v0.x, acc4); acc5 = fmaf(w0, v0.y, acc5);
        acc6 = fmaf(w0, v0.z, acc6); acc7 = fmaf(w0, v0.w, acc7);
    }
    const float4* b4 = (const float4*)bias;
    float4 bb0 = b4[lane * 2], bb1 = b4[lane * 2 + 1];
    float o[8] = {acc0 + bb0.x, acc1 + bb0.y, acc2 + bb0.z, acc3 + bb0.w,
                  acc4 + bb1.x, acc5 + bb1.y, acc6 + bb1.z, acc7 + bb1.w};
    float4* od = (float4*)(Out + (size_t)w * 256);
    od[lane * 2] = make_float4(o[0], o[1], o[2], o[3]);
    od[lane * 2 + 1] = make_float4(o[4], o[5], o[6], o[7]);
    if (WS) {
        uint32_t hw[4], lw[4];
#pragma unroll
        for (int q = 0; q < 4; q++) {
            __half h0, l0, h1, l1;
            split2(fmaxf(o[q * 2], 0.f), h0, l0);
            split2(fmaxf(o[q * 2 + 1], 0.f), h1, l1);
            hw[q] = hpack2(h0, h1); lw[q] = hpack2(l0, l1);
        }
        size_t so = (size_t)w * 256 + lane * 8;
        *(uint4*)(g_Ahi + so) = make_uint4(hw[0], hw[1], hw[2], hw[3]);
        *(uint4*)(g_Alo + so) = make_uint4(lw[0], lw[1], lw[2], lw[3]);
    }
}

__global__ void k_H(float* __restrict__ Hout) {
    int n = blockIdx.x * blockDim.x + threadIdx.x;
    if (n >= N_NODES) return;
    int c0 = g_cls[n];
    int c1 = g_cls[N_NODES + n];
    int c2 = g_cls[2 * N_NODES + n];
    int c3 = g_cls[3 * N_NODES + n];
    int c4 = g_cls[4 * N_NODES + n];
    float* o = Hout + (size_t)n * 64;
#pragma unroll
    for (int j = 0; j < 64; j++)
        o[j] = (float)((c0 == j) + (c1 == j) + (c2 == j) + (c3 == j) + (c4 == j));
}

__global__ void k_hyperedge(const float* __restrict__ Hout, float* __restrict__ hf) {
    extern __shared__ float acc[];
    int tid = threadIdx.x;
    for (int i = tid; i < 16384; i += 256) acc[i] = 0.f;
    __syncthreads();
    int warp = tid >> 5, lane = tid & 31;
    for (int n = blockIdx.x * 8 + warp; n < N_NODES; n += gridDim.x * 8) {
        float h0 = Hout[(size_t)n * 64 + lane];
        float h1 = Hout[(size_t)n * 64 + lane + 32];
        unsigned m0 = __ballot_sync(0xffffffffu, h0 > 0.f);
        unsigned m1 = __ballot_sync(0xffffffffu, h1 > 0.f);
        const float4* xr = (const float4*)(g_B + (size_t)n * 256);
        float4 a = xr[lane * 2], b = xr[lane * 2 + 1];
        unsigned mm = m0;
        while (mm) {
            int c = __ffs(mm) - 1; mm &= mm - 1;
            float* p = acc + c * 256 + lane * 8;
            atomicAdd(p + 0, a.x); atomicAdd(p + 1, a.y); atomicAdd(p + 2, a.z); atomicAdd(p + 3, a.w);
            atomicAdd(p + 4, b.x); atomicAdd(p + 5, b.y); atomicAdd(p + 6, b.z); atomicAdd(p + 7, b.w);
        }
        mm = m1;
        while (mm) {
            int c = (__ffs(mm) - 1) + 32; mm &= mm - 1;
            float* p = acc + c * 256 + lane * 8;
            atomicAdd(p + 0, a.x); atomicAdd(p + 1, a.y); atomicAdd(p + 2, a.z); atomicAdd(p + 3, a.w);
            atomicAdd(p + 4, b.x); atomicAdd(p + 5, b.y); atomicAdd(p + 6, b.z); atomicAdd(p + 7, b.w);
        }
    }
    __syncthreads();
    for (int i = tid; i < 16384; i += 256) atomicAdd(&hf[i], acc[i]);
}

// ---------------- launch ----------------
extern "C" void kernel_launch(void* const* d_in, const int* in_sizes, int n_in,
                              void* d_out, int out_size) {
    const int*   ei       = (const int*)d_in[0];
    const float* features = (const float*)d_in[1];
    const float* lin_w    = (const float*)d_in[2];
    const float* lin_b    = (const float*)d_in[3];
    const float* gcn0_w   = (const float*)d_in[4];
    const float* gcn0_b   = (const float*)d_in[5];
    const float* gcn1_w   = (const float*)d_in[6];
    const float* gcn1_b   = (const float*)d_in[7];
    const float* lin1_w   = (const float*)d_in[8];
    const float* lin1_b   = (const float*)d_in[9];

    float* out      = (float*)d_out;
    float* H_out    = out;
    float* hf_out   = out + (size_t)N_NODES * NS;
    float* dots_out = hf_out + NS * D;

    float *AF, *X, *B, *ZB;
    int *CUR, *DEG, *ROWPTR, *ODEG, *OROW, *OCUR;
    __half *AH, *AL, *AH2, *AL2, *WH, *WL;
    cudaGetSymbolAddress((void**)&AF, g_AF);
    cudaGetSymbolAddress((void**)&X,  g_X);
    cudaGetSymbolAddress((void**)&B,  g_B);
    cudaGetSymbolAddress((void**)&ZB, g_zerobias);
    cudaGetSymbolAddress((void**)&CUR, g_cursor);
    cudaGetSymbolAddress((void**)&DEG, g_deg);
    cudaGetSymbolAddress((void**)&ROWPTR, g_rowptr);
    cudaGetSymbolAddress((void**)&ODEG, g_odeg);
    cudaGetSymbolAddress((void**)&OROW, g_orow);
    cudaGetSymbolAddress((void**)&OCUR, g_ocur);
    cudaGetSymbolAddress((void**)&AH, g_Ahi);
    cudaGetSymbolAddress((void**)&AL, g_Alo);
    cudaGetSymbolAddress((void**)&AH2, g_Ahi2);
    cudaGetSymbolAddress((void**)&AL2, g_Alo2);
    cudaGetSymbolAddress((void**)&WH, g_Whi);
    cudaGetSymbolAddress((void**)&WL, g_Wlo);

    cudaFuncSetAttribute(k_hyperedge,  cudaFuncAttributeMaxDynamicSharedMemorySize, 65536);
    cudaFuncSetAttribute(k_mmagemm<0>, cudaFuncAttributeMaxDynamicSharedMemorySize, SMG_BYTES);
    cudaFuncSetAttribute(k_mmagemm<1>, cudaFuncAttributeMaxDynamicSharedMemorySize, SMG_BYTES);
    cudaFuncSetAttribute(k_mmagemm64<0>, cudaFuncAttributeMaxDynamicSharedMemorySize, SM64_BYTES);
    cudaFuncSetAttribute(k_mmagemm64<1>, cudaFuncAttributeMaxDynamicSharedMemorySize, SM64_BYTES);

    const int nb_tot  = (N_TOT + SCAN_BLK - 1) / SCAN_BLK;
    const int nb_node = (N_NODES + SCAN_BLK - 1) / SCAN_BLK;

    // weight splits (heads fused via gridDim.y) + raw feature split (buf1+buf2+AF copy)
    k_wsplit<<<dim3(256, 4), 256>>>(lin_w, 0, 256, 65536);
    k_split<0, 1, 1><<<(N_NODES * 64 + 255) / 256, 256>>>((const float4*)features, N_NODES * 64);

    // heads GEMM on raw features; epilogue: split(relu)->buf1, split(raw)->buf2, rows N..5N
    k_mmagemm<1><<<dim3(2, (N_NODES + 127) / 128, 4), 256, SMG_BYTES>>>(
        AH, AL, WH, WL, lin_b, AF + (size_t)N_NODES * 256,
        N_NODES, 65536, N_NODES * 256, 256, N_NODES, N_NODES);

    k_wsplit<<<dim3(256, 1), 256>>>(gcn0_w, 4, 256, 0);
    k_wsplit<<<dim3(256, 1), 256>>>(gcn1_w, 5, 256, 0);
    k_wsplit<<<dim3(64, 1), 256>>>(lin1_w, 6, 64, 0);
    k_split<1, 0, 0><<<(N_NODES * 64 + 255) / 256, 256>>>((const float4*)features, N_NODES * 64);

    // original-edge CSR
    cudaMemsetAsync(ODEG, 0, N_NODES * sizeof(int));
    cudaMemsetAsync(OCUR, 0, N_NODES * sizeof(int));
    k_ocount<<<(N_EDGES + 255) / 256, 256>>>(ei);
    k_scan1<<<nb_node, 256>>>(ODEG, OROW, N_NODES, 0);
    k_scan2<<<1, 256>>>(nb_node);
    k_scan3<<<(N_NODES + 255) / 256, 256>>>(OROW, N_NODES);
    k_ofill<<<(N_EDGES + 255) / 256, 256>>>(ei);

    // per-edge best replica
    k_invnorm<<<(T_REP * N_NODES * 32 + 255) / 256, 256>>>();
    k_edge_sim2<<<(N_NODES * 32 + 255) / 256, 256>>>(ei);

    // augmented-graph CSR (deg = in-edge count, self loop folded into dinv)
    cudaMemsetAsync(DEG, 0, N_TOT * sizeof(int));
    k_count<<<(NE_TOT + 255) / 256, 256>>>(ei);
    k_dinv<<<(N_TOT + 255) / 256, 256>>>();
    k_scan1<<<nb_tot, 256>>>(DEG, ROWPTR, N_TOT, 0);
    k_scan2<<<1, 256>>>(nb_tot);
    k_scan3<<<(N_TOT + 255) / 256, 256>>>(ROWPTR, N_TOT);
    cudaMemsetAsync(CUR, 0, N_TOT * sizeof(int));
    k_fill<<<(NE_TOT + 255) / 256, 256>>>(ei);

    // GCN layer 0
    k_mmagemm<0><<<dim3(2, (N_TOT + 127) / 128, 1), 256, SMG_BYTES>>>(
        AH, AL, WH + 4 * 65536, WL + 4 * 65536, ZB, X, N_TOT, 0, 0, 0, 0, 0);
    k_aggregate<1><<<(N_TOT * 32 + 255) / 256, 256>>>(X, gcn0_b, B);

    // GCN layer 1
    k_mmagemm<0><<<dim3(2, (N_TOT + 127) / 128, 1), 256, SMG_BYTES>>>(
        AH, AL, WH + 5 * 65536, WL + 5 * 65536, ZB, X, N_TOT, 0, 0, 0, 0, 0);
    k_aggregate<1><<<(N_TOT * 32 + 255) / 256, 256>>>(X, gcn1_b, B);

    // logits mma with fused argmax -> g_cls; then H
    k_mmagemm64<0><<<(N_TOT + 127) / 128, 256, SM64_BYTES>>>(
        AH, AL, WH + 6 * 65536, WL + 6 * 65536, lin1_b, X, N_TOT, 0.f);
    k_H<<<(N_NODES + 255) / 256, 256>>>(H_out);

    // hyperedge features, split hf into slot 7
    cudaMemsetAsync(hf_out, 0, (size_t)NS * D * sizeof(float));
    k_hyperedge<<<160, 256, 65536>>>(H_out, hf_out);
    k_wsplit_dir<<<64, 256>>>(hf_out, 7, NS * D);

    // dots via mma on raw-AF splits (buf2)
    k_mmagemm64<1><<<(N_TOT + 127) / 128, 256, SM64_BYTES>>>(
        AH2, AL2, WH + 7 * 65536, WL + 7 * 65536, ZB, dots_out, N_TOT, 0.0625f);
}

// round 14
// speedup vs baseline: 1.0471x; 1.0293x over previous
#include <cuda_runtime.h>
#include <cuda_fp16.h>
#include <cstdint>

#define N_NODES 50000
#define N_EDGES 800000
#define D 256
#define T_REP 4
#define NS 64
#define N_TOT (5 * N_NODES)                 /* 250000 */
#define NE_TOT (2 * N_EDGES + 3 * N_NODES)  /* 1750000 */
#define SCAN_BLK 1024
#define NPAD 250112

typedef unsigned long long u64;

__device__ __forceinline__ uint32_t smem_to_u32(const void* p) {
    uint32_t a;
    asm("{ .reg .u64 t; cvta.to.shared.u64 t, %1; cvt.u32.u64 %0, t; }" : "=r"(a) : "l"(p));
    return a;
}

#define LDMATRIX_X4(r0, r1, r2, r3, addr) \
    asm volatile("ldmatrix.sync.aligned.m8n8.x4.shared.b16 {%0,%1,%2,%3}, [%4];" \
                 : "=r"(r0), "=r"(r1), "=r"(r2), "=r"(r3) : "r"(addr))

#define MMAF16(c, a, b0, b1) \
    asm volatile("mma.sync.aligned.m16n8k16.row.col.f32.f16.f16.f32 " \
                 "{%0,%1,%2,%3}, {%4,%5,%6,%7}, {%8,%9}, {%0,%1,%2,%3};" \
                 : "+f"((c)[0]), "+f"((c)[1]), "+f"((c)[2]), "+f"((c)[3]) \
                 : "r"((a)[0]), "r"((a)[1]), "r"((a)[2]), "r"((a)[3]), "r"(b0), "r"(b1))

#define CP16(dst, src, sz) \
    asm volatile("cp.async.cg.shared.global [%0], [%1], 16, %2;" \
                 :: "r"(dst), "l"(src), "r"(sz))
#define CP_COMMIT() asm volatile("cp.async.commit_group;" ::: "memory")
#define CP_WAIT0()  asm volatile("cp.async.wait_group 0;" ::: "memory")

__device__ __forceinline__ void split2(float x, __half& h, __half& l) {
    h = __float2half_rn(x);
    l = __float2half_rn(x - __half2float(h));
}
__device__ __forceinline__ uint32_t hpack2(__half a, __half b) {
    return (uint32_t)__half_as_ushort(a) | ((uint32_t)__half_as_ushort(b) << 16);
}

// ---------------- scratch (device globals) ----------------
__device__ float g_AF[(size_t)N_TOT * D];
__device__ float g_X[(size_t)N_TOT * D];
__device__ float g_B[(size_t)N_TOT * D];
__device__ float g_invn[T_REP * N_NODES];
__device__ int   g_deg[N_TOT];              // in-edge count (no self loop)
__device__ float g_dinv[N_TOT];
__device__ int   g_best[N_EDGES];
__device__ int   g_cls[N_TOT];
__device__ float g_zerobias[D];
__device__ int   g_rowptr[N_TOT];
__device__ int   g_blocksum[256];
__device__ int   g_cursor[N_TOT];
__device__ int   g_csr_src[NE_TOT];
__device__ float g_csr_w[NE_TOT];
__device__ int   g_odeg[N_NODES];
__device__ int   g_orow[N_NODES];
__device__ int   g_ocur[N_NODES];
__device__ int   g_oedge[N_EDGES];
// fp16 split buffers: buf1 = GEMM activations (relu), buf2 = raw AF (for dots + heads A)
__device__ __half g_Ahi[(size_t)NPAD * D];
__device__ __half g_Alo[(size_t)NPAD * D];
__device__ __half g_Ahi2[(size_t)NPAD * D];
__device__ __half g_Alo2[(size_t)NPAD * D];
__device__ __half g_Whi[8 * 65536];
__device__ __half g_Wlo[8 * 65536];

// ---------------- small kernels ----------------

// split relu(X) -> buf1, raw X -> buf2, raw X -> g_AF
__global__ void k_split_both(const float4* __restrict__ X, int n4) {
    int i = blockIdx.x * blockDim.x + threadIdx.x;
    if (i >= n4) return;
    float4 v = X[i];
    ((float4*)g_AF)[i] = v;
    __half h0,l0,h1,l1,h2,l2,h3,l3;
    split2(v.x,h0,l0); split2(v.y,h1,l1); split2(v.z,h2,l2); split2(v.w,h3,l3);
    ((uint2*)g_Ahi2)[i] = make_uint2(hpack2(h0,h1), hpack2(h2,h3));
    ((uint2*)g_Alo2)[i] = make_uint2(hpack2(l0,l1), hpack2(l2,l3));
    float x0 = fmaxf(v.x, 0.f), x1 = fmaxf(v.y, 0.f);
    float x2 = fmaxf(v.z, 0.f), x3 = fmaxf(v.w, 0.f);
    split2(x0,h0,l0); split2(x1,h1,l1); split2(x2,h2,l2); split2(x3,h3,l3);
    ((uint2*)g_Ahi)[i] = make_uint2(hpack2(h0,h1), hpack2(h2,h3));
    ((uint2*)g_Alo)[i] = make_uint2(hpack2(l0,l1), hpack2(l2,l3));
}

// split + transpose a [256 x ncols] weight into slot widxBase + blockIdx.y
__global__ void k_wsplit(const float* __restrict__ W, int widxBase, int ncols, int wstride) {
    int widx = widxBase + blockIdx.y;
    const float* Wz = W + (size_t)blockIdx.y * wstride;
    int i = blockIdx.x * 256 + threadIdx.x;
    int n = i >> 8, k = i & 255;
    float x = Wz[k * ncols + n];
    __half h, l;
    split2(x, h, l);
    g_Whi[widx * 65536 + i] = h;
    g_Wlo[widx * 65536 + i] = l;
}

__global__ void k_wsplit_dir(const float* __restrict__ src, int widx, int nelem) {
    int i = blockIdx.x * 256 + threadIdx.x;
    if (i >= nelem) return;
    __half h, l;
    split2(src[i], h, l);
    g_Whi[widx * 65536 + i] = h;
    g_Wlo[widx * 65536 + i] = l;
}

// ---- fp16x3 GEMM (N=256): C[M,256] = A @ W + bias ----
#define ASTRIDE 72
#define SMBUF (128 * ASTRIDE)
#define SMG_BYTES (4 * SMBUF * 2)
template<int WS>
__global__ __launch_bounds__(256, 2) void k_mmagemm(
    const __half* Ahi, const __half* Alo,
    const __half* __restrict__ Whi, const __half* __restrict__ Wlo,
    const float* __restrict__ bias, float* __restrict__ C,
    int M, int wz, int cz, int bzs, int splitBase, int splitZ)
{
    extern __shared__ __half smh[];
    __half* sAh = smh;
    __half* sAl = smh + SMBUF;
    __half* sBh = smh + 2 * SMBUF;
    __half* sBl = smh + 3 * SMBUF;

    const int tid = threadIdx.x;
    const int warp = tid >> 5, lane = tid & 31;
    const int wm = warp & 1, wn = warp >> 1;
    const int z = blockIdx.z;
    const int rBase = blockIdx.y << 7;
    const int colBase = blockIdx.x << 7;

    const __half* Wh = Whi + (size_t)z * wz;
    const __half* Wl = Wlo + (size_t)z * wz;

    float acc[4][4][4];
#pragma unroll
    for (int i = 0; i < 4; i++)
#pragma unroll
        for (int j = 0; j < 4; j++)
#pragma unroll
            for (int q = 0; q < 4; q++) acc[i][j][q] = 0.f;

    const uint32_t uAh = smem_to_u32(sAh);
    const uint32_t uAl = smem_to_u32(sAl);
    const uint32_t uBh = smem_to_u32(sBh);
    const uint32_t uBl = smem_to_u32(sBl);
    const int a_row_l = lane & 15;
    const int a_kh = (lane >> 4) << 3;
    const int b_n_off = (lane & 7) + ((lane >> 4) << 3);
    const int b_k_off = ((lane >> 3) & 1) << 3;

#pragma unroll 1
    for (int c = 0; c < 4; c++) {
#pragma unroll
        for (int s = 0; s < 2; s++) {
            const __half* ap = s ? Alo : Ahi;
            uint32_t ud = s ? uAl : uAh;
#pragma unroll
            for (int j = 0; j < 4; j++) {
                int i = tid + j * 256;
                int row = i >> 3, seg = i & 7;
                int gr = rBase + row;
                int grc = gr < M ? gr : 0;
                unsigned sz = gr < M ? 16u : 0u;
                CP16(ud + (uint32_t)(row * ASTRIDE + seg * 8) * 2,
                     ap + (size_t)grc * 256 + c * 64 + seg * 8, sz);
            }
            const __half* wp = s ? Wl : Wh;
            uint32_t wd = s ? uBl : uBh;
#pragma unroll
            for (int j = 0; j < 4; j++) {
                int i = tid + j * 256;
                int row = i >> 3, seg = i & 7;
                CP16(wd + (uint32_t)(row * ASTRIDE + seg * 8) * 2,
                     wp + (size_t)(colBase + row) * 256 + c * 64 + seg * 8, 16u);
            }
        }
        CP_COMMIT();
        CP_WAIT0();
        __syncthreads();
#pragma unroll
        for (int k = 0; k < 4; k++) {
            const int k0 = k << 4;
            const uint32_t aoff = (uint32_t)(((wm << 6) + a_row_l) * ASTRIDE + k0 + a_kh) * 2;
            const uint32_t boff0 = (uint32_t)(((wn << 5) + b_n_off) * ASTRIDE + k0 + b_k_off) * 2;
            const uint32_t boff1 = boff0 + (uint32_t)(16 * ASTRIDE) * 2;
            uint32_t ah[4][4], al[4][4], bh[2][4], bl[2][4];
#pragma unroll
            for (int mi = 0; mi < 4; mi++) {
                LDMATRIX_X4(ah[mi][0], ah[mi][1], ah[mi][2], ah[mi][3],
                            uAh + aoff + (uint32_t)((mi << 4) * ASTRIDE) * 2);
                LDMATRIX_X4(al[mi][0], al[mi][1], al[mi][2], al[mi][3],
                            uAl + aoff + (uint32_t)((mi << 4) * ASTRIDE) * 2);
            }
            LDMATRIX_X4(bh[0][0], bh[0][1], bh[0][2], bh[0][3], uBh + boff0);
            LDMATRIX_X4(bh[1][0], bh[1][1], bh[1][2], bh[1][3], uBh + boff1);
            LDMATRIX_X4(bl[0][0], bl[0][1], bl[0][2], bl[0][3], uBl + boff0);
            LDMATRIX_X4(bl[1][0], bl[1][1], bl[1][2], bl[1][3], uBl + boff1);
#pragma unroll
            for (int mi = 0; mi < 4; mi++)
#pragma unroll
                for (int ni = 0; ni < 4; ni++) {
                    uint32_t b0h = bh[ni >> 1][(ni & 1) * 2], b1h = bh[ni >> 1][(ni & 1) * 2 + 1];
                    uint32_t b0l = bl[ni >> 1][(ni & 1) * 2], b1l = bl[ni >> 1][(ni & 1) * 2 + 1];
                    MMAF16(acc[mi][ni], ah[mi], b0h, b1h);
                    MMAF16(acc[mi][ni], ah[mi], b0l, b1l);
                    MMAF16(acc[mi][ni], al[mi], b0h, b1h);
                }
        }
        __syncthreads();
    }

    const float* bp = bias + (size_t)z * bzs;
    float* Cz = C + (size_t)z * cz;
#pragma unroll
    for (int mi = 0; mi < 4; mi++) {
#pragma unroll
        for (int hf2 = 0; hf2 < 2; hf2++) {
            int gr = rBase + (wm << 6) + (mi << 4) + (lane >> 2) + hf2 * 8;
            if (gr >= M) continue;
#pragma unroll
            for (int ni = 0; ni < 4; ni++) {
                int col = colBase + (wn << 5) + (ni << 3) + (lane & 3) * 2;
                float o0 = acc[mi][ni][hf2 * 2] + bp[col];
                float o1 = acc[mi][ni][hf2 * 2 + 1] + bp[col + 1];
                *(float2*)&Cz[(size_t)gr * 256 + col] = make_float2(o0, o1);
                if (WS) {
                    size_t so = (size_t)(splitBase + z * splitZ + gr) * 256 + col;
                    __half h0, l0, h1, l1;
                    split2(fmaxf(o0, 0.f), h0, l0);
                    split2(fmaxf(o1, 0.f), h1, l1);
                    *(uint32_t*)(g_Ahi + so) = hpack2(h0, h1);
                    *(uint32_t*)(g_Alo + so) = hpack2(l0, l1);
                    split2(o0, h0, l0);
                    split2(o1, h1, l1);
                    *(uint32_t*)(g_Ahi2 + so) = hpack2(h0, h1);
                    *(uint32_t*)(g_Alo2 + so) = hpack2(l0, l1);
                }
            }
        }
    }
}

// ---- fp16x3 GEMM (N=64): MODE 0 logits+fused argmax; MODE 1 *scale ----
#define SM64_A (128 * ASTRIDE)
#define SM64_B (64 * ASTRIDE)
#define SM64_BYTES ((2 * SM64_A + 2 * SM64_B) * 2)
template<int MODE>
__global__ __launch_bounds__(256, 2) void k_mmagemm64(
    const __half* Ahi, const __half* Alo,
    const __half* __restrict__ Wh, const __half* __restrict__ Wl,
    const float* __restrict__ bias, float* __restrict__ C, int M, float scale)
{
    extern __shared__ __half smh[];
    __half* sAh = smh;
    __half* sAl = smh + SM64_A;
    __half* sBh = smh + 2 * SM64_A;
    __half* sBl = smh + 2 * SM64_A + SM64_B;
    __shared__ float sval[128];
    __shared__ int   sidx[128];

    const int tid = threadIdx.x;
    const int warp = tid >> 5, lane = tid & 31;
    const int wm = warp >> 1, wn = warp & 1;
    const int rBase = blockIdx.x << 7;

    float acc[2][4][4];
#pragma unroll
    for (int i = 0; i < 2; i++)
#pragma unroll
        for (int j = 0; j < 4; j++)
#pragma unroll
            for (int q = 0; q < 4; q++) acc[i][j][q] = 0.f;

    const uint32_t uAh = smem_to_u32(sAh);
    const uint32_t uAl = smem_to_u32(sAl);
    const uint32_t uBh = smem_to_u32(sBh);
    const uint32_t uBl = smem_to_u32(sBl);
    const int a_row_l = lane & 15;
    const int a_kh = (lane >> 4) << 3;
    const int b_n_off = (lane & 7) + ((lane >> 4) << 3);
    const int b_k_off = ((lane >> 3) & 1) << 3;

#pragma unroll 1
    for (int c = 0; c < 4; c++) {
#pragma unroll
        for (int s = 0; s < 2; s++) {
            const __half* ap = s ? Alo : Ahi;
            uint32_t ud = s ? uAl : uAh;
#pragma unroll
            for (int j = 0; j < 4; j++) {
                int i = tid + j * 256;
                int row = i >> 3, seg = i & 7;
                int gr = rBase + row;
                int grc = gr < M ? gr : 0;
                unsigned sz = gr < M ? 16u : 0u;
                CP16(ud + (uint32_t)(row * ASTRIDE + seg * 8) * 2,
                     ap + (size_t)grc * 256 + c * 64 + seg * 8, sz);
            }
            const __half* wp = s ? Wl : Wh;
            uint32_t wd = s ? uBl : uBh;
#pragma unroll
            for (int j = 0; j < 2; j++) {
                int i = tid + j * 256;
                int row = i >> 3, seg = i & 7;
                CP16(wd + (uint32_t)(row * ASTRIDE + seg * 8) * 2,
                     wp + (size_t)row * 256 + c * 64 + seg * 8, 16u);
            }
        }
        CP_COMMIT();
        CP_WAIT0();
        __syncthreads();
#pragma unroll
        for (int k = 0; k < 4; k++) {
            const int k0 = k << 4;
            const uint32_t aoff = (uint32_t)(((wm << 5) + a_row_l) * ASTRIDE + k0 + a_kh) * 2;
            const uint32_t boff0 = (uint32_t)(((wn << 5) + b_n_off) * ASTRIDE + k0 + b_k_off) * 2;
            const uint32_t boff1 = boff0 + (uint32_t)(16 * ASTRIDE) * 2;
            uint32_t ah[2][4], al[2][4], bh[2][4], bl[2][4];
#pragma unroll
            for (int mi = 0; mi < 2; mi++) {
                LDMATRIX_X4(ah[mi][0], ah[mi][1], ah[mi][2], ah[mi][3],
                            uAh + aoff + (uint32_t)((mi << 4) * ASTRIDE) * 2);
                LDMATRIX_X4(al[mi][0], al[mi][1], al[mi][2], al[mi][3],
                            uAl + aoff + (uint32_t)((mi << 4) * ASTRIDE) * 2);
            }
            LDMATRIX_X4(bh[0][0], bh[0][1], bh[0][2], bh[0][3], uBh + boff0);
            LDMATRIX_X4(bh[1][0], bh[1][1], bh[1][2], bh[1][3], uBh + boff1);
            LDMATRIX_X4(bl[0][0], bl[0][1], bl[0][2], bl[0][3], uBl + boff0);
            LDMATRIX_X4(bl[1][0], bl[1][1], bl[1][2], bl[1][3], uBl + boff1);
#pragma unroll
            for (int mi = 0; mi < 2; mi++)
#pragma unroll
                for (int ni = 0; ni < 4; ni++) {
                    uint32_t b0h = bh[ni >> 1][(ni & 1) * 2], b1h = bh[ni >> 1][(ni & 1) * 2 + 1];
                    uint32_t b0l = bl[ni >> 1][(ni & 1) * 2], b1l = bl[ni >> 1][(ni & 1) * 2 + 1];
                    MMAF16(acc[mi][ni], ah[mi], b0h, b1h);
                    MMAF16(acc[mi][ni], ah[mi], b0l, b1l);
                    MMAF16(acc[mi][ni], al[mi], b0h, b1h);
                }
        }
        __syncthreads();
    }

    if (MODE == 1) {
#pragma unroll
        for (int mi = 0; mi < 2; mi++)
#pragma unroll
            for (int hf2 = 0; hf2 < 2; hf2++) {
                int gr = rBase + (wm << 5) + (mi << 4) + (lane >> 2) + hf2 * 8;
                if (gr >= M) continue;
#pragma unroll
                for (int ni = 0; ni < 4; ni++) {
                    int col = (wn << 5) + (ni << 3) + (lane & 3) * 2;
                    float o0 = acc[mi][ni][hf2 * 2] * scale;
                    float o1 = acc[mi][ni][hf2 * 2 + 1] * scale;
                    *(float2*)&C[(size_t)gr * 64 + col] = make_float2(o0, o1);
                }
            }
    } else {
        float rv[4]; int ridx[4];
#pragma unroll
        for (int mi = 0; mi < 2; mi++)
#pragma unroll
            for (int hf2 = 0; hf2 < 2; hf2++) {
                float v = -3.4e38f; int idx = 0;
#pragma unroll
                for (int ni = 0; ni < 4; ni++) {
                    int col = (wn << 5) + (ni << 3) + (lane & 3) * 2;
                    float o0 = acc[mi][ni][hf2 * 2] + bias[col];
                    float o1 = acc[mi][ni][hf2 * 2 + 1] + bias[col + 1];
                    if (o0 > v) { v = o0; idx = col; }
                    if (o1 > v) { v = o1; idx = col + 1; }
                }
#pragma unroll
                for (int o = 1; o <= 2; o <<= 1) {
                    float ov = __shfl_xor_sync(0xffffffffu, v, o);
                    int oi = __shfl_xor_sync(0xffffffffu, idx, o);
                    if (ov > v || (ov == v && oi < idx)) { v = ov; idx = oi; }
                }
                int lr = (wm << 5) + (mi << 4) + hf2 * 8 + (lane >> 2);
                if (wn == 0 && (lane & 3) == 0) { sval[lr] = v; sidx[lr] = idx; }
                rv[mi * 2 + hf2] = v; ridx[mi * 2 + hf2] = idx;
            }
        __syncthreads();
        if (wn == 1 && (lane & 3) == 0) {
#pragma unroll
            for (int mi = 0; mi < 2; mi++)
#pragma unroll
                for (int hf2 = 0; hf2 < 2; hf2++) {
                    int lr = (wm << 5) + (mi << 4) + hf2 * 8 + (lane >> 2);
                    int gr = rBase + lr;
                    if (gr >= M) continue;
                    float v0 = sval[lr]; int i0 = sidx[lr];
                    float v1 = rv[mi * 2 + hf2]; int i1 = ridx[mi * 2 + hf2];
                    g_cls[gr] = (v1 > v0) ? i1 : i0;
                }
        }
    }
}

__global__ void k_invnorm() {
    int warp = (blockIdx.x * blockDim.x + threadIdx.x) >> 5;
    int lane = threadIdx.x & 31;
    if (warp >= T_REP * N_NODES) return;
    const float4* r = (const float4*)(g_AF + ((size_t)N_NODES + warp) * 256);
    float4 a = r[lane * 2], b = r[lane * 2 + 1];
    float s = a.x * a.x + a.y * a.y + a.z * a.z + a.w * a.w +
              b.x * b.x + b.y * b.y + b.z * b.z + b.w * b.w;
#pragma unroll
    for (int o = 16; o; o >>= 1) s += __shfl_xor_sync(0xffffffffu, s, o);
    if (lane == 0) g_invn[warp] = 1.f / fmaxf(sqrtf(s), 1e-8f);
}

__device__ __forceinline__ float dot8(float4 f0, float4 f1, float4 a, float4 b) {
    return f0.x * a.x + f0.y * a.y + f0.z * a.z + f0.w * a.w +
           f1.x * b.x + f1.y * b.y + f1.z * b.z + f1.w * b.w;
}

__global__ void k_ocount(const int* __restrict__ ei) {
    int i = blockIdx.x * blockDim.x + threadIdx.x;
    if (i < N_EDGES) atomicAdd(&g_odeg[ei[N_EDGES + i]], 1);
}

__global__ void k_ofill(const int* __restrict__ ei) {
    int i = blockIdx.x * blockDim.x + threadIdx.x;
    if (i >= N_EDGES) return;
    int d = ei[N_EDGES + i];
    int pos = g_orow[d] + atomicAdd(&g_ocur[d], 1);
    g_oedge[pos] = i;
}

__global__ void k_edge_sim2(const int* __restrict__ ei) {
    int d = (blockIdx.x * blockDim.x + threadIdx.x) >> 5;
    if (d >= N_NODES) return;
    int lane = threadIdx.x & 31;
    int len = g_odeg[d];
    if (len == 0) return;
    int start = g_orow[d];
    const float4* t0 = (const float4*)(g_AF + ((size_t)1 * N_NODES + d) * 256);
    const float4* t1 = (const float4*)(g_AF + ((size_t)2 * N_NODES + d) * 256);
    const float4* t2 = (const float4*)(g_AF + ((size_t)3 * N_NODES + d) * 256);
    const float4* t3 = (const float4*)(g_AF + ((size_t)4 * N_NODES + d) * 256);
    float4 a0 = t0[lane * 2], b0 = t0[lane * 2 + 1];
    float4 a1 = t1[lane * 2], b1 = t1[lane * 2 + 1];
    float4 a2 = t2[lane * 2], b2 = t2[lane * 2 + 1];
    float4 a3 = t3[lane * 2], b3 = t3[lane * 2 + 1];
    float i0 = g_invn[d];
    float i1 = g_invn[N_NODES + d];
    float i2 = g_invn[2 * N_NODES + d];
    float i3 = g_invn[3 * N_NODES + d];
    int j = 0;
    for (; j + 2 <= len; j += 2) {
        int e0 = g_oedge[start + j], e1 = g_oedge[start + j + 1];
        int s0 = __ldg(ei + e0), s1 = __ldg(ei + e1);
        const float4* fr0 = (const float4*)(g_AF + (size_t)s0 * 256);
        const float4* fr1 = (const float4*)(g_AF + (size_t)s1 * 256);
        float4 fA = __ldg(fr0 + lane * 2), fB = __ldg(fr0 + lane * 2 + 1);
        float4 gA = __ldg(fr1 + lane * 2), gB = __ldg(fr1 + lane * 2 + 1);
        float p0 = dot8(fA, fB, a0, b0), q0 = dot8(gA, gB, a0, b0);
        float p1 = dot8(fA, fB, a1, b1), q1 = dot8(gA, gB, a1, b1);
        float p2 = dot8(fA, fB, a2, b2), q2 = dot8(gA, gB, a2, b2);
        float p3 = dot8(fA, fB, a3, b3), q3 = dot8(gA, gB, a3, b3);
#pragma unroll
        for (int o = 16; o; o >>= 1) {
            p0 += __shfl_xor_sync(0xffffffffu, p0, o);
            p1 += __shfl_xor_sync(0xffffffffu, p1, o);
            p2 += __shfl_xor_sync(0xffffffffu, p2, o);
            p3 += __shfl_xor_sync(0xffffffffu, p3, o);
            q0 += __shfl_xor_sync(0xffffffffu, q0, o);
            q1 += __shfl_xor_sync(0xffffffffu, q1, o);
            q2 += __shfl_xor_sync(0xffffffffu, q2, o);
            q3 += __shfl_xor_sync(0xffffffffu, q3, o);
        }
        if (lane == 0) {
            float s0v = p0 * i0, s1v = p1 * i1, s2v = p2 * i2, s3v = p3 * i3;
            float bv = s0v; int bi = 0;
            if (s1v > bv) { bv = s1v; bi = 1; }
            if (s2v > bv) { bv = s2v; bi = 2; }
            if (s3v > bv) { bv = s3v; bi = 3; }
            g_best[e0] = bi;
            float u0v = q0 * i0, u1v = q1 * i1, u2v = q2 * i2, u3v = q3 * i3;
            float cv = u0v; int ci = 0;
            if (u1v > cv) { cv = u1v; ci = 1; }
            if (u2v > cv) { cv = u2v; ci = 2; }
            if (u3v > cv) { cv = u3v; ci = 3; }
            g_best[e1] = ci;
        }
    }
    if (j < len) {
        int e = g_oedge[start + j];
        int s = __ldg(ei + e);
        const float4* fr = (const float4*)(g_AF + (size_t)s * 256);
        float4 f0 = __ldg(fr + lane * 2), f1 = __ldg(fr + lane * 2 + 1);
        float p0 = dot8(f0, f1, a0, b0);
        float p1 = dot8(f0, f1, a1, b1);
        float p2 = dot8(f0, f1, a2, b2);
        float p3 = dot8(f0, f1, a3, b3);
#pragma unroll
        for (int o = 16; o; o >>= 1) {
            p0 += __shfl_xor_sync(0xffffffffu, p0, o);
            p1 += __shfl_xor_sync(0xffffffffu, p1, o);
            p2 += __shfl_xor_sync(0xffffffffu, p2, o);
            p3 += __shfl_xor_sync(0xffffffffu, p3, o);
        }
        if (lane == 0) {
            float s0v = p0 * i0, s1v = p1 * i1, s2v = p2 * i2, s3v = p3 * i3;
            float bv = s0v; int bi = 0;
            if (s1v > bv) { bv = s1v; bi = 1; }
            if (s2v > bv) { bv = s2v; bi = 2; }
            if (s3v > bv) { bv = s3v; bi = 3; }
            g_best[e] = bi;
        }
    }
}

__device__ __forceinline__ void decode_edge(const int* __restrict__ ei, int i, int& s, int& d) {
    if (i < N_EDGES) {
        s = ei[i]; d = ei[N_EDGES + i];
    } else if (i < 2 * N_EDGES) {
        int e = i - N_EDGES;
        s = ei[e]; d = ei[N_EDGES + e] + g_best[e] * N_NODES;
    } else {
        int r = i - 2 * N_EDGES;
        int rep = r / N_NODES + 1;
        int n = r - (rep - 1) * N_NODES;
        s = n; d = n + rep * N_NODES;
    }
}

__global__ void k_count(const int* __restrict__ ei) {
    int i = blockIdx.x * blockDim.x + threadIdx.x;
    if (i >= NE_TOT) return;
    int s, d;
    decode_edge(ei, i, s, d);
    if (s != d) atomicAdd(&g_deg[d], 1);
}

__global__ void k_dinv() {
    int i = blockIdx.x * blockDim.x + threadIdx.x;
    if (i < N_TOT) g_dinv[i] = rsqrtf((float)(g_deg[i] + 1));
}

__global__ void k_scan1(const int* __restrict__ in, int* __restrict__ out, int n, int minus) {
    __shared__ int sm[256];
    int tid = threadIdx.x;
    int base = blockIdx.x * SCAN_BLK;
    int loc[4]; int sum = 0;
#pragma unroll
    for (int u = 0; u < 4; u++) {
        int i = base + tid * 4 + u;
        int v = (i < n) ? (in[i] - minus) : 0;
        loc[u] = sum; sum += v;
    }
    sm[tid] = sum;
    __syncthreads();
    for (int o = 1; o < 256; o <<= 1) {
        int t = (tid >= o) ? sm[tid - o] : 0;
        __syncthreads();
        sm[tid] += t;
        __syncthreads();
    }
    int pre = tid ? sm[tid - 1] : 0;
#pragma unroll
    for (int u = 0; u < 4; u++) {
        int i = base + tid * 4 + u;
        if (i < n) out[i] = pre + loc[u];
    }
    if (tid == 255) g_blocksum[blockIdx.x] = sm[255];
}

__global__ void k_scan2(int nb) {
    __shared__ int sm[256];
    int tid = threadIdx.x;
    sm[tid] = (tid < nb) ? g_blocksum[tid] : 0;
    __syncthreads();
    for (int o = 1; o < 256; o <<= 1) {
        int t = (tid >= o) ? sm[tid - o] : 0;
        __syncthreads();
        sm[tid] += t;
        __syncthreads();
    }
    if (tid < nb) g_blocksum[tid] = tid ? sm[tid - 1] : 0;
}

__global__ void k_scan3(int* __restrict__ out, int n) {
    int i = blockIdx.x * blockDim.x + threadIdx.x;
    if (i < n) out[i] += g_blocksum[i >> 10];
}

__global__ void k_fill(const int* __restrict__ ei) {
    int i = blockIdx.x * blockDim.x + threadIdx.x;
    if (i >= NE_TOT) return;
    int s, d;
    decode_edge(ei, i, s, d);
    if (s == d) return;
    int pos = g_rowptr[d] + atomicAdd(&g_cursor[d], 1);
    g_csr_src[pos] = s;
    g_csr_w[pos] = g_dinv[s] * g_dinv[d];
}

// OUT: 0 = skip fp32 store; 1 = store rows < N_NODES only; 2 = store all
template<int WS, int OUT>
__global__ void k_aggregate(const float* __restrict__ X, const float* __restrict__ bias,
                            float* __restrict__ Out) {
    int w = (blockIdx.x * blockDim.x + threadIdx.x) >> 5;
    if (w >= N_TOT) return;
    int lane = threadIdx.x & 31;
    int start = g_rowptr[w];
    int len = g_deg[w];
    float dv = g_dinv[w];
    float ws = dv * dv;
    const float4* xd = (const float4*)(X + (size_t)w * 256);
    float4 sa = xd[lane * 2], sb = xd[lane * 2 + 1];
    float acc0 = ws * sa.x, acc1 = ws * sa.y, acc2 = ws * sa.z, acc3 = ws * sa.w;
    float acc4 = ws * sb.x, acc5 = ws * sb.y, acc6 = ws * sb.z, acc7 = ws * sb.w;
    int j = 0;
    for (; j + 4 <= len; j += 4) {
        int s0 = g_csr_src[start + j];
        int s1 = g_csr_src[start + j + 1];
        int s2 = g_csr_src[start + j + 2];
        int s3 = g_csr_src[start + j + 3];
        float w0 = g_csr_w[start + j];
        float w1 = g_csr_w[start + j + 1];
        float w2 = g_csr_w[start + j + 2];
        float w3 = g_csr_w[start + j + 3];
        const float4* x0 = (const float4*)(X + (size_t)s0 * 256);
        const float4* x1 = (const float4*)(X + (size_t)s1 * 256);
        const float4* x2 = (const float4*)(X + (size_t)s2 * 256);
        const float4* x3 = (const float4*)(X + (size_t)s3 * 256);
        float4 u0 = x0[lane * 2], v0 = x0[lane * 2 + 1];
        float4 u1 = x1[lane * 2], v1 = x1[lane * 2 + 1];
        float4 u2 = x2[lane * 2], v2 = x2[lane * 2 + 1];
        float4 u3 = x3[lane * 2], v3 = x3[lane * 2 + 1];
        acc0 = fmaf(w0, u0.x, acc0); acc1 = fmaf(w0, u0.y, acc1);
        acc2 = fmaf(w0, u0.z, acc2); acc3 = fmaf(w0, u0.w, acc3);
        acc4 = fmaf(w0, v0.x, acc4); acc5 = fmaf(w0, v0.y, acc5);
        acc6 = fmaf(w0, v0.z, acc6); acc7 = fmaf(w0, v0.w, acc7);
        acc0 = fmaf(w1, u1.x, acc0); acc1 = fmaf(w1, u1.y, acc1);
        acc2 = fmaf(w1, u1.z, acc2); acc3 = fmaf(w1, u1.w, acc3);
        acc4 = fmaf(w1, v1.x, acc4); acc5 = fmaf(w1, v1.y, acc5);
        acc6 = fmaf(w1, v1.z, acc6); acc7 = fmaf(w1, v1.w, acc7);
        acc0 = fmaf(w2, u2.x, acc0); acc1 = fmaf(w2, u2.y, acc1);
        acc2 = fmaf(w2, u2.z, acc2); acc3 = fmaf(w2, u2.w, acc3);
        acc4 = fmaf(w2, v2.x, acc4); acc5 = fmaf(w2, v2.y, acc5);
        acc6 = fmaf(w2, v2.z, acc6); acc7 = fmaf(w2, v2.w, acc7);
        acc0 = fmaf(w3, u3.x, acc0); acc1 = fmaf(w3, u3.y, acc1);
        acc2 = fmaf(w3, u3.z, acc2); acc3 = fmaf(w3, u3.w, acc3);
        acc4 = fmaf(w3, v3.x, acc4); acc5 = fmaf(w3, v3.y, acc5);
        acc6 = fmaf(w3, v3.z, acc6); acc7 = fmaf(w3, v3.w, acc7);
    }
    for (; j < len; j++) {
        int s0 = g_csr_src[start + j];
        float w0 = g_csr_w[start + j];
        const float4* x0 = (const float4*)(X + (size_t)s0 * 256);
        float4 u0 = x0[lane * 2], v0 = x0[lane * 2 + 1];
        acc0 = fmaf(w0, u0.x, acc0); acc1 = fmaf(w0, u0.y, acc1);
        acc2 = fmaf(w0, u0.z, acc2); acc3 = fmaf(w0, u0.w, acc3);
        acc4 = fmaf(w0, v0.x, acc4); acc5 = fmaf(w0, v0.y, acc5);
        acc6 = fmaf(w0, v0.z, acc6); acc7 = fmaf(w0, v0.w, acc7);
    }
    const float4* b4 = (const float4*)bias;
    float4 bb0 = b4[lane * 2], bb1 = b4[lane * 2 + 1];
    float o[8] = {acc0 + bb0.x, acc1 + bb0.y, acc2 + bb0.z, acc3 + bb0.w,
                  acc4 + bb1.x, acc5 + bb1.y, acc6 + bb1.z, acc7 + bb1.w};
    if (OUT == 2 || (OUT == 1 && w < N_NODES)) {
        float4* od = (float4*)(Out + (size_t)w * 256);
        od[lane * 2] = make_float4(o[0], o[1], o[2], o[3]);
        od[lane * 2 + 1] = make_float4(o[4], o[5], o[6], o[7]);
    }
    if (WS) {
        uint32_t hw[4], lw[4];
#pragma unroll
        for (int q = 0; q < 4; q++) {
            __half h0, l0, h1, l1;
            split2(fmaxf(o[q * 2], 0.f), h0, l0);
            split2(fmaxf(o[q * 2 + 1], 0.f), h1, l1);
            hw[q] = hpack2(h0, h1); lw[q] = hpack2(l0, l1);
        }
        size_t so = (size_t)w * 256 + lane * 8;
        *(uint4*)(g_Ahi + so) = make_uint4(hw[0], hw[1], hw[2], hw[3]);
        *(uint4*)(g_Alo + so) = make_uint4(lw[0], lw[1], lw[2], lw[3]);
    }
}

__global__ void k_H(float* __restrict__ Hout) {
    int n = blockIdx.x * blockDim.x + threadIdx.x;
    if (n >= N_NODES) return;
    int c0 = g_cls[n];
    int c1 = g_cls[N_NODES + n];
    int c2 = g_cls[2 * N_NODES + n];
    int c3 = g_cls[3 * N_NODES + n];
    int c4 = g_cls[4 * N_NODES + n];
    float* o = Hout + (size_t)n * 64;
#pragma unroll
    for (int j = 0; j < 64; j++)
        o[j] = (float)((c0 == j) + (c1 == j) + (c2 == j) + (c3 == j) + (c4 == j));
}

__global__ void k_hyperedge(const float* __restrict__ Hout, float* __restrict__ hf) {
    extern __shared__ float acc[];
    int tid = threadIdx.x;
    for (int i = tid; i < 16384; i += 256) acc[i] = 0.f;
    __syncthreads();
    int warp = tid >> 5, lane = tid & 31;
    for (int n = blockIdx.x * 8 + warp; n < N_NODES; n += gridDim.x * 8) {
        float h0 = Hout[(size_t)n * 64 + lane];
        float h1 = Hout[(size_t)n * 64 + lane + 32];
        unsigned m0 = __ballot_sync(0xffffffffu, h0 > 0.f);
        unsigned m1 = __ballot_sync(0xffffffffu, h1 > 0.f);
        const float4* xr = (const float4*)(g_B + (size_t)n * 256);
        float4 a = xr[lane * 2], b = xr[lane * 2 + 1];
        unsigned mm = m0;
        while (mm) {
            int c = __ffs(mm) - 1; mm &= mm - 1;
            float* p = acc + c * 256 + lane * 8;
            atomicAdd(p + 0, a.x); atomicAdd(p + 1, a.y); atomicAdd(p + 2, a.z); atomicAdd(p + 3, a.w);
            atomicAdd(p + 4, b.x); atomicAdd(p + 5, b.y); atomicAdd(p + 6, b.z); atomicAdd(p + 7, b.w);
        }
        mm = m1;
        while (mm) {
            int c = (__ffs(mm) - 1) + 32; mm &= mm - 1;
            float* p = acc + c * 256 + lane * 8;
            atomicAdd(p + 0, a.x); atomicAdd(p + 1, a.y); atomicAdd(p + 2, a.z); atomicAdd(p + 3, a.w);
            atomicAdd(p + 4, b.x); atomicAdd(p + 5, b.y); atomicAdd(p + 6, b.z); atomicAdd(p + 7, b.w);
        }
    }
    __syncthreads();
    for (int i = tid; i < 16384; i += 256) atomicAdd(&hf[i], acc[i]);
}

// ---------------- launch ----------------
extern "C" void kernel_launch(void* const* d_in, const int* in_sizes, int n_in,
                              void* d_out, int out_size) {
    const int*   ei       = (const int*)d_in[0];
    const float* features = (const float*)d_in[1];
    const float* lin_w    = (const float*)d_in[2];
    const float* lin_b    = (const float*)d_in[3];
    const float* gcn0_w   = (const float*)d_in[4];
    const float* gcn0_b   = (const float*)d_in[5];
    const float* gcn1_w   = (const float*)d_in[6];
    const float* gcn1_b   = (const float*)d_in[7];
    const float* lin1_w   = (const float*)d_in[8];
    const float* lin1_b   = (const float*)d_in[9];

    float* out      = (float*)d_out;
    float* H_out    = out;
    float* hf_out   = out + (size_t)N_NODES * NS;
    float* dots_out = hf_out + NS * D;

    float *AF, *X, *B, *ZB;
    int *CUR, *DEG, *ROWPTR, *ODEG, *OROW, *OCUR;
    __half *AH, *AL, *AH2, *AL2, *WH, *WL;
    cudaGetSymbolAddress((void**)&AF, g_AF);
    cudaGetSymbolAddress((void**)&X,  g_X);
    cudaGetSymbolAddress((void**)&B,  g_B);
    cudaGetSymbolAddress((void**)&ZB, g_zerobias);
    cudaGetSymbolAddress((void**)&CUR, g_cursor);
    cudaGetSymbolAddress((void**)&DEG, g_deg);
    cudaGetSymbolAddress((void**)&ROWPTR, g_rowptr);
    cudaGetSymbolAddress((void**)&ODEG, g_odeg);
    cudaGetSymbolAddress((void**)&OROW, g_orow);
    cudaGetSymbolAddress((void**)&OCUR, g_ocur);
    cudaGetSymbolAddress((void**)&AH, g_Ahi);
    cudaGetSymbolAddress((void**)&AL, g_Alo);
    cudaGetSymbolAddress((void**)&AH2, g_Ahi2);
    cudaGetSymbolAddress((void**)&AL2, g_Alo2);
    cudaGetSymbolAddress((void**)&WH, g_Whi);
    cudaGetSymbolAddress((void**)&WL, g_Wlo);

    cudaFuncSetAttribute(k_hyperedge,  cudaFuncAttributeMaxDynamicSharedMemorySize, 65536);
    cudaFuncSetAttribute(k_mmagemm<0>, cudaFuncAttributeMaxDynamicSharedMemorySize, SMG_BYTES);
    cudaFuncSetAttribute(k_mmagemm<1>, cudaFuncAttributeMaxDynamicSharedMemorySize, SMG_BYTES);
    cudaFuncSetAttribute(k_mmagemm64<0>, cudaFuncAttributeMaxDynamicSharedMemorySize, SM64_BYTES);
    cudaFuncSetAttribute(k_mmagemm64<1>, cudaFuncAttributeMaxDynamicSharedMemorySize, SM64_BYTES);

    const int nb_tot  = (N_TOT + SCAN_BLK - 1) / SCAN_BLK;
    const int nb_node = (N_NODES + SCAN_BLK - 1) / SCAN_BLK;

    // weight splits + single feature split (relu->buf1, raw->buf2, copy->AF)
    k_wsplit<<<dim3(256, 4), 256>>>(lin_w, 0, 256, 65536);
    k_split_both<<<(N_NODES * 64 + 255) / 256, 256>>>((const float4*)features, N_NODES * 64);

    // heads GEMM: A = RAW feature splits (buf2 rows 0..N);
    // epilogue: split(relu)->buf1, split(raw)->buf2, rows N..5N
    k_mmagemm<1><<<dim3(2, (N_NODES + 127) / 128, 4), 256, SMG_BYTES>>>(
        AH2, AL2, WH, WL, lin_b, AF + (size_t)N_NODES * 256,
        N_NODES, 65536, N_NODES * 256, 256, N_NODES, N_NODES);

    k_wsplit<<<dim3(256, 1), 256>>>(gcn0_w, 4, 256, 0);
    k_wsplit<<<dim3(256, 1), 256>>>(gcn1_w, 5, 256, 0);
    k_wsplit<<<dim3(64, 1), 256>>>(lin1_w, 6, 64, 0);

    // original-edge CSR
    cudaMemsetAsync(ODEG, 0, N_NODES * sizeof(int));
    cudaMemsetAsync(OCUR, 0, N_NODES * sizeof(int));
    k_ocount<<<(N_EDGES + 255) / 256, 256>>>(ei);
    k_scan1<<<nb_node, 256>>>(ODEG, OROW, N_NODES, 0);
    k_scan2<<<1, 256>>>(nb_node);
    k_scan3<<<(N_NODES + 255) / 256, 256>>>(OROW, N_NODES);
    k_ofill<<<(N_EDGES + 255) / 256, 256>>>(ei);

    // per-edge best replica
    k_invnorm<<<(T_REP * N_NODES * 32 + 255) / 256, 256>>>();
    k_edge_sim2<<<(N_NODES * 32 + 255) / 256, 256>>>(ei);

    // augmented-graph CSR (deg = in-edge count, self loop folded into dinv)
    cudaMemsetAsync(DEG, 0, N_TOT * sizeof(int));
    k_count<<<(NE_TOT + 255) / 256, 256>>>(ei);
    k_dinv<<<(N_TOT + 255) / 256, 256>>>();
    k_scan1<<<nb_tot, 256>>>(DEG, ROWPTR, N_TOT, 0);
    k_scan2<<<1, 256>>>(nb_tot);
    k_scan3<<<(N_TOT + 255) / 256, 256>>>(ROWPTR, N_TOT);
    cudaMemsetAsync(CUR, 0, N_TOT * sizeof(int));
    k_fill<<<(NE_TOT + 255) / 256, 256>>>(ei);

    // GCN layer 0 (aggregate fp32 output is dead -> OUT=0)
    k_mmagemm<0><<<dim3(2, (N_TOT + 127) / 128, 1), 256, SMG_BYTES>>>(
        AH, AL, WH + 4 * 65536, WL + 4 * 65536, ZB, X, N_TOT, 0, 0, 0, 0, 0);
    k_aggregate<1, 0><<<(N_TOT * 32 + 255) / 256, 256>>>(X, gcn0_b, B);

    // GCN layer 1 (fp32 output needed only for base rows -> OUT=1)
    k_mmagemm<0><<<dim3(2, (N_TOT + 127) / 128, 1), 256, SMG_BYTES>>>(
        AH, AL, WH + 5 * 65536, WL + 5 * 65536, ZB, X, N_TOT, 0, 0, 0, 0, 0);
    k_aggregate<1, 1><<<(N_TOT * 32 + 255) / 256, 256>>>(X, gcn1_b, B);

    // logits mma with fused argmax -> g_cls; then H
    k_mmagemm64<0><<<(N_TOT + 127) / 128, 256, SM64_BYTES>>>(
        AH, AL, WH + 6 * 65536, WL + 6 * 65536, lin1_b, X, N_TOT, 0.f);
    k_H<<<(N_NODES + 255) / 256, 256>>>(H_out);

    // hyperedge features, split hf into slot 7
    cudaMemsetAsync(hf_out, 0, (size_t)NS * D * sizeof(float));
    k_hyperedge<<<160, 256, 65536>>>(H_out, hf_out);
    k_wsplit_dir<<<64, 256>>>(hf_out, 7, NS * D);

    // dots via mma on raw-AF splits (buf2)
    k_mmagemm64<1><<<(N_TOT + 127) / 128, 256, SM64_BYTES>>>(
        AH2, AL2, WH + 7 * 65536, WL + 7 * 65536, ZB, dots_out, N_TOT, 0.0625f);
}

// round 15
// speedup vs baseline: 1.0810x; 1.0323x over previous
#include <cuda_runtime.h>
#include <cuda_fp16.h>
#include <cstdint>

#define N_NODES 50000
#define N_EDGES 800000
#define D 256
#define T_REP 4
#define NS 64
#define N_TOT (5 * N_NODES)                 /* 250000 */
#define NE_TOT (2 * N_EDGES + 3 * N_NODES)  /* 1750000 */
#define SCAN_BLK 1024
#define NPAD 250112

typedef unsigned long long u64;

__device__ __forceinline__ uint32_t smem_to_u32(const void* p) {
    uint32_t a;
    asm("{ .reg .u64 t; cvta.to.shared.u64 t, %1; cvt.u32.u64 %0, t; }" : "=r"(a) : "l"(p));
    return a;
}

#define LDMATRIX_X4(r0, r1, r2, r3, addr) \
    asm volatile("ldmatrix.sync.aligned.m8n8.x4.shared.b16 {%0,%1,%2,%3}, [%4];" \
                 : "=r"(r0), "=r"(r1), "=r"(r2), "=r"(r3) : "r"(addr))

#define MMAF16(c, a, b0, b1) \
    asm volatile("mma.sync.aligned.m16n8k16.row.col.f32.f16.f16.f32 " \
                 "{%0,%1,%2,%3}, {%4,%5,%6,%7}, {%8,%9}, {%0,%1,%2,%3};" \
                 : "+f"((c)[0]), "+f"((c)[1]), "+f"((c)[2]), "+f"((c)[3]) \
                 : "r"((a)[0]), "r"((a)[1]), "r"((a)[2]), "r"((a)[3]), "r"(b0), "r"(b1))

#define CP16(dst, src, sz) \
    asm volatile("cp.async.cg.shared.global [%0], [%1], 16, %2;" \
                 :: "r"(dst), "l"(src), "r"(sz))
#define CP_COMMIT() asm volatile("cp.async.commit_group;" ::: "memory")
#define CP_WAIT0()  asm volatile("cp.async.wait_group 0;" ::: "memory")

__device__ __forceinline__ void split2(float x, __half& h, __half& l) {
    h = __float2half_rn(x);
    l = __float2half_rn(x - __half2float(h));
}
__device__ __forceinline__ uint32_t hpack2(__half a, __half b) {
    return (uint32_t)__half_as_ushort(a) | ((uint32_t)__half_as_ushort(b) << 16);
}

// ---------------- scratch (device globals) ----------------
__device__ float g_X[(size_t)N_TOT * D];
__device__ float g_B[(size_t)N_TOT * D];
__device__ float g_invn[T_REP * N_NODES];   // sumsq accum -> 1/max(||.||,eps)
__device__ int   g_deg[N_TOT];              // in-edge count (no self loop)
__device__ float g_dinv[N_TOT];
__device__ int   g_best[N_EDGES];
__device__ int   g_cls[N_TOT];
__device__ float g_zerobias[D];
__device__ int   g_rowptr[N_TOT];
__device__ int   g_blocksum[256];
__device__ int   g_cursor[N_TOT];
__device__ int   g_csr_src[NE_TOT];
__device__ float g_csr_w[NE_TOT];
__device__ int   g_odeg[N_NODES];
__device__ int   g_orow[N_NODES];
__device__ int   g_ocur[N_NODES];
__device__ int   g_oedge[N_EDGES];
// fp16 split buffers: buf1 = GEMM activations (relu), buf2 = raw values
__device__ __half g_Ahi[(size_t)NPAD * D];
__device__ __half g_Alo[(size_t)NPAD * D];
__device__ __half g_Ahi2[(size_t)NPAD * D];
__device__ __half g_Alo2[(size_t)NPAD * D];
__device__ __half g_Whi[8 * 65536];
__device__ __half g_Wlo[8 * 65536];

// reconstruct 8 floats (lane's 16B slice) from hi/lo split row
__device__ __forceinline__ void rec8(const __half* hi, const __half* lo, int lane,
                                     float4& a, float4& b) {
    uint4 h = __ldg((const uint4*)hi + lane);
    uint4 l = __ldg((const uint4*)lo + lane);
    float2 f0 = __half22float2(*(__half2*)&h.x), g0 = __half22float2(*(__half2*)&l.x);
    float2 f1 = __half22float2(*(__half2*)&h.y), g1 = __half22float2(*(__half2*)&l.y);
    float2 f2 = __half22float2(*(__half2*)&h.z), g2 = __half22float2(*(__half2*)&l.z);
    float2 f3 = __half22float2(*(__half2*)&h.w), g3 = __half22float2(*(__half2*)&l.w);
    a = make_float4(f0.x + g0.x, f0.y + g0.y, f1.x + g1.x, f1.y + g1.y);
    b = make_float4(f2.x + g2.x, f2.y + g2.y, f3.x + g3.x, f3.y + g3.y);
}

// ---------------- small kernels ----------------

// split relu(X) -> buf1, raw X -> buf2; also zero g_invn
__global__ void k_split_both(const float4* __restrict__ X, int n4) {
    int i = blockIdx.x * blockDim.x + threadIdx.x;
    if (i >= n4) return;
    if (i < T_REP * N_NODES) g_invn[i] = 0.f;
    float4 v = X[i];
    __half h0,l0,h1,l1,h2,l2,h3,l3;
    split2(v.x,h0,l0); split2(v.y,h1,l1); split2(v.z,h2,l2); split2(v.w,h3,l3);
    ((uint2*)g_Ahi2)[i] = make_uint2(hpack2(h0,h1), hpack2(h2,h3));
    ((uint2*)g_Alo2)[i] = make_uint2(hpack2(l0,l1), hpack2(l2,l3));
    float x0 = fmaxf(v.x, 0.f), x1 = fmaxf(v.y, 0.f);
    float x2 = fmaxf(v.z, 0.f), x3 = fmaxf(v.w, 0.f);
    split2(x0,h0,l0); split2(x1,h1,l1); split2(x2,h2,l2); split2(x3,h3,l3);
    ((uint2*)g_Ahi)[i] = make_uint2(hpack2(h0,h1), hpack2(h2,h3));
    ((uint2*)g_Alo)[i] = make_uint2(hpack2(l0,l1), hpack2(l2,l3));
}

__global__ void k_finish_invn() {
    int i = blockIdx.x * blockDim.x + threadIdx.x;
    if (i < T_REP * N_NODES) g_invn[i] = 1.f / fmaxf(sqrtf(g_invn[i]), 1e-8f);
}

// split + transpose a [256 x ncols] weight into slot widxBase + blockIdx.y
__global__ void k_wsplit(const float* __restrict__ W, int widxBase, int ncols, int wstride) {
    int widx = widxBase + blockIdx.y;
    const float* Wz = W + (size_t)blockIdx.y * wstride;
    int i = blockIdx.x * 256 + threadIdx.x;
    int n = i >> 8, k = i & 255;
    float x = Wz[k * ncols + n];
    __half h, l;
    split2(x, h, l);
    g_Whi[widx * 65536 + i] = h;
    g_Wlo[widx * 65536 + i] = l;
}

__global__ void k_wsplit_dir(const float* __restrict__ src, int widx, int nelem) {
    int i = blockIdx.x * 256 + threadIdx.x;
    if (i >= nelem) return;
    __half h, l;
    split2(src[i], h, l);
    g_Whi[widx * 65536 + i] = h;
    g_Wlo[widx * 65536 + i] = l;
}

// ---- fp16x3 GEMM (N=256) ----
// WS=0: C = A@W + bias (store fp32 C only)
// WS=1 (heads): NO C store; write split(relu)->buf1, split(raw)->buf2 at
//               rows N_NODES + z*N_NODES + gr; atomic sumsq -> g_invn.
#define ASTRIDE 72
#define SMBUF (128 * ASTRIDE)
#define SMG_BYTES (4 * SMBUF * 2)
template<int WS>
__global__ __launch_bounds__(256, 2) void k_mmagemm(
    const __half* Ahi, const __half* Alo,
    const __half* __restrict__ Whi, const __half* __restrict__ Wlo,
    const float* __restrict__ bias, float* __restrict__ C,
    int M, int wz, int cz, int bzs)
{
    extern __shared__ __half smh[];
    __half* sAh = smh;
    __half* sAl = smh + SMBUF;
    __half* sBh = smh + 2 * SMBUF;
    __half* sBl = smh + 3 * SMBUF;

    const int tid = threadIdx.x;
    const int warp = tid >> 5, lane = tid & 31;
    const int wm = warp & 1, wn = warp >> 1;
    const int z = blockIdx.z;
    const int rBase = blockIdx.y << 7;
    const int colBase = blockIdx.x << 7;

    const __half* Wh = Whi + (size_t)z * wz;
    const __half* Wl = Wlo + (size_t)z * wz;

    float acc[4][4][4];
#pragma unroll
    for (int i = 0; i < 4; i++)
#pragma unroll
        for (int j = 0; j < 4; j++)
#pragma unroll
            for (int q = 0; q < 4; q++) acc[i][j][q] = 0.f;

    const uint32_t uAh = smem_to_u32(sAh);
    const uint32_t uAl = smem_to_u32(sAl);
    const uint32_t uBh = smem_to_u32(sBh);
    const uint32_t uBl = smem_to_u32(sBl);
    const int a_row_l = lane & 15;
    const int a_kh = (lane >> 4) << 3;
    const int b_n_off = (lane & 7) + ((lane >> 4) << 3);
    const int b_k_off = ((lane >> 3) & 1) << 3;

#pragma unroll 1
    for (int c = 0; c < 4; c++) {
#pragma unroll
        for (int s = 0; s < 2; s++) {
            const __half* ap = s ? Alo : Ahi;
            uint32_t ud = s ? uAl : uAh;
#pragma unroll
            for (int j = 0; j < 4; j++) {
                int i = tid + j * 256;
                int row = i >> 3, seg = i & 7;
                int gr = rBase + row;
                int grc = gr < M ? gr : 0;
                unsigned sz = gr < M ? 16u : 0u;
                CP16(ud + (uint32_t)(row * ASTRIDE + seg * 8) * 2,
                     ap + (size_t)grc * 256 + c * 64 + seg * 8, sz);
            }
            const __half* wp = s ? Wl : Wh;
            uint32_t wd = s ? uBl : uBh;
#pragma unroll
            for (int j = 0; j < 4; j++) {
                int i = tid + j * 256;
                int row = i >> 3, seg = i & 7;
                CP16(wd + (uint32_t)(row * ASTRIDE + seg * 8) * 2,
                     wp + (size_t)(colBase + row) * 256 + c * 64 + seg * 8, 16u);
            }
        }
        CP_COMMIT();
        CP_WAIT0();
        __syncthreads();
#pragma unroll
        for (int k = 0; k < 4; k++) {
            const int k0 = k << 4;
            const uint32_t aoff = (uint32_t)(((wm << 6) + a_row_l) * ASTRIDE + k0 + a_kh) * 2;
            const uint32_t boff0 = (uint32_t)(((wn << 5) + b_n_off) * ASTRIDE + k0 + b_k_off) * 2;
            const uint32_t boff1 = boff0 + (uint32_t)(16 * ASTRIDE) * 2;
            uint32_t ah[4][4], al[4][4], bh[2][4], bl[2][4];
#pragma unroll
            for (int mi = 0; mi < 4; mi++) {
                LDMATRIX_X4(ah[mi][0], ah[mi][1], ah[mi][2], ah[mi][3],
                            uAh + aoff + (uint32_t)((mi << 4) * ASTRIDE) * 2);
                LDMATRIX_X4(al[mi][0], al[mi][1], al[mi][2], al[mi][3],
                            uAl + aoff + (uint32_t)((mi << 4) * ASTRIDE) * 2);
            }
            LDMATRIX_X4(bh[0][0], bh[0][1], bh[0][2], bh[0][3], uBh + boff0);
            LDMATRIX_X4(bh[1][0], bh[1][1], bh[1][2], bh[1][3], uBh + boff1);
            LDMATRIX_X4(bl[0][0], bl[0][1], bl[0][2], bl[0][3], uBl + boff0);
            LDMATRIX_X4(bl[1][0], bl[1][1], bl[1][2], bl[1][3], uBl + boff1);
#pragma unroll
            for (int mi = 0; mi < 4; mi++)
#pragma unroll
                for (int ni = 0; ni < 4; ni++) {
                    uint32_t b0h = bh[ni >> 1][(ni & 1) * 2], b1h = bh[ni >> 1][(ni & 1) * 2 + 1];
                    uint32_t b0l = bl[ni >> 1][(ni & 1) * 2], b1l = bl[ni >> 1][(ni & 1) * 2 + 1];
                    MMAF16(acc[mi][ni], ah[mi], b0h, b1h);
                    MMAF16(acc[mi][ni], ah[mi], b0l, b1l);
                    MMAF16(acc[mi][ni], al[mi], b0h, b1h);
                }
        }
        __syncthreads();
    }

    const float* bp = bias + (size_t)z * bzs;
    float* Cz = C + (size_t)z * cz;
#pragma unroll
    for (int mi = 0; mi < 4; mi++) {
#pragma unroll
        for (int hf2 = 0; hf2 < 2; hf2++) {
            int gr = rBase + (wm << 6) + (mi << 4) + (lane >> 2) + hf2 * 8;
            if (WS == 0) {
                if (gr >= M) continue;
#pragma unroll
                for (int ni = 0; ni < 4; ni++) {
                    int col = colBase + (wn << 5) + (ni << 3) + (lane & 3) * 2;
                    float o0 = acc[mi][ni][hf2 * 2] + bp[col];
                    float o1 = acc[mi][ni][hf2 * 2 + 1] + bp[col + 1];
                    *(float2*)&Cz[(size_t)gr * 256 + col] = make_float2(o0, o1);
                }
            } else {
                float ss = 0.f;
                if (gr < M) {
#pragma unroll
                    for (int ni = 0; ni < 4; ni++) {
                        int col = colBase + (wn << 5) + (ni << 3) + (lane & 3) * 2;
                        float o0 = acc[mi][ni][hf2 * 2] + bp[col];
                        float o1 = acc[mi][ni][hf2 * 2 + 1] + bp[col + 1];
                        ss += o0 * o0 + o1 * o1;
                        size_t so = (size_t)(N_NODES + z * N_NODES + gr) * 256 + col;
                        __half h0, l0, h1, l1;
                        split2(fmaxf(o0, 0.f), h0, l0);
                        split2(fmaxf(o1, 0.f), h1, l1);
                        *(uint32_t*)(g_Ahi + so) = hpack2(h0, h1);
                        *(uint32_t*)(g_Alo + so) = hpack2(l0, l1);
                        split2(o0, h0, l0);
                        split2(o1, h1, l1);
                        *(uint32_t*)(g_Ahi2 + so) = hpack2(h0, h1);
                        *(uint32_t*)(g_Alo2 + so) = hpack2(l0, l1);
                    }
                }
                ss += __shfl_xor_sync(0xffffffffu, ss, 1);
                ss += __shfl_xor_sync(0xffffffffu, ss, 2);
                if ((lane & 3) == 0 && gr < M)
                    atomicAdd(&g_invn[z * N_NODES + gr], ss);
            }
        }
    }
}

// ---- fp16x3 GEMM (N=64): MODE 0 logits+fused argmax; MODE 1 *scale ----
#define SM64_A (128 * ASTRIDE)
#define SM64_B (64 * ASTRIDE)
#define SM64_BYTES ((2 * SM64_A + 2 * SM64_B) * 2)
template<int MODE>
__global__ __launch_bounds__(256, 2) void k_mmagemm64(
    const __half* Ahi, const __half* Alo,
    const __half* __restrict__ Wh, const __half* __restrict__ Wl,
    const float* __restrict__ bias, float* __restrict__ C, int M, float scale)
{
    extern __shared__ __half smh[];
    __half* sAh = smh;
    __half* sAl = smh + SM64_A;
    __half* sBh = smh + 2 * SM64_A;
    __half* sBl = smh + 2 * SM64_A + SM64_B;
    __shared__ float sval[128];
    __shared__ int   sidx[128];

    const int tid = threadIdx.x;
    const int warp = tid >> 5, lane = tid & 31;
    const int wm = warp >> 1, wn = warp & 1;
    const int rBase = blockIdx.x << 7;

    float acc[2][4][4];
#pragma unroll
    for (int i = 0; i < 2; i++)
#pragma unroll
        for (int j = 0; j < 4; j++)
#pragma unroll
            for (int q = 0; q < 4; q++) acc[i][j][q] = 0.f;

    const uint32_t uAh = smem_to_u32(sAh);
    const uint32_t uAl = smem_to_u32(sAl);
    const uint32_t uBh = smem_to_u32(sBh);
    const uint32_t uBl = smem_to_u32(sBl);
    const int a_row_l = lane & 15;
    const int a_kh = (lane >> 4) << 3;
    const int b_n_off = (lane & 7) + ((lane >> 4) << 3);
    const int b_k_off = ((lane >> 3) & 1) << 3;

#pragma unroll 1
    for (int c = 0; c < 4; c++) {
#pragma unroll
        for (int s = 0; s < 2; s++) {
            const __half* ap = s ? Alo : Ahi;
            uint32_t ud = s ? uAl : uAh;
#pragma unroll
            for (int j = 0; j < 4; j++) {
                int i = tid + j * 256;
                int row = i >> 3, seg = i & 7;
                int gr = rBase + row;
                int grc = gr < M ? gr : 0;
                unsigned sz = gr < M ? 16u : 0u;
                CP16(ud + (uint32_t)(row * ASTRIDE + seg * 8) * 2,
                     ap + (size_t)grc * 256 + c * 64 + seg * 8, sz);
            }
            const __half* wp = s ? Wl : Wh;
            uint32_t wd = s ? uBl : uBh;
#pragma unroll
            for (int j = 0; j < 2; j++) {
                int i = tid + j * 256;
                int row = i >> 3, seg = i & 7;
                CP16(wd + (uint32_t)(row * ASTRIDE + seg * 8) * 2,
                     wp + (size_t)row * 256 + c * 64 + seg * 8, 16u);
            }
        }
        CP_COMMIT();
        CP_WAIT0();
        __syncthreads();
#pragma unroll
        for (int k = 0; k < 4; k++) {
            const int k0 = k << 4;
            const uint32_t aoff = (uint32_t)(((wm << 5) + a_row_l) * ASTRIDE + k0 + a_kh) * 2;
            const uint32_t boff0 = (uint32_t)(((wn << 5) + b_n_off) * ASTRIDE + k0 + b_k_off) * 2;
            const uint32_t boff1 = boff0 + (uint32_t)(16 * ASTRIDE) * 2;
            uint32_t ah[2][4], al[2][4], bh[2][4], bl[2][4];
#pragma unroll
            for (int mi = 0; mi < 2; mi++) {
                LDMATRIX_X4(ah[mi][0], ah[mi][1], ah[mi][2], ah[mi][3],
                            uAh + aoff + (uint32_t)((mi << 4) * ASTRIDE) * 2);
                LDMATRIX_X4(al[mi][0], al[mi][1], al[mi][2], al[mi][3],
                            uAl + aoff + (uint32_t)((mi << 4) * ASTRIDE) * 2);
            }
            LDMATRIX_X4(bh[0][0], bh[0][1], bh[0][2], bh[0][3], uBh + boff0);
            LDMATRIX_X4(bh[1][0], bh[1][1], bh[1][2], bh[1][3], uBh + boff1);
            LDMATRIX_X4(bl[0][0], bl[0][1], bl[0][2], bl[0][3], uBl + boff0);
            LDMATRIX_X4(bl[1][0], bl[1][1], bl[1][2], bl[1][3], uBl + boff1);
#pragma unroll
            for (int mi = 0; mi < 2; mi++)
#pragma unroll
                for (int ni = 0; ni < 4; ni++) {
                    uint32_t b0h = bh[ni >> 1][(ni & 1) * 2], b1h = bh[ni >> 1][(ni & 1) * 2 + 1];
                    uint32_t b0l = bl[ni >> 1][(ni & 1) * 2], b1l = bl[ni >> 1][(ni & 1) * 2 + 1];
                    MMAF16(acc[mi][ni], ah[mi], b0h, b1h);
                    MMAF16(acc[mi][ni], ah[mi], b0l, b1l);
                    MMAF16(acc[mi][ni], al[mi], b0h, b1h);
                }
        }
        __syncthreads();
    }

    if (MODE == 1) {
#pragma unroll
        for (int mi = 0; mi < 2; mi++)
#pragma unroll
            for (int hf2 = 0; hf2 < 2; hf2++) {
                int gr = rBase + (wm << 5) + (mi << 4) + (lane >> 2) + hf2 * 8;
                if (gr >= M) continue;
#pragma unroll
                for (int ni = 0; ni < 4; ni++) {
                    int col = (wn << 5) + (ni << 3) + (lane & 3) * 2;
                    float o0 = acc[mi][ni][hf2 * 2] * scale;
                    float o1 = acc[mi][ni][hf2 * 2 + 1] * scale;
                    *(float2*)&C[(size_t)gr * 64 + col] = make_float2(o0, o1);
                }
            }
    } else {
        float rv[4]; int ridx[4];
#pragma unroll
        for (int mi = 0; mi < 2; mi++)
#pragma unroll
            for (int hf2 = 0; hf2 < 2; hf2++) {
                float v = -3.4e38f; int idx = 0;
#pragma unroll
                for (int ni = 0; ni < 4; ni++) {
                    int col = (wn << 5) + (ni << 3) + (lane & 3) * 2;
                    float o0 = acc[mi][ni][hf2 * 2] + bias[col];
                    float o1 = acc[mi][ni][hf2 * 2 + 1] + bias[col + 1];
                    if (o0 > v) { v = o0; idx = col; }
                    if (o1 > v) { v = o1; idx = col + 1; }
                }
#pragma unroll
                for (int o = 1; o <= 2; o <<= 1) {
                    float ov = __shfl_xor_sync(0xffffffffu, v, o);
                    int oi = __shfl_xor_sync(0xffffffffu, idx, o);
                    if (ov > v || (ov == v && oi < idx)) { v = ov; idx = oi; }
                }
                int lr = (wm << 5) + (mi << 4) + hf2 * 8 + (lane >> 2);
                if (wn == 0 && (lane & 3) == 0) { sval[lr] = v; sidx[lr] = idx; }
                rv[mi * 2 + hf2] = v; ridx[mi * 2 + hf2] = idx;
            }
        __syncthreads();
        if (wn == 1 && (lane & 3) == 0) {
#pragma unroll
            for (int mi = 0; mi < 2; mi++)
#pragma unroll
                for (int hf2 = 0; hf2 < 2; hf2++) {
                    int lr = (wm << 5) + (mi << 4) + hf2 * 8 + (lane >> 2);
                    int gr = rBase + lr;
                    if (gr >= M) continue;
                    float v0 = sval[lr]; int i0 = sidx[lr];
                    float v1 = rv[mi * 2 + hf2]; int i1 = ridx[mi * 2 + hf2];
                    g_cls[gr] = (v1 > v0) ? i1 : i0;
                }
        }
    }
}

__device__ __forceinline__ float dot8(float4 f0, float4 f1, float4 a, float4 b) {
    return f0.x * a.x + f0.y * a.y + f0.z * a.z + f0.w * a.w +
           f1.x * b.x + f1.y * b.y + f1.z * b.z + f1.w * b.w;
}

__global__ void k_ocount(const int* __restrict__ ei) {
    int i = blockIdx.x * blockDim.x + threadIdx.x;
    if (i < N_EDGES) atomicAdd(&g_odeg[ei[N_EDGES + i]], 1);
}

__global__ void k_ofill(const int* __restrict__ ei) {
    int i = blockIdx.x * blockDim.x + threadIdx.x;
    if (i >= N_EDGES) return;
    int d = ei[N_EDGES + i];
    int pos = g_orow[d] + atomicAdd(&g_ocur[d], 1);
    g_oedge[pos] = i;
}

// per-edge best replica; all rows reconstructed from buf2 splits
__global__ void k_edge_sim2(const int* __restrict__ ei) {
    int d = (blockIdx.x * blockDim.x + threadIdx.x) >> 5;
    if (d >= N_NODES) return;
    int lane = threadIdx.x & 31;
    int len = g_odeg[d];
    if (len == 0) return;
    int start = g_orow[d];
    float4 a0, b0, a1, b1, a2, b2, a3, b3;
    rec8(g_Ahi2 + ((size_t)1 * N_NODES + d) * 256, g_Alo2 + ((size_t)1 * N_NODES + d) * 256, lane, a0, b0);
    rec8(g_Ahi2 + ((size_t)2 * N_NODES + d) * 256, g_Alo2 + ((size_t)2 * N_NODES + d) * 256, lane, a1, b1);
    rec8(g_Ahi2 + ((size_t)3 * N_NODES + d) * 256, g_Alo2 + ((size_t)3 * N_NODES + d) * 256, lane, a2, b2);
    rec8(g_Ahi2 + ((size_t)4 * N_NODES + d) * 256, g_Alo2 + ((size_t)4 * N_NODES + d) * 256, lane, a3, b3);
    float i0 = g_invn[d];
    float i1 = g_invn[N_NODES + d];
    float i2 = g_invn[2 * N_NODES + d];
    float i3 = g_invn[3 * N_NODES + d];
    int j = 0;
    for (; j + 2 <= len; j += 2) {
        int e0 = g_oedge[start + j], e1 = g_oedge[start + j + 1];
        int s0 = __ldg(ei + e0), s1 = __ldg(ei + e1);
        float4 fA, fB, gA, gB;
        rec8(g_Ahi2 + (size_t)s0 * 256, g_Alo2 + (size_t)s0 * 256, lane, fA, fB);
        rec8(g_Ahi2 + (size_t)s1 * 256, g_Alo2 + (size_t)s1 * 256, lane, gA, gB);
        float p0 = dot8(fA, fB, a0, b0), q0 = dot8(gA, gB, a0, b0);
        float p1 = dot8(fA, fB, a1, b1), q1 = dot8(gA, gB, a1, b1);
        float p2 = dot8(fA, fB, a2, b2), q2 = dot8(gA, gB, a2, b2);
        float p3 = dot8(fA, fB, a3, b3), q3 = dot8(gA, gB, a3, b3);
#pragma unroll
        for (int o = 16; o; o >>= 1) {
            p0 += __shfl_xor_sync(0xffffffffu, p0, o);
            p1 += __shfl_xor_sync(0xffffffffu, p1, o);
            p2 += __shfl_xor_sync(0xffffffffu, p2, o);
            p3 += __shfl_xor_sync(0xffffffffu, p3, o);
            q0 += __shfl_xor_sync(0xffffffffu, q0, o);
            q1 += __shfl_xor_sync(0xffffffffu, q1, o);
            q2 += __shfl_xor_sync(0xffffffffu, q2, o);
            q3 += __shfl_xor_sync(0xffffffffu, q3, o);
        }
        if (lane == 0) {
            float s0v = p0 * i0, s1v = p1 * i1, s2v = p2 * i2, s3v = p3 * i3;
            float bv = s0v; int bi = 0;
            if (s1v > bv) { bv = s1v; bi = 1; }
            if (s2v > bv) { bv = s2v; bi = 2; }
            if (s3v > bv) { bv = s3v; bi = 3; }
            g_best[e0] = bi;
            float u0v = q0 * i0, u1v = q1 * i1, u2v = q2 * i2, u3v = q3 * i3;
            float cv = u0v; int ci = 0;
            if (u1v > cv) { cv = u1v; ci = 1; }
            if (u2v > cv) { cv = u2v; ci = 2; }
            if (u3v > cv) { cv = u3v; ci = 3; }
            g_best[e1] = ci;
        }
    }
    if (j < len) {
        int e = g_oedge[start + j];
        int s = __ldg(ei + e);
        float4 f0, f1;
        rec8(g_Ahi2 + (size_t)s * 256, g_Alo2 + (size_t)s * 256, lane, f0, f1);
        float p0 = dot8(f0, f1, a0, b0);
        float p1 = dot8(f0, f1, a1, b1);
        float p2 = dot8(f0, f1, a2, b2);
        float p3 = dot8(f0, f1, a3, b3);
#pragma unroll
        for (int o = 16; o; o >>= 1) {
            p0 += __shfl_xor_sync(0xffffffffu, p0, o);
            p1 += __shfl_xor_sync(0xffffffffu, p1, o);
            p2 += __shfl_xor_sync(0xffffffffu, p2, o);
            p3 += __shfl_xor_sync(0xffffffffu, p3, o);
        }
        if (lane == 0) {
            float s0v = p0 * i0, s1v = p1 * i1, s2v = p2 * i2, s3v = p3 * i3;
            float bv = s0v; int bi = 0;
            if (s1v > bv) { bv = s1v; bi = 1; }
            if (s2v > bv) { bv = s2v; bi = 2; }
            if (s3v > bv) { bv = s3v; bi = 3; }
            g_best[e] = bi;
        }
    }
}

__device__ __forceinline__ void decode_edge(const int* __restrict__ ei, int i, int& s, int& d) {
    if (i < N_EDGES) {
        s = ei[i]; d = ei[N_EDGES + i];
    } else if (i < 2 * N_EDGES) {
        int e = i - N_EDGES;
        s = ei[e]; d = ei[N_EDGES + e] + g_best[e] * N_NODES;
    } else {
        int r = i - 2 * N_EDGES;
        int rep = r / N_NODES + 1;
        int n = r - (rep - 1) * N_NODES;
        s = n; d = n + rep * N_NODES;
    }
}

__global__ void k_count(const int* __restrict__ ei) {
    int i = blockIdx.x * blockDim.x + threadIdx.x;
    if (i >= NE_TOT) return;
    int s, d;
    decode_edge(ei, i, s, d);
    if (s != d) atomicAdd(&g_deg[d], 1);
}

__global__ void k_dinv() {
    int i = blockIdx.x * blockDim.x + threadIdx.x;
    if (i < N_TOT) g_dinv[i] = rsqrtf((float)(g_deg[i] + 1));
}

__global__ void k_scan1(const int* __restrict__ in, int* __restrict__ out, int n, int minus) {
    __shared__ int sm[256];
    int tid = threadIdx.x;
    int base = blockIdx.x * SCAN_BLK;
    int loc[4]; int sum = 0;
#pragma unroll
    for (int u = 0; u < 4; u++) {
        int i = base + tid * 4 + u;
        int v = (i < n) ? (in[i] - minus) : 0;
        loc[u] = sum; sum += v;
    }
    sm[tid] = sum;
    __syncthreads();
    for (int o = 1; o < 256; o <<= 1) {
        int t = (tid >= o) ? sm[tid - o] : 0;
        __syncthreads();
        sm[tid] += t;
        __syncthreads();
    }
    int pre = tid ? sm[tid - 1] : 0;
#pragma unroll
    for (int u = 0; u < 4; u++) {
        int i = base + tid * 4 + u;
        if (i < n) out[i] = pre + loc[u];
    }
    if (tid == 255) g_blocksum[blockIdx.x] = sm[255];
}

__global__ void k_scan2(int nb) {
    __shared__ int sm[256];
    int tid = threadIdx.x;
    sm[tid] = (tid < nb) ? g_blocksum[tid] : 0;
    __syncthreads();
    for (int o = 1; o < 256; o <<= 1) {
        int t = (tid >= o) ? sm[tid - o] : 0;
        __syncthreads();
        sm[tid] += t;
        __syncthreads();
    }
    if (tid < nb) g_blocksum[tid] = tid ? sm[tid - 1] : 0;
}

__global__ void k_scan3(int* __restrict__ out, int n) {
    int i = blockIdx.x * blockDim.x + threadIdx.x;
    if (i < n) out[i] += g_blocksum[i >> 10];
}

__global__ void k_fill(const int* __restrict__ ei) {
    int i = blockIdx.x * blockDim.x + threadIdx.x;
    if (i >= NE_TOT) return;
    int s, d;
    decode_edge(ei, i, s, d);
    if (s == d) return;
    int pos = g_rowptr[d] + atomicAdd(&g_cursor[d], 1);
    g_csr_src[pos] = s;
    g_csr_w[pos] = g_dinv[s] * g_dinv[d];
}

// OUT: 0 = skip fp32 store; 1 = store rows < N_NODES only; 2 = store all
template<int WS, int OUT>
__global__ void k_aggregate(const float* __restrict__ X, const float* __restrict__ bias,
                            float* __restrict__ Out) {
    int w = (blockIdx.x * blockDim.x + threadIdx.x) >> 5;
    if (w >= N_TOT) return;
    int lane = threadIdx.x & 31;
    int start = g_rowptr[w];
    int len = g_deg[w];
    float dv = g_dinv[w];
    float ws = dv * dv;
    const float4* xd = (const float4*)(X + (size_t)w * 256);
    float4 sa = xd[lane * 2], sb = xd[lane * 2 + 1];
    float acc0 = ws * sa.x, acc1 = ws * sa.y, acc2 = ws * sa.z, acc3 = ws * sa.w;
    float acc4 = ws * sb.x, acc5 = ws * sb.y, acc6 = ws * sb.z, acc7 = ws * sb.w;
    int j = 0;
    for (; j + 4 <= len; j += 4) {
        int s0 = g_csr_src[start + j];
        int s1 = g_csr_src[start + j + 1];
        int s2 = g_csr_src[start + j + 2];
        int s3 = g_csr_src[start + j + 3];
        float w0 = g_csr_w[start + j];
        float w1 = g_csr_w[start + j + 1];
        float w2 = g_csr_w[start + j + 2];
        float w3 = g_csr_w[start + j + 3];
        const float4* x0 = (const float4*)(X + (size_t)s0 * 256);
        const float4* x1 = (const float4*)(X + (size_t)s1 * 256);
        const float4* x2 = (const float4*)(X + (size_t)s2 * 256);
        const float4* x3 = (const float4*)(X + (size_t)s3 * 256);
        float4 u0 = x0[lane * 2], v0 = x0[lane * 2 + 1];
        float4 u1 = x1[lane * 2], v1 = x1[lane * 2 + 1];
        float4 u2 = x2[lane * 2], v2 = x2[lane * 2 + 1];
        float4 u3 = x3[lane * 2], v3 = x3[lane * 2 + 1];
        acc0 = fmaf(w0, u0.x, acc0); acc1 = fmaf(w0, u0.y, acc1);
        acc2 = fmaf(w0, u0.z, acc2); acc3 = fmaf(w0, u0.w, acc3);
        acc4 = fmaf(w0, v0.x, acc4); acc5 = fmaf(w0, v0.y, acc5);
        acc6 = fmaf(w0, v0.z, acc6); acc7 = fmaf(w0, v0.w, acc7);
        acc0 = fmaf(w1, u1.x, acc0); acc1 = fmaf(w1, u1.y, acc1);
        acc2 = fmaf(w1, u1.z, acc2); acc3 = fmaf(w1, u1.w, acc3);
        acc4 = fmaf(w1, v1.x, acc4); acc5 = fmaf(w1, v1.y, acc5);
        acc6 = fmaf(w1, v1.z, acc6); acc7 = fmaf(w1, v1.w, acc7);
        acc0 = fmaf(w2, u2.x, acc0); acc1 = fmaf(w2, u2.y, acc1);
        acc2 = fmaf(w2, u2.z, acc2); acc3 = fmaf(w2, u2.w, acc3);
        acc4 = fmaf(w2, v2.x, acc4); acc5 = fmaf(w2, v2.y, acc5);
        acc6 = fmaf(w2, v2.z, acc6); acc7 = fmaf(w2, v2.w, acc7);
        acc0 = fmaf(w3, u3.x, acc0); acc1 = fmaf(w3, u3.y, acc1);
        acc2 = fmaf(w3, u3.z, acc2); acc3 = fmaf(w3, u3.w, acc3);
        acc4 = fmaf(w3, v3.x, acc4); acc5 = fmaf(w3, v3.y, acc5);
        acc6 = fmaf(w3, v3.z, acc6); acc7 = fmaf(w3, v3.w, acc7);
    }
    for (; j < len; j++) {
        int s0 = g_csr_src[start + j];
        float w0 = g_csr_w[start + j];
        const float4* x0 = (const float4*)(X + (size_t)s0 * 256);
        float4 u0 = x0[lane * 2], v0 = x0[lane * 2 + 1];
        acc0 = fmaf(w0, u0.x, acc0); acc1 = fmaf(w0, u0.y, acc1);
        acc2 = fmaf(w0, u0.z, acc2); acc3 = fmaf(w0, u0.w, acc3);
        acc4 = fmaf(w0, v0.x, acc4); acc5 = fmaf(w0, v0.y, acc5);
        acc6 = fmaf(w0, v0.z, acc6); acc7 = fmaf(w0, v0.w, acc7);
    }
    const float4* b4 = (const float4*)bias;
    float4 bb0 = b4[lane * 2], bb1 = b4[lane * 2 + 1];
    float o[8] = {acc0 + bb0.x, acc1 + bb0.y, acc2 + bb0.z, acc3 + bb0.w,
                  acc4 + bb1.x, acc5 + bb1.y, acc6 + bb1.z, acc7 + bb1.w};
    if (OUT == 2 || (OUT == 1 && w < N_NODES)) {
        float4* od = (float4*)(Out + (size_t)w * 256);
        od[lane * 2] = make_float4(o[0], o[1], o[2], o[3]);
        od[lane * 2 + 1] = make_float4(o[4], o[5], o[6], o[7]);
    }
    if (WS) {
        uint32_t hw[4], lw[4];
#pragma unroll
        for (int q = 0; q < 4; q++) {
            __half h0, l0, h1, l1;
            split2(fmaxf(o[q * 2], 0.f), h0, l0);
            split2(fmaxf(o[q * 2 + 1], 0.f), h1, l1);
            hw[q] = hpack2(h0, h1); lw[q] = hpack2(l0, l1);
        }
        size_t so = (size_t)w * 256 + lane * 8;
        *(uint4*)(g_Ahi + so) = make_uint4(hw[0], hw[1], hw[2], hw[3]);
        *(uint4*)(g_Alo + so) = make_uint4(lw[0], lw[1], lw[2], lw[3]);
    }
}

__global__ void k_H(float* __restrict__ Hout) {
    int n = blockIdx.x * blockDim.x + threadIdx.x;
    if (n >= N_NODES) return;
    int c0 = g_cls[n];
    int c1 = g_cls[N_NODES + n];
    int c2 = g_cls[2 * N_NODES + n];
    int c3 = g_cls[3 * N_NODES + n];
    int c4 = g_cls[4 * N_NODES + n];
    float* o = Hout + (size_t)n * 64;
#pragma unroll
    for (int j = 0; j < 64; j++)
        o[j] = (float)((c0 == j) + (c1 == j) + (c2 == j) + (c3 == j) + (c4 == j));
}

__global__ void k_hyperedge(const float* __restrict__ Hout, float* __restrict__ hf) {
    extern __shared__ float acc[];
    int tid = threadIdx.x;
    for (int i = tid; i < 16384; i += 256) acc[i] = 0.f;
    __syncthreads();
    int warp = tid >> 5, lane = tid & 31;
    for (int n = blockIdx.x * 8 + warp; n < N_NODES; n += gridDim.x * 8) {
        float h0 = Hout[(size_t)n * 64 + lane];
        float h1 = Hout[(size_t)n * 64 + lane + 32];
        unsigned m0 = __ballot_sync(0xffffffffu, h0 > 0.f);
        unsigned m1 = __ballot_sync(0xffffffffu, h1 > 0.f);
        const float4* xr = (const float4*)(g_B + (size_t)n * 256);
        float4 a = xr[lane * 2], b = xr[lane * 2 + 1];
        unsigned mm = m0;
        while (mm) {
            int c = __ffs(mm) - 1; mm &= mm - 1;
            float* p = acc + c * 256 + lane * 8;
            atomicAdd(p + 0, a.x); atomicAdd(p + 1, a.y); atomicAdd(p + 2, a.z); atomicAdd(p + 3, a.w);
            atomicAdd(p + 4, b.x); atomicAdd(p + 5, b.y); atomicAdd(p + 6, b.z); atomicAdd(p + 7, b.w);
        }
        mm = m1;
        while (mm) {
            int c = (__ffs(mm) - 1) + 32; mm &= mm - 1;
            float* p = acc + c * 256 + lane * 8;
            atomicAdd(p + 0, a.x); atomicAdd(p + 1, a.y); atomicAdd(p + 2, a.z); atomicAdd(p + 3, a.w);
            atomicAdd(p + 4, b.x); atomicAdd(p + 5, b.y); atomicAdd(p + 6, b.z); atomicAdd(p + 7, b.w);
        }
    }
    __syncthreads();
    for (int i = tid; i < 16384; i += 256) atomicAdd(&hf[i], acc[i]);
}

// ---------------- launch ----------------
extern "C" void kernel_launch(void* const* d_in, const int* in_sizes, int n_in,
                              void* d_out, int out_size) {
    const int*   ei       = (const int*)d_in[0];
    const float* features = (const float*)d_in[1];
    const float* lin_w    = (const float*)d_in[2];
    const float* lin_b    = (const float*)d_in[3];
    const float* gcn0_w   = (const float*)d_in[4];
    const float* gcn0_b   = (const float*)d_in[5];
    const float* gcn1_w   = (const float*)d_in[6];
    const float* gcn1_b   = (const float*)d_in[7];
    const float* lin1_w   = (const float*)d_in[8];
    const float* lin1_b   = (const float*)d_in[9];

    float* out      = (float*)d_out;
    float* H_out    = out;
    float* hf_out   = out + (size_t)N_NODES * NS;
    float* dots_out = hf_out + NS * D;

    float *X, *B, *ZB;
    int *CUR, *DEG, *ROWPTR, *ODEG, *OROW, *OCUR;
    __half *AH, *AL, *AH2, *AL2, *WH, *WL;
    cudaGetSymbolAddress((void**)&X,  g_X);
    cudaGetSymbolAddress((void**)&B,  g_B);
    cudaGetSymbolAddress((void**)&ZB, g_zerobias);
    cudaGetSymbolAddress((void**)&CUR, g_cursor);
    cudaGetSymbolAddress((void**)&DEG, g_deg);
    cudaGetSymbolAddress((void**)&ROWPTR, g_rowptr);
    cudaGetSymbolAddress((void**)&ODEG, g_odeg);
    cudaGetSymbolAddress((void**)&OROW, g_orow);
    cudaGetSymbolAddress((void**)&OCUR, g_ocur);
    cudaGetSymbolAddress((void**)&AH, g_Ahi);
    cudaGetSymbolAddress((void**)&AL, g_Alo);
    cudaGetSymbolAddress((void**)&AH2, g_Ahi2);
    cudaGetSymbolAddress((void**)&AL2, g_Alo2);
    cudaGetSymbolAddress((void**)&WH, g_Whi);
    cudaGetSymbolAddress((void**)&WL, g_Wlo);

    cudaFuncSetAttribute(k_hyperedge,  cudaFuncAttributeMaxDynamicSharedMemorySize, 65536);
    cudaFuncSetAttribute(k_mmagemm<0>, cudaFuncAttributeMaxDynamicSharedMemorySize, SMG_BYTES);
    cudaFuncSetAttribute(k_mmagemm<1>, cudaFuncAttributeMaxDynamicSharedMemorySize, SMG_BYTES);
    cudaFuncSetAttribute(k_mmagemm64<0>, cudaFuncAttributeMaxDynamicSharedMemorySize, SM64_BYTES);
    cudaFuncSetAttribute(k_mmagemm64<1>, cudaFuncAttributeMaxDynamicSharedMemorySize, SM64_BYTES);

    const int nb_tot  = (N_TOT + SCAN_BLK - 1) / SCAN_BLK;
    const int nb_node = (N_NODES + SCAN_BLK - 1) / SCAN_BLK;

    // launches 1-4: weight splits; 5: feature split (relu->buf1, raw->buf2, zero invn)
    k_wsplit<<<dim3(256, 4), 256>>>(lin_w, 0, 256, 65536);
    k_wsplit<<<dim3(256, 1), 256>>>(gcn0_w, 4, 256, 0);
    k_wsplit<<<dim3(256, 1), 256>>>(gcn1_w, 5, 256, 0);
    k_wsplit<<<dim3(64, 1), 256>>>(lin1_w, 6, 64, 0);
    k_split_both<<<(N_NODES * 64 + 255) / 256, 256>>>((const float4*)features, N_NODES * 64);

    // launch 6 (PROFILED): heads GEMM on raw splits; epilogue writes
    // split(relu)->buf1, split(raw)->buf2 rows N..5N + sumsq atomics (no fp32 C)
    k_mmagemm<1><<<dim3(2, (N_NODES + 127) / 128, 4), 256, SMG_BYTES>>>(
        AH2, AL2, WH, WL, lin_b, X /*unused*/, N_NODES, 65536, 0, 256);
    k_finish_invn<<<(T_REP * N_NODES + 255) / 256, 256>>>();

    // original-edge CSR
    cudaMemsetAsync(ODEG, 0, N_NODES * sizeof(int));
    cudaMemsetAsync(OCUR, 0, N_NODES * sizeof(int));
    k_ocount<<<(N_EDGES + 255) / 256, 256>>>(ei);
    k_scan1<<<nb_node, 256>>>(ODEG, OROW, N_NODES, 0);
    k_scan2<<<1, 256>>>(nb_node);
    k_scan3<<<(N_NODES + 255) / 256, 256>>>(OROW, N_NODES);
    k_ofill<<<(N_EDGES + 255) / 256, 256>>>(ei);

    // per-edge best replica (split-reconstructed rows)
    k_edge_sim2<<<(N_NODES * 32 + 255) / 256, 256>>>(ei);

    // augmented-graph CSR
    cudaMemsetAsync(DEG, 0, N_TOT * sizeof(int));
    k_count<<<(NE_TOT + 255) / 256, 256>>>(ei);
    k_dinv<<<(N_TOT + 255) / 256, 256>>>();
    k_scan1<<<nb_tot, 256>>>(DEG, ROWPTR, N_TOT, 0);
    k_scan2<<<1, 256>>>(nb_tot);
    k_scan3<<<(N_TOT + 255) / 256, 256>>>(ROWPTR, N_TOT);
    cudaMemsetAsync(CUR, 0, N_TOT * sizeof(int));
    k_fill<<<(NE_TOT + 255) / 256, 256>>>(ei);

    // GCN layer 0 (aggregate fp32 output dead -> OUT=0)
    k_mmagemm<0><<<dim3(2, (N_TOT + 127) / 128, 1), 256, SMG_BYTES>>>(
        AH, AL, WH + 4 * 65536, WL + 4 * 65536, ZB, X, N_TOT, 0, 0, 0);
    k_aggregate<1, 0><<<(N_TOT * 32 + 255) / 256, 256>>>(X, gcn0_b, B);

    // GCN layer 1 (fp32 out only base rows -> OUT=1)
    k_mmagemm<0><<<dim3(2, (N_TOT + 127) / 128, 1), 256, SMG_BYTES>>>(
        AH, AL, WH + 5 * 65536, WL + 5 * 65536, ZB, X, N_TOT, 0, 0, 0);
    k_aggregate<1, 1><<<(N_TOT * 32 + 255) / 256, 256>>>(X, gcn1_b, B);

    // logits mma with fused argmax -> g_cls; then H
    k_mmagemm64<0><<<(N_TOT + 127) / 128, 256, SM64_BYTES>>>(
        AH, AL, WH + 6 * 65536, WL + 6 * 65536, lin1_b, X, N_TOT, 0.f);
    k_H<<<(N_NODES + 255) / 256, 256>>>(H_out);

    // hyperedge features, split hf into slot 7
    cudaMemsetAsync(hf_out, 0, (size_t)NS * D * sizeof(float));
    k_hyperedge<<<160, 256, 65536>>>(H_out, hf_out);
    k_wsplit_dir<<<64, 256>>>(hf_out, 7, NS * D);

    // dots via mma on raw splits (buf2)
    k_mmagemm64<1><<<(N_TOT + 127) / 128, 256, SM64_BYTES>>>(
        AH2, AL2, WH + 7 * 65536, WL + 7 * 65536, ZB, dots_out, N_TOT, 0.0625f);
}

// round 16
// speedup vs baseline: 1.0889x; 1.0073x over previous
#include <cuda_runtime.h>
#include <cuda_fp16.h>
#include <cstdint>

#define N_NODES 50000
#define N_EDGES 800000
#define D 256
#define T_REP 4
#define NS 64
#define N_TOT (5 * N_NODES)                 /* 250000 */
#define NE_TOT (2 * N_EDGES + 3 * N_NODES)  /* 1750000 */
#define SCAN_BLK 1024
#define NPAD 250112

typedef unsigned long long u64;

__device__ __forceinline__ uint32_t smem_to_u32(const void* p) {
    uint32_t a;
    asm("{ .reg .u64 t; cvta.to.shared.u64 t, %1; cvt.u32.u64 %0, t; }" : "=r"(a) : "l"(p));
    return a;
}

#define LDMATRIX_X4(r0, r1, r2, r3, addr) \
    asm volatile("ldmatrix.sync.aligned.m8n8.x4.shared.b16 {%0,%1,%2,%3}, [%4];" \
                 : "=r"(r0), "=r"(r1), "=r"(r2), "=r"(r3) : "r"(addr))

#define MMAF16(c, a, b0, b1) \
    asm volatile("mma.sync.aligned.m16n8k16.row.col.f32.f16.f16.f32 " \
                 "{%0,%1,%2,%3}, {%4,%5,%6,%7}, {%8,%9}, {%0,%1,%2,%3};" \
                 : "+f"((c)[0]), "+f"((c)[1]), "+f"((c)[2]), "+f"((c)[3]) \
                 : "r"((a)[0]), "r"((a)[1]), "r"((a)[2]), "r"((a)[3]), "r"(b0), "r"(b1))

#define CP16(dst, src, sz) \
    asm volatile("cp.async.cg.shared.global [%0], [%1], 16, %2;" \
                 :: "r"(dst), "l"(src), "r"(sz))
#define CP_COMMIT() asm volatile("cp.async.commit_group;" ::: "memory")
#define CP_WAIT0()  asm volatile("cp.async.wait_group 0;" ::: "memory")

__device__ __forceinline__ void split2(float x, __half& h, __half& l) {
    h = __float2half_rn(x);
    l = __float2half_rn(x - __half2float(h));
}
__device__ __forceinline__ uint32_t hpack2(__half a, __half b) {
    return (uint32_t)__half_as_ushort(a) | ((uint32_t)__half_as_ushort(b) << 16);
}

// ---------------- scratch (device globals) ----------------
__device__ float g_X[(size_t)N_TOT * D];
__device__ float g_B[(size_t)N_TOT * D];
__device__ float g_invn[T_REP * N_NODES];   // sumsq accum (rsqrt applied in edge_sim)
__device__ int   g_deg[N_TOT];              // in-edge count (no self loop)
__device__ float g_dinv[N_TOT];
__device__ int   g_best[N_EDGES];
__device__ int   g_cls[N_TOT];
__device__ float g_zerobias[D];
__device__ int   g_rowptr[N_TOT];
__device__ int   g_blocksum[256];
__device__ int   g_cursor[N_TOT];
__device__ int   g_csr_src[NE_TOT];
__device__ float g_csr_w[NE_TOT];
__device__ int   g_odeg[N_NODES];
__device__ int   g_orow[N_NODES];
__device__ int   g_ocur[N_NODES];
__device__ int   g_oedge[N_EDGES];
// fp16 split buffers: buf1 = GEMM activations (relu), buf2 = raw values
__device__ __half g_Ahi[(size_t)NPAD * D];
__device__ __half g_Alo[(size_t)NPAD * D];
__device__ __half g_Ahi2[(size_t)NPAD * D];
__device__ __half g_Alo2[(size_t)NPAD * D];
__device__ __half g_Whi[8 * 65536];
__device__ __half g_Wlo[8 * 65536];

// reconstruct 8 floats (lane's 16B slice) from hi/lo split row
__device__ __forceinline__ void rec8(const __half* hi, const __half* lo, int lane,
                                     float4& a, float4& b) {
    uint4 h = __ldg((const uint4*)hi + lane);
    uint4 l = __ldg((const uint4*)lo + lane);
    float2 f0 = __half22float2(*(__half2*)&h.x), g0 = __half22float2(*(__half2*)&l.x);
    float2 f1 = __half22float2(*(__half2*)&h.y), g1 = __half22float2(*(__half2*)&l.y);
    float2 f2 = __half22float2(*(__half2*)&h.z), g2 = __half22float2(*(__half2*)&l.z);
    float2 f3 = __half22float2(*(__half2*)&h.w), g3 = __half22float2(*(__half2*)&l.w);
    a = make_float4(f0.x + g0.x, f0.y + g0.y, f1.x + g1.x, f1.y + g1.y);
    b = make_float4(f2.x + g2.x, f2.y + g2.y, f3.x + g3.x, f3.y + g3.y);
}

// ---------------- small kernels ----------------

// split relu(X)->buf1, raw X->buf2; zero invn/deg/cursor/odeg/ocur scratch
__global__ void k_split_both(const float4* __restrict__ X, int n4) {
    int i = blockIdx.x * blockDim.x + threadIdx.x;
    if (i >= n4) return;
    if (i < T_REP * N_NODES) g_invn[i] = 0.f;
    if (i < N_TOT) { g_deg[i] = 0; g_cursor[i] = 0; }
    if (i < N_NODES) { g_odeg[i] = 0; g_ocur[i] = 0; }
    float4 v = X[i];
    __half h0,l0,h1,l1,h2,l2,h3,l3;
    split2(v.x,h0,l0); split2(v.y,h1,l1); split2(v.z,h2,l2); split2(v.w,h3,l3);
    ((uint2*)g_Ahi2)[i] = make_uint2(hpack2(h0,h1), hpack2(h2,h3));
    ((uint2*)g_Alo2)[i] = make_uint2(hpack2(l0,l1), hpack2(l2,l3));
    float x0 = fmaxf(v.x, 0.f), x1 = fmaxf(v.y, 0.f);
    float x2 = fmaxf(v.z, 0.f), x3 = fmaxf(v.w, 0.f);
    split2(x0,h0,l0); split2(x1,h1,l1); split2(x2,h2,l2); split2(x3,h3,l3);
    ((uint2*)g_Ahi)[i] = make_uint2(hpack2(h0,h1), hpack2(h2,h3));
    ((uint2*)g_Alo)[i] = make_uint2(hpack2(l0,l1), hpack2(l2,l3));
}

// split + transpose a [256 x ncols] weight into slot widxBase + blockIdx.y
__global__ void k_wsplit(const float* __restrict__ W, int widxBase, int ncols, int wstride) {
    int widx = widxBase + blockIdx.y;
    const float* Wz = W + (size_t)blockIdx.y * wstride;
    int i = blockIdx.x * 256 + threadIdx.x;
    int n = i >> 8, k = i & 255;
    float x = Wz[k * ncols + n];
    __half h, l;
    split2(x, h, l);
    g_Whi[widx * 65536 + i] = h;
    g_Wlo[widx * 65536 + i] = l;
}

__global__ void k_wsplit_dir(const float* __restrict__ src, int widx, int nelem) {
    int i = blockIdx.x * 256 + threadIdx.x;
    if (i >= nelem) return;
    __half h, l;
    split2(src[i], h, l);
    g_Whi[widx * 65536 + i] = h;
    g_Wlo[widx * 65536 + i] = l;
}

// ---- fp16x3 GEMM (N=256) ----
// WS=0: C = A@W + bias. WS=1 (heads): splits to buf1/buf2 rows N..5N + sumsq atomics.
#define ASTRIDE 72
#define SMBUF (128 * ASTRIDE)
#define SMG_BYTES (4 * SMBUF * 2)
template<int WS>
__global__ __launch_bounds__(256, 2) void k_mmagemm(
    const __half* Ahi, const __half* Alo,
    const __half* __restrict__ Whi, const __half* __restrict__ Wlo,
    const float* __restrict__ bias, float* __restrict__ C,
    int M, int wz, int cz, int bzs)
{
    extern __shared__ __half smh[];
    __half* sAh = smh;
    __half* sAl = smh + SMBUF;
    __half* sBh = smh + 2 * SMBUF;
    __half* sBl = smh + 3 * SMBUF;

    const int tid = threadIdx.x;
    const int warp = tid >> 5, lane = tid & 31;
    const int wm = warp & 1, wn = warp >> 1;
    const int z = blockIdx.z;
    const int rBase = blockIdx.y << 7;
    const int colBase = blockIdx.x << 7;

    const __half* Wh = Whi + (size_t)z * wz;
    const __half* Wl = Wlo + (size_t)z * wz;

    float acc[4][4][4];
#pragma unroll
    for (int i = 0; i < 4; i++)
#pragma unroll
        for (int j = 0; j < 4; j++)
#pragma unroll
            for (int q = 0; q < 4; q++) acc[i][j][q] = 0.f;

    const uint32_t uAh = smem_to_u32(sAh);
    const uint32_t uAl = smem_to_u32(sAl);
    const uint32_t uBh = smem_to_u32(sBh);
    const uint32_t uBl = smem_to_u32(sBl);
    const int a_row_l = lane & 15;
    const int a_kh = (lane >> 4) << 3;
    const int b_n_off = (lane & 7) + ((lane >> 4) << 3);
    const int b_k_off = ((lane >> 3) & 1) << 3;

#pragma unroll 1
    for (int c = 0; c < 4; c++) {
#pragma unroll
        for (int s = 0; s < 2; s++) {
            const __half* ap = s ? Alo : Ahi;
            uint32_t ud = s ? uAl : uAh;
#pragma unroll
            for (int j = 0; j < 4; j++) {
                int i = tid + j * 256;
                int row = i >> 3, seg = i & 7;
                int gr = rBase + row;
                int grc = gr < M ? gr : 0;
                unsigned sz = gr < M ? 16u : 0u;
                CP16(ud + (uint32_t)(row * ASTRIDE + seg * 8) * 2,
                     ap + (size_t)grc * 256 + c * 64 + seg * 8, sz);
            }
            const __half* wp = s ? Wl : Wh;
            uint32_t wd = s ? uBl : uBh;
#pragma unroll
            for (int j = 0; j < 4; j++) {
                int i = tid + j * 256;
                int row = i >> 3, seg = i & 7;
                CP16(wd + (uint32_t)(row * ASTRIDE + seg * 8) * 2,
                     wp + (size_t)(colBase + row) * 256 + c * 64 + seg * 8, 16u);
            }
        }
        CP_COMMIT();
        CP_WAIT0();
        __syncthreads();
#pragma unroll
        for (int k = 0; k < 4; k++) {
            const int k0 = k << 4;
            const uint32_t aoff = (uint32_t)(((wm << 6) + a_row_l) * ASTRIDE + k0 + a_kh) * 2;
            const uint32_t boff0 = (uint32_t)(((wn << 5) + b_n_off) * ASTRIDE + k0 + b_k_off) * 2;
            const uint32_t boff1 = boff0 + (uint32_t)(16 * ASTRIDE) * 2;
            uint32_t ah[4][4], al[4][4], bh[2][4], bl[2][4];
#pragma unroll
            for (int mi = 0; mi < 4; mi++) {
                LDMATRIX_X4(ah[mi][0], ah[mi][1], ah[mi][2], ah[mi][3],
                            uAh + aoff + (uint32_t)((mi << 4) * ASTRIDE) * 2);
                LDMATRIX_X4(al[mi][0], al[mi][1], al[mi][2], al[mi][3],
                            uAl + aoff + (uint32_t)((mi << 4) * ASTRIDE) * 2);
            }
            LDMATRIX_X4(bh[0][0], bh[0][1], bh[0][2], bh[0][3], uBh + boff0);
            LDMATRIX_X4(bh[1][0], bh[1][1], bh[1][2], bh[1][3], uBh + boff1);
            LDMATRIX_X4(bl[0][0], bl[0][1], bl[0][2], bl[0][3], uBl + boff0);
            LDMATRIX_X4(bl[1][0], bl[1][1], bl[1][2], bl[1][3], uBl + boff1);
#pragma unroll
            for (int mi = 0; mi < 4; mi++)
#pragma unroll
                for (int ni = 0; ni < 4; ni++) {
                    uint32_t b0h = bh[ni >> 1][(ni & 1) * 2], b1h = bh[ni >> 1][(ni & 1) * 2 + 1];
                    uint32_t b0l = bl[ni >> 1][(ni & 1) * 2], b1l = bl[ni >> 1][(ni & 1) * 2 + 1];
                    MMAF16(acc[mi][ni], ah[mi], b0h, b1h);
                    MMAF16(acc[mi][ni], ah[mi], b0l, b1l);
                    MMAF16(acc[mi][ni], al[mi], b0h, b1h);
                }
        }
        __syncthreads();
    }

    const float* bp = bias + (size_t)z * bzs;
    float* Cz = C + (size_t)z * cz;
#pragma unroll
    for (int mi = 0; mi < 4; mi++) {
#pragma unroll
        for (int hf2 = 0; hf2 < 2; hf2++) {
            int gr = rBase + (wm << 6) + (mi << 4) + (lane >> 2) + hf2 * 8;
            if (WS == 0) {
                if (gr >= M) continue;
#pragma unroll
                for (int ni = 0; ni < 4; ni++) {
                    int col = colBase + (wn << 5) + (ni << 3) + (lane & 3) * 2;
                    float o0 = acc[mi][ni][hf2 * 2] + bp[col];
                    float o1 = acc[mi][ni][hf2 * 2 + 1] + bp[col + 1];
                    *(float2*)&Cz[(size_t)gr * 256 + col] = make_float2(o0, o1);
                }
            } else {
                float ss = 0.f;
                if (gr < M) {
#pragma unroll
                    for (int ni = 0; ni < 4; ni++) {
                        int col = colBase + (wn << 5) + (ni << 3) + (lane & 3) * 2;
                        float o0 = acc[mi][ni][hf2 * 2] + bp[col];
                        float o1 = acc[mi][ni][hf2 * 2 + 1] + bp[col + 1];
                        ss += o0 * o0 + o1 * o1;
                        size_t so = (size_t)(N_NODES + z * N_NODES + gr) * 256 + col;
                        __half h0, l0, h1, l1;
                        split2(fmaxf(o0, 0.f), h0, l0);
                        split2(fmaxf(o1, 0.f), h1, l1);
                        *(uint32_t*)(g_Ahi + so) = hpack2(h0, h1);
                        *(uint32_t*)(g_Alo + so) = hpack2(l0, l1);
                        split2(o0, h0, l0);
                        split2(o1, h1, l1);
                        *(uint32_t*)(g_Ahi2 + so) = hpack2(h0, h1);
                        *(uint32_t*)(g_Alo2 + so) = hpack2(l0, l1);
                    }
                }
                ss += __shfl_xor_sync(0xffffffffu, ss, 1);
                ss += __shfl_xor_sync(0xffffffffu, ss, 2);
                if ((lane & 3) == 0 && gr < M)
                    atomicAdd(&g_invn[z * N_NODES + gr], ss);
            }
        }
    }
}

// ---- fp16x3 GEMM (N=64): MODE 0 logits+fused argmax; MODE 1 *scale ----
#define SM64_A (128 * ASTRIDE)
#define SM64_B (64 * ASTRIDE)
#define SM64_BYTES ((2 * SM64_A + 2 * SM64_B) * 2)
template<int MODE>
__global__ __launch_bounds__(256, 2) void k_mmagemm64(
    const __half* Ahi, const __half* Alo,
    const __half* __restrict__ Wh, const __half* __restrict__ Wl,
    const float* __restrict__ bias, float* __restrict__ C, int M, float scale)
{
    extern __shared__ __half smh[];
    __half* sAh = smh;
    __half* sAl = smh + SM64_A;
    __half* sBh = smh + 2 * SM64_A;
    __half* sBl = smh + 2 * SM64_A + SM64_B;
    __shared__ float sval[128];
    __shared__ int   sidx[128];

    const int tid = threadIdx.x;
    const int warp = tid >> 5, lane = tid & 31;
    const int wm = warp >> 1, wn = warp & 1;
    const int rBase = blockIdx.x << 7;

    float acc[2][4][4];
#pragma unroll
    for (int i = 0; i < 2; i++)
#pragma unroll
        for (int j = 0; j < 4; j++)
#pragma unroll
            for (int q = 0; q < 4; q++) acc[i][j][q] = 0.f;

    const uint32_t uAh = smem_to_u32(sAh);
    const uint32_t uAl = smem_to_u32(sAl);
    const uint32_t uBh = smem_to_u32(sBh);
    const uint32_t uBl = smem_to_u32(sBl);
    const int a_row_l = lane & 15;
    const int a_kh = (lane >> 4) << 3;
    const int b_n_off = (lane & 7) + ((lane >> 4) << 3);
    const int b_k_off = ((lane >> 3) & 1) << 3;

#pragma unroll 1
    for (int c = 0; c < 4; c++) {
#pragma unroll
        for (int s = 0; s < 2; s++) {
            const __half* ap = s ? Alo : Ahi;
            uint32_t ud = s ? uAl : uAh;
#pragma unroll
            for (int j = 0; j < 4; j++) {
                int i = tid + j * 256;
                int row = i >> 3, seg = i & 7;
                int gr = rBase + row;
                int grc = gr < M ? gr : 0;
                unsigned sz = gr < M ? 16u : 0u;
                CP16(ud + (uint32_t)(row * ASTRIDE + seg * 8) * 2,
                     ap + (size_t)grc * 256 + c * 64 + seg * 8, sz);
            }
            const __half* wp = s ? Wl : Wh;
            uint32_t wd = s ? uBl : uBh;
#pragma unroll
            for (int j = 0; j < 2; j++) {
                int i = tid + j * 256;
                int row = i >> 3, seg = i & 7;
                CP16(wd + (uint32_t)(row * ASTRIDE + seg * 8) * 2,
                     wp + (size_t)row * 256 + c * 64 + seg * 8, 16u);
            }
        }
        CP_COMMIT();
        CP_WAIT0();
        __syncthreads();
#pragma unroll
        for (int k = 0; k < 4; k++) {
            const int k0 = k << 4;
            const uint32_t aoff = (uint32_t)(((wm << 5) + a_row_l) * ASTRIDE + k0 + a_kh) * 2;
            const uint32_t boff0 = (uint32_t)(((wn << 5) + b_n_off) * ASTRIDE + k0 + b_k_off) * 2;
            const uint32_t boff1 = boff0 + (uint32_t)(16 * ASTRIDE) * 2;
            uint32_t ah[2][4], al[2][4], bh[2][4], bl[2][4];
#pragma unroll
            for (int mi = 0; mi < 2; mi++) {
                LDMATRIX_X4(ah[mi][0], ah[mi][1], ah[mi][2], ah[mi][3],
                            uAh + aoff + (uint32_t)((mi << 4) * ASTRIDE) * 2);
                LDMATRIX_X4(al[mi][0], al[mi][1], al[mi][2], al[mi][3],
                            uAl + aoff + (uint32_t)((mi << 4) * ASTRIDE) * 2);
            }
            LDMATRIX_X4(bh[0][0], bh[0][1], bh[0][2], bh[0][3], uBh + boff0);
            LDMATRIX_X4(bh[1][0], bh[1][1], bh[1][2], bh[1][3], uBh + boff1);
            LDMATRIX_X4(bl[0][0], bl[0][1], bl[0][2], bl[0][3], uBl + boff0);
            LDMATRIX_X4(bl[1][0], bl[1][1], bl[1][2], bl[1][3], uBl + boff1);
#pragma unroll
            for (int mi = 0; mi < 2; mi++)
#pragma unroll
                for (int ni = 0; ni < 4; ni++) {
                    uint32_t b0h = bh[ni >> 1][(ni & 1) * 2], b1h = bh[ni >> 1][(ni & 1) * 2 + 1];
                    uint32_t b0l = bl[ni >> 1][(ni & 1) * 2], b1l = bl[ni >> 1][(ni & 1) * 2 + 1];
                    MMAF16(acc[mi][ni], ah[mi], b0h, b1h);
                    MMAF16(acc[mi][ni], ah[mi], b0l, b1l);
                    MMAF16(acc[mi][ni], al[mi], b0h, b1h);
                }
        }
        __syncthreads();
    }

    if (MODE == 1) {
#pragma unroll
        for (int mi = 0; mi < 2; mi++)
#pragma unroll
            for (int hf2 = 0; hf2 < 2; hf2++) {
                int gr = rBase + (wm << 5) + (mi << 4) + (lane >> 2) + hf2 * 8;
                if (gr >= M) continue;
#pragma unroll
                for (int ni = 0; ni < 4; ni++) {
                    int col = (wn << 5) + (ni << 3) + (lane & 3) * 2;
                    float o0 = acc[mi][ni][hf2 * 2] * scale;
                    float o1 = acc[mi][ni][hf2 * 2 + 1] * scale;
                    *(float2*)&C[(size_t)gr * 64 + col] = make_float2(o0, o1);
                }
            }
    } else {
        float rv[4]; int ridx[4];
#pragma unroll
        for (int mi = 0; mi < 2; mi++)
#pragma unroll
            for (int hf2 = 0; hf2 < 2; hf2++) {
                float v = -3.4e38f; int idx = 0;
#pragma unroll
                for (int ni = 0; ni < 4; ni++) {
                    int col = (wn << 5) + (ni << 3) + (lane & 3) * 2;
                    float o0 = acc[mi][ni][hf2 * 2] + bias[col];
                    float o1 = acc[mi][ni][hf2 * 2 + 1] + bias[col + 1];
                    if (o0 > v) { v = o0; idx = col; }
                    if (o1 > v) { v = o1; idx = col + 1; }
                }
#pragma unroll
                for (int o = 1; o <= 2; o <<= 1) {
                    float ov = __shfl_xor_sync(0xffffffffu, v, o);
                    int oi = __shfl_xor_sync(0xffffffffu, idx, o);
                    if (ov > v || (ov == v && oi < idx)) { v = ov; idx = oi; }
                }
                int lr = (wm << 5) + (mi << 4) + hf2 * 8 + (lane >> 2);
                if (wn == 0 && (lane & 3) == 0) { sval[lr] = v; sidx[lr] = idx; }
                rv[mi * 2 + hf2] = v; ridx[mi * 2 + hf2] = idx;
            }
        __syncthreads();
        if (wn == 1 && (lane & 3) == 0) {
#pragma unroll
            for (int mi = 0; mi < 2; mi++)
#pragma unroll
                for (int hf2 = 0; hf2 < 2; hf2++) {
                    int lr = (wm << 5) + (mi << 4) + hf2 * 8 + (lane >> 2);
                    int gr = rBase + lr;
                    if (gr >= M) continue;
                    float v0 = sval[lr]; int i0 = sidx[lr];
                    float v1 = rv[mi * 2 + hf2]; int i1 = ridx[mi * 2 + hf2];
                    g_cls[gr] = (v1 > v0) ? i1 : i0;
                }
        }
    }
}

__device__ __forceinline__ float dot8(float4 f0, float4 f1, float4 a, float4 b) {
    return f0.x * a.x + f0.y * a.y + f0.z * a.z + f0.w * a.w +
           f1.x * b.x + f1.y * b.y + f1.z * b.z + f1.w * b.w;
}

__global__ void k_ocount(const int* __restrict__ ei) {
    int i = blockIdx.x * blockDim.x + threadIdx.x;
    if (i < N_EDGES) atomicAdd(&g_odeg[ei[N_EDGES + i]], 1);
}

__global__ void k_ofill(const int* __restrict__ ei) {
    int i = blockIdx.x * blockDim.x + threadIdx.x;
    if (i >= N_EDGES) return;
    int d = ei[N_EDGES + i];
    int pos = g_orow[d] + atomicAdd(&g_ocur[d], 1);
    g_oedge[pos] = i;
}

// per-edge best replica; rows reconstructed from buf2 splits; invn from sumsq
__global__ void k_edge_sim2(const int* __restrict__ ei) {
    int d = (blockIdx.x * blockDim.x + threadIdx.x) >> 5;
    if (d >= N_NODES) return;
    int lane = threadIdx.x & 31;
    int len = g_odeg[d];
    if (len == 0) return;
    int start = g_orow[d];
    float4 a0, b0, a1, b1, a2, b2, a3, b3;
    rec8(g_Ahi2 + ((size_t)1 * N_NODES + d) * 256, g_Alo2 + ((size_t)1 * N_NODES + d) * 256, lane, a0, b0);
    rec8(g_Ahi2 + ((size_t)2 * N_NODES + d) * 256, g_Alo2 + ((size_t)2 * N_NODES + d) * 256, lane, a1, b1);
    rec8(g_Ahi2 + ((size_t)3 * N_NODES + d) * 256, g_Alo2 + ((size_t)3 * N_NODES + d) * 256, lane, a2, b2);
    rec8(g_Ahi2 + ((size_t)4 * N_NODES + d) * 256, g_Alo2 + ((size_t)4 * N_NODES + d) * 256, lane, a3, b3);
    float i0 = 1.f / fmaxf(sqrtf(g_invn[d]), 1e-8f);
    float i1 = 1.f / fmaxf(sqrtf(g_invn[N_NODES + d]), 1e-8f);
    float i2 = 1.f / fmaxf(sqrtf(g_invn[2 * N_NODES + d]), 1e-8f);
    float i3 = 1.f / fmaxf(sqrtf(g_invn[3 * N_NODES + d]), 1e-8f);
    int j = 0;
    for (; j + 2 <= len; j += 2) {
        int e0 = g_oedge[start + j], e1 = g_oedge[start + j + 1];
        int s0 = __ldg(ei + e0), s1 = __ldg(ei + e1);
        float4 fA, fB, gA, gB;
        rec8(g_Ahi2 + (size_t)s0 * 256, g_Alo2 + (size_t)s0 * 256, lane, fA, fB);
        rec8(g_Ahi2 + (size_t)s1 * 256, g_Alo2 + (size_t)s1 * 256, lane, gA, gB);
        float p0 = dot8(fA, fB, a0, b0), q0 = dot8(gA, gB, a0, b0);
        float p1 = dot8(fA, fB, a1, b1), q1 = dot8(gA, gB, a1, b1);
        float p2 = dot8(fA, fB, a2, b2), q2 = dot8(gA, gB, a2, b2);
        float p3 = dot8(fA, fB, a3, b3), q3 = dot8(gA, gB, a3, b3);
#pragma unroll
        for (int o = 16; o; o >>= 1) {
            p0 += __shfl_xor_sync(0xffffffffu, p0, o);
            p1 += __shfl_xor_sync(0xffffffffu, p1, o);
            p2 += __shfl_xor_sync(0xffffffffu, p2, o);
            p3 += __shfl_xor_sync(0xffffffffu, p3, o);
            q0 += __shfl_xor_sync(0xffffffffu, q0, o);
            q1 += __shfl_xor_sync(0xffffffffu, q1, o);
            q2 += __shfl_xor_sync(0xffffffffu, q2, o);
            q3 += __shfl_xor_sync(0xffffffffu, q3, o);
        }
        if (lane == 0) {
            float s0v = p0 * i0, s1v = p1 * i1, s2v = p2 * i2, s3v = p3 * i3;
            float bv = s0v; int bi = 0;
            if (s1v > bv) { bv = s1v; bi = 1; }
            if (s2v > bv) { bv = s2v; bi = 2; }
            if (s3v > bv) { bv = s3v; bi = 3; }
            g_best[e0] = bi;
            float u0v = q0 * i0, u1v = q1 * i1, u2v = q2 * i2, u3v = q3 * i3;
            float cv = u0v; int ci = 0;
            if (u1v > cv) { cv = u1v; ci = 1; }
            if (u2v > cv) { cv = u2v; ci = 2; }
            if (u3v > cv) { cv = u3v; ci = 3; }
            g_best[e1] = ci;
        }
    }
    if (j < len) {
        int e = g_oedge[start + j];
        int s = __ldg(ei + e);
        float4 f0, f1;
        rec8(g_Ahi2 + (size_t)s * 256, g_Alo2 + (size_t)s * 256, lane, f0, f1);
        float p0 = dot8(f0, f1, a0, b0);
        float p1 = dot8(f0, f1, a1, b1);
        float p2 = dot8(f0, f1, a2, b2);
        float p3 = dot8(f0, f1, a3, b3);
#pragma unroll
        for (int o = 16; o; o >>= 1) {
            p0 += __shfl_xor_sync(0xffffffffu, p0, o);
            p1 += __shfl_xor_sync(0xffffffffu, p1, o);
            p2 += __shfl_xor_sync(0xffffffffu, p2, o);
            p3 += __shfl_xor_sync(0xffffffffu, p3, o);
        }
        if (lane == 0) {
            float s0v = p0 * i0, s1v = p1 * i1, s2v = p2 * i2, s3v = p3 * i3;
            float bv = s0v; int bi = 0;
            if (s1v > bv) { bv = s1v; bi = 1; }
            if (s2v > bv) { bv = s2v; bi = 2; }
            if (s3v > bv) { bv = s3v; bi = 3; }
            g_best[e] = bi;
        }
    }
}

__device__ __forceinline__ void decode_edge(const int* __restrict__ ei, int i, int& s, int& d) {
    if (i < N_EDGES) {
        s = ei[i]; d = ei[N_EDGES + i];
    } else if (i < 2 * N_EDGES) {
        int e = i - N_EDGES;
        s = ei[e]; d = ei[N_EDGES + e] + g_best[e] * N_NODES;
    } else {
        int r = i - 2 * N_EDGES;
        int rep = r / N_NODES + 1;
        int n = r - (rep - 1) * N_NODES;
        s = n; d = n + rep * N_NODES;
    }
}

__global__ void k_count(const int* __restrict__ ei) {
    int i = blockIdx.x * blockDim.x + threadIdx.x;
    if (i >= NE_TOT) return;
    int s, d;
    decode_edge(ei, i, s, d);
    if (s != d) atomicAdd(&g_deg[d], 1);
}

// exclusive scan; DODINV: also write g_dinv[i] = rsqrt(in[i]+1)
template<int DODINV>
__global__ void k_scan1(const int* __restrict__ in, int* __restrict__ out, int n) {
    __shared__ int sm[256];
    int tid = threadIdx.x;
    int base = blockIdx.x * SCAN_BLK;
    int loc[4]; int sum = 0;
#pragma unroll
    for (int u = 0; u < 4; u++) {
        int i = base + tid * 4 + u;
        int v = (i < n) ? in[i] : 0;
        if (DODINV && i < n) g_dinv[i] = rsqrtf((float)(v + 1));
        loc[u] = sum; sum += v;
    }
    sm[tid] = sum;
    __syncthreads();
    for (int o = 1; o < 256; o <<= 1) {
        int t = (tid >= o) ? sm[tid - o] : 0;
        __syncthreads();
        sm[tid] += t;
        __syncthreads();
    }
    int pre = tid ? sm[tid - 1] : 0;
#pragma unroll
    for (int u = 0; u < 4; u++) {
        int i = base + tid * 4 + u;
        if (i < n) out[i] = pre + loc[u];
    }
    if (tid == 255) g_blocksum[blockIdx.x] = sm[255];
}

__global__ void k_scan2(int nb) {
    __shared__ int sm[256];
    int tid = threadIdx.x;
    sm[tid] = (tid < nb) ? g_blocksum[tid] : 0;
    __syncthreads();
    for (int o = 1; o < 256; o <<= 1) {
        int t = (tid >= o) ? sm[tid - o] : 0;
        __syncthreads();
        sm[tid] += t;
        __syncthreads();
    }
    if (tid < nb) g_blocksum[tid] = tid ? sm[tid - 1] : 0;
}

__global__ void k_scan3(int* __restrict__ out, int n) {
    int i = blockIdx.x * blockDim.x + threadIdx.x;
    if (i < n) out[i] += g_blocksum[i >> 10];
}

__global__ void k_fill(const int* __restrict__ ei) {
    int i = blockIdx.x * blockDim.x + threadIdx.x;
    if (i >= NE_TOT) return;
    int s, d;
    decode_edge(ei, i, s, d);
    if (s == d) return;
    int pos = g_rowptr[d] + atomicAdd(&g_cursor[d], 1);
    g_csr_src[pos] = s;
    g_csr_w[pos] = g_dinv[s] * g_dinv[d];
}

// OUT: 0 = skip fp32 store; 1 = store rows < N_NODES only; 2 = store all
template<int WS, int OUT>
__global__ void k_aggregate(const float* __restrict__ X, const float* __restrict__ bias,
                            float* __restrict__ Out) {
    int w = (blockIdx.x * blockDim.x + threadIdx.x) >> 5;
    if (w >= N_TOT) return;
    int lane = threadIdx.x & 31;
    int start = g_rowptr[w];
    int len = g_deg[w];
    float dv = g_dinv[w];
    float ws = dv * dv;
    const float4* xd = (const float4*)(X + (size_t)w * 256);
    float4 sa = xd[lane * 2], sb = xd[lane * 2 + 1];
    float acc0 = ws * sa.x, acc1 = ws * sa.y, acc2 = ws * sa.z, acc3 = ws * sa.w;
    float acc4 = ws * sb.x, acc5 = ws * sb.y, acc6 = ws * sb.z, acc7 = ws * sb.w;
    int j = 0;
    for (; j + 4 <= len; j += 4) {
        int s0 = g_csr_src[start + j];
        int s1 = g_csr_src[start + j + 1];
        int s2 = g_csr_src[start + j + 2];
        int s3 = g_csr_src[start + j + 3];
        float w0 = g_csr_w[start + j];
        float w1 = g_csr_w[start + j + 1];
        float w2 = g_csr_w[start + j + 2];
        float w3 = g_csr_w[start + j + 3];
        const float4* x0 = (const float4*)(X + (size_t)s0 * 256);
        const float4* x1 = (const float4*)(X + (size_t)s1 * 256);
        const float4* x2 = (const float4*)(X + (size_t)s2 * 256);
        const float4* x3 = (const float4*)(X + (size_t)s3 * 256);
        float4 u0 = x0[lane * 2], v0 = x0[lane * 2 + 1];
        float4 u1 = x1[lane * 2], v1 = x1[lane * 2 + 1];
        float4 u2 = x2[lane * 2], v2 = x2[lane * 2 + 1];
        float4 u3 = x3[lane * 2], v3 = x3[lane * 2 + 1];
        acc0 = fmaf(w0, u0.x, acc0); acc1 = fmaf(w0, u0.y, acc1);
        acc2 = fmaf(w0, u0.z, acc2); acc3 = fmaf(w0, u0.w, acc3);
        acc4 = fmaf(w0, v0.x, acc4); acc5 = fmaf(w0, v0.y, acc5);
        acc6 = fmaf(w0, v0.z, acc6); acc7 = fmaf(w0, v0.w, acc7);
        acc0 = fmaf(w1, u1.x, acc0); acc1 = fmaf(w1, u1.y, acc1);
        acc2 = fmaf(w1, u1.z, acc2); acc3 = fmaf(w1, u1.w, acc3);
        acc4 = fmaf(w1, v1.x, acc4); acc5 = fmaf(w1, v1.y, acc5);
        acc6 = fmaf(w1, v1.z, acc6); acc7 = fmaf(w1, v1.w, acc7);
        acc0 = fmaf(w2, u2.x, acc0); acc1 = fmaf(w2, u2.y, acc1);
        acc2 = fmaf(w2, u2.z, acc2); acc3 = fmaf(w2, u2.w, acc3);
        acc4 = fmaf(w2, v2.x, acc4); acc5 = fmaf(w2, v2.y, acc5);
        acc6 = fmaf(w2, v2.z, acc6); acc7 = fmaf(w2, v2.w, acc7);
        acc0 = fmaf(w3, u3.x, acc0); acc1 = fmaf(w3, u3.y, acc1);
        acc2 = fmaf(w3, u3.z, acc2); acc3 = fmaf(w3, u3.w, acc3);
        acc4 = fmaf(w3, v3.x, acc4); acc5 = fmaf(w3, v3.y, acc5);
        acc6 = fmaf(w3, v3.z, acc6); acc7 = fmaf(w3, v3.w, acc7);
    }
    for (; j < len; j++) {
        int s0 = g_csr_src[start + j];
        float w0 = g_csr_w[start + j];
        const float4* x0 = (const float4*)(X + (size_t)s0 * 256);
        float4 u0 = x0[lane * 2], v0 = x0[lane * 2 + 1];
        acc0 = fmaf(w0, u0.x, acc0); acc1 = fmaf(w0, u0.y, acc1);
        acc2 = fmaf(w0, u0.z, acc2); acc3 = fmaf(w0, u0.w, acc3);
        acc4 = fmaf(w0, v0.x, acc4); acc5 = fmaf(w0, v0.y, acc5);
        acc6 = fmaf(w0, v0.z, acc6); acc7 = fmaf(w0, v0.w, acc7);
    }
    const float4* b4 = (const float4*)bias;
    float4 bb0 = b4[lane * 2], bb1 = b4[lane * 2 + 1];
    float o[8] = {acc0 + bb0.x, acc1 + bb0.y, acc2 + bb0.z, acc3 + bb0.w,
                  acc4 + bb1.x, acc5 + bb1.y, acc6 + bb1.z, acc7 + bb1.w};
    if (OUT == 2 || (OUT == 1 && w < N_NODES)) {
        float4* od = (float4*)(Out + (size_t)w * 256);
        od[lane * 2] = make_float4(o[0], o[1], o[2], o[3]);
        od[lane * 2 + 1] = make_float4(o[4], o[5], o[6], o[7]);
    }
    if (WS) {
        uint32_t hw[4], lw[4];
#pragma unroll
        for (int q = 0; q < 4; q++) {
            __half h0, l0, h1, l1;
            split2(fmaxf(o[q * 2], 0.f), h0, l0);
            split2(fmaxf(o[q * 2 + 1], 0.f), h1, l1);
            hw[q] = hpack2(h0, h1); lw[q] = hpack2(l0, l1);
        }
        size_t so = (size_t)w * 256 + lane * 8;
        *(uint4*)(g_Ahi + so) = make_uint4(hw[0], hw[1], hw[2], hw[3]);
        *(uint4*)(g_Alo + so) = make_uint4(lw[0], lw[1], lw[2], lw[3]);
    }
}

// hyperedge features + H output, reading classes directly
__global__ void k_hyperedge(float* __restrict__ Hout, float* __restrict__ hf) {
    extern __shared__ float acc[];
    int tid = threadIdx.x;
    for (int i = tid; i < 16384; i += 256) acc[i] = 0.f;
    __syncthreads();
    int warp = tid >> 5, lane = tid & 31;
    for (int n = blockIdx.x * 8 + warp; n < N_NODES; n += gridDim.x * 8) {
        int c0 = __ldg(g_cls + n);
        int c1 = __ldg(g_cls + N_NODES + n);
        int c2 = __ldg(g_cls + 2 * N_NODES + n);
        int c3 = __ldg(g_cls + 3 * N_NODES + n);
        int c4 = __ldg(g_cls + 4 * N_NODES + n);
        int h0 = (c0 == lane) + (c1 == lane) + (c2 == lane) + (c3 == lane) + (c4 == lane);
        int l2 = lane + 32;
        int h1 = (c0 == l2) + (c1 == l2) + (c2 == l2) + (c3 == l2) + (c4 == l2);
        Hout[(size_t)n * 64 + lane] = (float)h0;
        Hout[(size_t)n * 64 + lane + 32] = (float)h1;
        unsigned m0 = __ballot_sync(0xffffffffu, h0 > 0);
        unsigned m1 = __ballot_sync(0xffffffffu, h1 > 0);
        const float4* xr = (const float4*)(g_B + (size_t)n * 256);
        float4 a = xr[lane * 2], b = xr[lane * 2 + 1];
        unsigned mm = m0;
        while (mm) {
            int c = __ffs(mm) - 1; mm &= mm - 1;
            float* p = acc + c * 256 + lane * 8;
            atomicAdd(p + 0, a.x); atomicAdd(p + 1, a.y); atomicAdd(p + 2, a.z); atomicAdd(p + 3, a.w);
            atomicAdd(p + 4, b.x); atomicAdd(p + 5, b.y); atomicAdd(p + 6, b.z); atomicAdd(p + 7, b.w);
        }
        mm = m1;
        while (mm) {
            int c = (__ffs(mm) - 1) + 32; mm &= mm - 1;
            float* p = acc + c * 256 + lane * 8;
            atomicAdd(p + 0, a.x); atomicAdd(p + 1, a.y); atomicAdd(p + 2, a.z); atomicAdd(p + 3, a.w);
            atomicAdd(p + 4, b.x); atomicAdd(p + 5, b.y); atomicAdd(p + 6, b.z); atomicAdd(p + 7, b.w);
        }
    }
    __syncthreads();
    for (int i = tid; i < 16384; i += 256) atomicAdd(&hf[i], acc[i]);
}

// ---------------- launch ----------------
extern "C" void kernel_launch(void* const* d_in, const int* in_sizes, int n_in,
                              void* d_out, int out_size) {
    const int*   ei       = (const int*)d_in[0];
    const float* features = (const float*)d_in[1];
    const float* lin_w    = (const float*)d_in[2];
    const float* lin_b    = (const float*)d_in[3];
    const float* gcn0_w   = (const float*)d_in[4];
    const float* gcn0_b   = (const float*)d_in[5];
    const float* gcn1_w   = (const float*)d_in[6];
    const float* gcn1_b   = (const float*)d_in[7];
    const float* lin1_w   = (const float*)d_in[8];
    const float* lin1_b   = (const float*)d_in[9];

    float* out      = (float*)d_out;
    float* H_out    = out;
    float* hf_out   = out + (size_t)N_NODES * NS;
    float* dots_out = hf_out + NS * D;

    float *X, *B, *ZB;
    int *DEG, *ROWPTR, *ODEG, *OROW;
    __half *AH, *AL, *AH2, *AL2, *WH, *WL;
    cudaGetSymbolAddress((void**)&X,  g_X);
    cudaGetSymbolAddress((void**)&B,  g_B);
    cudaGetSymbolAddress((void**)&ZB, g_zerobias);
    cudaGetSymbolAddress((void**)&DEG, g_deg);
    cudaGetSymbolAddress((void**)&ROWPTR, g_rowptr);
    cudaGetSymbolAddress((void**)&ODEG, g_odeg);
    cudaGetSymbolAddress((void**)&OROW, g_orow);
    cudaGetSymbolAddress((void**)&AH, g_Ahi);
    cudaGetSymbolAddress((void**)&AL, g_Alo);
    cudaGetSymbolAddress((void**)&AH2, g_Ahi2);
    cudaGetSymbolAddress((void**)&AL2, g_Alo2);
    cudaGetSymbolAddress((void**)&WH, g_Whi);
    cudaGetSymbolAddress((void**)&WL, g_Wlo);

    cudaFuncSetAttribute(k_hyperedge,  cudaFuncAttributeMaxDynamicSharedMemorySize, 65536);
    cudaFuncSetAttribute(k_mmagemm<0>, cudaFuncAttributeMaxDynamicSharedMemorySize, SMG_BYTES);
    cudaFuncSetAttribute(k_mmagemm<1>, cudaFuncAttributeMaxDynamicSharedMemorySize, SMG_BYTES);
    cudaFuncSetAttribute(k_mmagemm64<0>, cudaFuncAttributeMaxDynamicSharedMemorySize, SM64_BYTES);
    cudaFuncSetAttribute(k_mmagemm64<1>, cudaFuncAttributeMaxDynamicSharedMemorySize, SM64_BYTES);

    const int nb_tot  = (N_TOT + SCAN_BLK - 1) / SCAN_BLK;
    const int nb_node = (N_NODES + SCAN_BLK - 1) / SCAN_BLK;

    // weight splits; feature split (also zeroes invn/deg/cursor/odeg/ocur)
    k_wsplit<<<dim3(256, 4), 256>>>(lin_w, 0, 256, 65536);
    k_wsplit<<<dim3(256, 1), 256>>>(gcn0_w, 4, 256, 0);
    k_wsplit<<<dim3(256, 1), 256>>>(gcn1_w, 5, 256, 0);
    k_wsplit<<<dim3(64, 1), 256>>>(lin1_w, 6, 64, 0);
    k_split_both<<<(N_NODES * 64 + 255) / 256, 256>>>((const float4*)features, N_NODES * 64);

    // heads GEMM on raw splits; epilogue writes split buffers + sumsq atomics
    k_mmagemm<1><<<dim3(2, (N_NODES + 127) / 128, 4), 256, SMG_BYTES>>>(
        AH2, AL2, WH, WL, lin_b, X /*unused*/, N_NODES, 65536, 0, 256);

    // original-edge CSR
    k_ocount<<<(N_EDGES + 255) / 256, 256>>>(ei);
    k_scan1<0><<<nb_node, 256>>>(ODEG, OROW, N_NODES);
    k_scan2<<<1, 256>>>(nb_node);
    k_scan3<<<(N_NODES + 255) / 256, 256>>>(OROW, N_NODES);
    k_ofill<<<(N_EDGES + 255) / 256, 256>>>(ei);

    // per-edge best replica (invn rsqrt inline)
    k_edge_sim2<<<(N_NODES * 32 + 255) / 256, 256>>>(ei);

    // augmented-graph CSR (dinv fused into scan1)
    k_count<<<(NE_TOT + 255) / 256, 256>>>(ei);
    k_scan1<1><<<nb_tot, 256>>>(DEG, ROWPTR, N_TOT);
    k_scan2<<<1, 256>>>(nb_tot);
    k_scan3<<<(N_TOT + 255) / 256, 256>>>(ROWPTR, N_TOT);
    k_fill<<<(NE_TOT + 255) / 256, 256>>>(ei);

    // GCN layer 0 (aggregate fp32 output dead -> OUT=0)
    k_mmagemm<0><<<dim3(2, (N_TOT + 127) / 128, 1), 256, SMG_BYTES>>>(
        AH, AL, WH + 4 * 65536, WL + 4 * 65536, ZB, X, N_TOT, 0, 0, 0);
    k_aggregate<1, 0><<<(N_TOT * 32 + 255) / 256, 256>>>(X, gcn0_b, B);

    // GCN layer 1 (fp32 out only base rows -> OUT=1)
    k_mmagemm<0><<<dim3(2, (N_TOT + 127) / 128, 1), 256, SMG_BYTES>>>(
        AH, AL, WH + 5 * 65536, WL + 5 * 65536, ZB, X, N_TOT, 0, 0, 0);
    k_aggregate<1, 1><<<(N_TOT * 32 + 255) / 256, 256>>>(X, gcn1_b, B);

    // logits mma with fused argmax -> g_cls
    k_mmagemm64<0><<<(N_TOT + 127) / 128, 256, SM64_BYTES>>>(
        AH, AL, WH + 6 * 65536, WL + 6 * 65536, lin1_b, X, N_TOT, 0.f);

    // hyperedge features + H output (classes read directly); split hf to slot 7
    cudaMemsetAsync(hf_out, 0, (size_t)NS * D * sizeof(float));
    k_hyperedge<<<160, 256, 65536>>>(H_out, hf_out);
    k_wsplit_dir<<<64, 256>>>(hf_out, 7, NS * D);

    // dots via mma on raw splits (buf2)
    k_mmagemm64<1><<<(N_TOT + 127) / 128, 256, SM64_BYTES>>>(
        AH2, AL2, WH + 7 * 65536, WL + 7 * 65536, ZB, dots_out, N_TOT, 0.0625f);
}

// round 17
// speedup vs baseline: 1.0997x; 1.0099x over previous
#include <cuda_runtime.h>
#include <cuda_fp16.h>
#include <cstdint>

#define N_NODES 50000
#define N_EDGES 800000
#define D 256
#define T_REP 4
#define NS 64
#define N_TOT (5 * N_NODES)                 /* 250000 */
#define NE_TOT (2 * N_EDGES + 3 * N_NODES)  /* 1750000 */
#define SCAN_BLK 1024
#define NPAD 250112

typedef unsigned long long u64;

__device__ __forceinline__ uint32_t smem_to_u32(const void* p) {
    uint32_t a;
    asm("{ .reg .u64 t; cvta.to.shared.u64 t, %1; cvt.u32.u64 %0, t; }" : "=r"(a) : "l"(p));
    return a;
}

#define LDMATRIX_X4(r0, r1, r2, r3, addr) \
    asm volatile("ldmatrix.sync.aligned.m8n8.x4.shared.b16 {%0,%1,%2,%3}, [%4];" \
                 : "=r"(r0), "=r"(r1), "=r"(r2), "=r"(r3) : "r"(addr))

#define MMAF16(c, a, b0, b1) \
    asm volatile("mma.sync.aligned.m16n8k16.row.col.f32.f16.f16.f32 " \
                 "{%0,%1,%2,%3}, {%4,%5,%6,%7}, {%8,%9}, {%0,%1,%2,%3};" \
                 : "+f"((c)[0]), "+f"((c)[1]), "+f"((c)[2]), "+f"((c)[3]) \
                 : "r"((a)[0]), "r"((a)[1]), "r"((a)[2]), "r"((a)[3]), "r"(b0), "r"(b1))

#define CP16(dst, src, sz) \
    asm volatile("cp.async.cg.shared.global [%0], [%1], 16, %2;" \
                 :: "r"(dst), "l"(src), "r"(sz))
#define CP_COMMIT() asm volatile("cp.async.commit_group;" ::: "memory")
#define CP_WAIT0()  asm volatile("cp.async.wait_group 0;" ::: "memory")

__device__ __forceinline__ void split2(float x, __half& h, __half& l) {
    h = __float2half_rn(x);
    l = __float2half_rn(x - __half2float(h));
}
__device__ __forceinline__ uint32_t hpack2(__half a, __half b) {
    return (uint32_t)__half_as_ushort(a) | ((uint32_t)__half_as_ushort(b) << 16);
}

// ---------------- scratch (device globals) ----------------
__device__ float g_X[(size_t)N_TOT * D];
__device__ float g_B[(size_t)N_TOT * D];
__device__ float g_invn[T_REP * N_NODES];   // sumsq accum (rsqrt applied in edge_sim)
__device__ int   g_deg[N_TOT];              // in-edge count (no self loop)
__device__ float g_dinv[N_TOT];
__device__ int   g_best[N_EDGES];
__device__ int   g_cls[N_TOT];
__device__ float g_zerobias[D];
__device__ int   g_rowptr[N_TOT];
__device__ int   g_blocksum[256];
__device__ int   g_cursor[N_TOT];
__device__ int   g_csr_src[NE_TOT];
__device__ int   g_odeg[N_NODES];
__device__ int   g_orow[N_NODES];
__device__ int   g_ocur[N_NODES];
__device__ int   g_oedge[N_EDGES];
// fp16 split buffers: buf1 = GEMM activations (relu), buf2 = raw values
__device__ __half g_Ahi[(size_t)NPAD * D];
__device__ __half g_Alo[(size_t)NPAD * D];
__device__ __half g_Ahi2[(size_t)NPAD * D];
__device__ __half g_Alo2[(size_t)NPAD * D];
__device__ __half g_Whi[8 * 65536];
__device__ __half g_Wlo[8 * 65536];

// reconstruct 8 floats (lane's 16B slice) from hi/lo split row
__device__ __forceinline__ void rec8(const __half* hi, const __half* lo, int lane,
                                     float4& a, float4& b) {
    uint4 h = __ldg((const uint4*)hi + lane);
    uint4 l = __ldg((const uint4*)lo + lane);
    float2 f0 = __half22float2(*(__half2*)&h.x), g0 = __half22float2(*(__half2*)&l.x);
    float2 f1 = __half22float2(*(__half2*)&h.y), g1 = __half22float2(*(__half2*)&l.y);
    float2 f2 = __half22float2(*(__half2*)&h.z), g2 = __half22float2(*(__half2*)&l.z);
    float2 f3 = __half22float2(*(__half2*)&h.w), g3 = __half22float2(*(__half2*)&l.w);
    a = make_float4(f0.x + g0.x, f0.y + g0.y, f1.x + g1.x, f1.y + g1.y);
    b = make_float4(f2.x + g2.x, f2.y + g2.y, f3.x + g3.x, f3.y + g3.y);
}

// ---------------- small kernels ----------------

// split relu(X)->buf1, raw X->buf2; zero invn/deg/cursor/odeg/ocur scratch
__global__ void k_split_both(const float4* __restrict__ X, int n4) {
    int i = blockIdx.x * blockDim.x + threadIdx.x;
    if (i >= n4) return;
    if (i < T_REP * N_NODES) g_invn[i] = 0.f;
    if (i < N_TOT) { g_deg[i] = 0; g_cursor[i] = 0; }
    if (i < N_NODES) { g_odeg[i] = 0; g_ocur[i] = 0; }
    float4 v = X[i];
    __half h0,l0,h1,l1,h2,l2,h3,l3;
    split2(v.x,h0,l0); split2(v.y,h1,l1); split2(v.z,h2,l2); split2(v.w,h3,l3);
    ((uint2*)g_Ahi2)[i] = make_uint2(hpack2(h0,h1), hpack2(h2,h3));
    ((uint2*)g_Alo2)[i] = make_uint2(hpack2(l0,l1), hpack2(l2,l3));
    float x0 = fmaxf(v.x, 0.f), x1 = fmaxf(v.y, 0.f);
    float x2 = fmaxf(v.z, 0.f), x3 = fmaxf(v.w, 0.f);
    split2(x0,h0,l0); split2(x1,h1,l1); split2(x2,h2,l2); split2(x3,h3,l3);
    ((uint2*)g_Ahi)[i] = make_uint2(hpack2(h0,h1), hpack2(h2,h3));
    ((uint2*)g_Alo)[i] = make_uint2(hpack2(l0,l1), hpack2(l2,l3));
}

// split + transpose a [256 x ncols] weight into slot widxBase + blockIdx.y
__global__ void k_wsplit(const float* __restrict__ W, int widxBase, int ncols, int wstride) {
    int widx = widxBase + blockIdx.y;
    const float* Wz = W + (size_t)blockIdx.y * wstride;
    int i = blockIdx.x * 256 + threadIdx.x;
    int n = i >> 8, k = i & 255;
    float x = Wz[k * ncols + n];
    __half h, l;
    split2(x, h, l);
    g_Whi[widx * 65536 + i] = h;
    g_Wlo[widx * 65536 + i] = l;
}

__global__ void k_wsplit_dir(const float* __restrict__ src, int widx, int nelem) {
    int i = blockIdx.x * 256 + threadIdx.x;
    if (i >= nelem) return;
    __half h, l;
    split2(src[i], h, l);
    g_Whi[widx * 65536 + i] = h;
    g_Wlo[widx * 65536 + i] = l;
}

// ---- fp16x3 GEMM (N=256) ----
// WS=0: C = A@W + bias. WS=1 (heads): splits to buf1/buf2 rows N..5N + sumsq atomics.
#define ASTRIDE 72
#define SMBUF (128 * ASTRIDE)
#define SMG_BYTES (4 * SMBUF * 2)
template<int WS>
__global__ __launch_bounds__(256, 2) void k_mmagemm(
    const __half* Ahi, const __half* Alo,
    const __half* __restrict__ Whi, const __half* __restrict__ Wlo,
    const float* __restrict__ bias, float* __restrict__ C,
    int M, int wz, int cz, int bzs)
{
    extern __shared__ __half smh[];
    __half* sAh = smh;
    __half* sAl = smh + SMBUF;
    __half* sBh = smh + 2 * SMBUF;
    __half* sBl = smh + 3 * SMBUF;

    const int tid = threadIdx.x;
    const int warp = tid >> 5, lane = tid & 31;
    const int wm = warp & 1, wn = warp >> 1;
    const int z = blockIdx.z;
    const int rBase = blockIdx.y << 7;
    const int colBase = blockIdx.x << 7;

    const __half* Wh = Whi + (size_t)z * wz;
    const __half* Wl = Wlo + (size_t)z * wz;

    float acc[4][4][4];
#pragma unroll
    for (int i = 0; i < 4; i++)
#pragma unroll
        for (int j = 0; j < 4; j++)
#pragma unroll
            for (int q = 0; q < 4; q++) acc[i][j][q] = 0.f;

    const uint32_t uAh = smem_to_u32(sAh);
    const uint32_t uAl = smem_to_u32(sAl);
    const uint32_t uBh = smem_to_u32(sBh);
    const uint32_t uBl = smem_to_u32(sBl);
    const int a_row_l = lane & 15;
    const int a_kh = (lane >> 4) << 3;
    const int b_n_off = (lane & 7) + ((lane >> 4) << 3);
    const int b_k_off = ((lane >> 3) & 1) << 3;

#pragma unroll 1
    for (int c = 0; c < 4; c++) {
#pragma unroll
        for (int s = 0; s < 2; s++) {
            const __half* ap = s ? Alo : Ahi;
            uint32_t ud = s ? uAl : uAh;
#pragma unroll
            for (int j = 0; j < 4; j++) {
                int i = tid + j * 256;
                int row = i >> 3, seg = i & 7;
                int gr = rBase + row;
                int grc = gr < M ? gr : 0;
                unsigned sz = gr < M ? 16u : 0u;
                CP16(ud + (uint32_t)(row * ASTRIDE + seg * 8) * 2,
                     ap + (size_t)grc * 256 + c * 64 + seg * 8, sz);
            }
            const __half* wp = s ? Wl : Wh;
            uint32_t wd = s ? uBl : uBh;
#pragma unroll
            for (int j = 0; j < 4; j++) {
                int i = tid + j * 256;
                int row = i >> 3, seg = i & 7;
                CP16(wd + (uint32_t)(row * ASTRIDE + seg * 8) * 2,
                     wp + (size_t)(colBase + row) * 256 + c * 64 + seg * 8, 16u);
            }
        }
        CP_COMMIT();
        CP_WAIT0();
        __syncthreads();
#pragma unroll
        for (int k = 0; k < 4; k++) {
            const int k0 = k << 4;
            const uint32_t aoff = (uint32_t)(((wm << 6) + a_row_l) * ASTRIDE + k0 + a_kh) * 2;
            const uint32_t boff0 = (uint32_t)(((wn << 5) + b_n_off) * ASTRIDE + k0 + b_k_off) * 2;
            const uint32_t boff1 = boff0 + (uint32_t)(16 * ASTRIDE) * 2;
            uint32_t ah[4][4], al[4][4], bh[2][4], bl[2][4];
#pragma unroll
            for (int mi = 0; mi < 4; mi++) {
                LDMATRIX_X4(ah[mi][0], ah[mi][1], ah[mi][2], ah[mi][3],
                            uAh + aoff + (uint32_t)((mi << 4) * ASTRIDE) * 2);
                LDMATRIX_X4(al[mi][0], al[mi][1], al[mi][2], al[mi][3],
                            uAl + aoff + (uint32_t)((mi << 4) * ASTRIDE) * 2);
            }
            LDMATRIX_X4(bh[0][0], bh[0][1], bh[0][2], bh[0][3], uBh + boff0);
            LDMATRIX_X4(bh[1][0], bh[1][1], bh[1][2], bh[1][3], uBh + boff1);
            LDMATRIX_X4(bl[0][0], bl[0][1], bl[0][2], bl[0][3], uBl + boff0);
            LDMATRIX_X4(bl[1][0], bl[1][1], bl[1][2], bl[1][3], uBl + boff1);
#pragma unroll
            for (int mi = 0; mi < 4; mi++)
#pragma unroll
                for (int ni = 0; ni < 4; ni++) {
                    uint32_t b0h = bh[ni >> 1][(ni & 1) * 2], b1h = bh[ni >> 1][(ni & 1) * 2 + 1];
                    uint32_t b0l = bl[ni >> 1][(ni & 1) * 2], b1l = bl[ni >> 1][(ni & 1) * 2 + 1];
                    MMAF16(acc[mi][ni], ah[mi], b0h, b1h);
                    MMAF16(acc[mi][ni], ah[mi], b0l, b1l);
                    MMAF16(acc[mi][ni], al[mi], b0h, b1h);
                }
        }
        __syncthreads();
    }

    const float* bp = bias + (size_t)z * bzs;
    float* Cz = C + (size_t)z * cz;
#pragma unroll
    for (int mi = 0; mi < 4; mi++) {
#pragma unroll
        for (int hf2 = 0; hf2 < 2; hf2++) {
            int gr = rBase + (wm << 6) + (mi << 4) + (lane >> 2) + hf2 * 8;
            if (WS == 0) {
                if (gr >= M) continue;
#pragma unroll
                for (int ni = 0; ni < 4; ni++) {
                    int col = colBase + (wn << 5) + (ni << 3) + (lane & 3) * 2;
                    float o0 = acc[mi][ni][hf2 * 2] + bp[col];
                    float o1 = acc[mi][ni][hf2 * 2 + 1] + bp[col + 1];
                    *(float2*)&Cz[(size_t)gr * 256 + col] = make_float2(o0, o1);
                }
            } else {
                float ss = 0.f;
                if (gr < M) {
#pragma unroll
                    for (int ni = 0; ni < 4; ni++) {
                        int col = colBase + (wn << 5) + (ni << 3) + (lane & 3) * 2;
                        float o0 = acc[mi][ni][hf2 * 2] + bp[col];
                        float o1 = acc[mi][ni][hf2 * 2 + 1] + bp[col + 1];
                        ss += o0 * o0 + o1 * o1;
                        size_t so = (size_t)(N_NODES + z * N_NODES + gr) * 256 + col;
                        __half h0, l0, h1, l1;
                        split2(fmaxf(o0, 0.f), h0, l0);
                        split2(fmaxf(o1, 0.f), h1, l1);
                        *(uint32_t*)(g_Ahi + so) = hpack2(h0, h1);
                        *(uint32_t*)(g_Alo + so) = hpack2(l0, l1);
                        split2(o0, h0, l0);
                        split2(o1, h1, l1);
                        *(uint32_t*)(g_Ahi2 + so) = hpack2(h0, h1);
                        *(uint32_t*)(g_Alo2 + so) = hpack2(l0, l1);
                    }
                }
                ss += __shfl_xor_sync(0xffffffffu, ss, 1);
                ss += __shfl_xor_sync(0xffffffffu, ss, 2);
                if ((lane & 3) == 0 && gr < M)
                    atomicAdd(&g_invn[z * N_NODES + gr], ss);
            }
        }
    }
}

// ---- fp16x3 GEMM (N=64): MODE 0 logits+fused argmax; MODE 1 *scale ----
#define SM64_A (128 * ASTRIDE)
#define SM64_B (64 * ASTRIDE)
#define SM64_BYTES ((2 * SM64_A + 2 * SM64_B) * 2)
template<int MODE>
__global__ __launch_bounds__(256, 2) void k_mmagemm64(
    const __half* Ahi, const __half* Alo,
    const __half* __restrict__ Wh, const __half* __restrict__ Wl,
    const float* __restrict__ bias, float* __restrict__ C, int M, float scale)
{
    extern __shared__ __half smh[];
    __half* sAh = smh;
    __half* sAl = smh + SM64_A;
    __half* sBh = smh + 2 * SM64_A;
    __half* sBl = smh + 2 * SM64_A + SM64_B;
    __shared__ float sval[128];
    __shared__ int   sidx[128];

    const int tid = threadIdx.x;
    const int warp = tid >> 5, lane = tid & 31;
    const int wm = warp >> 1, wn = warp & 1;
    const int rBase = blockIdx.x << 7;

    float acc[2][4][4];
#pragma unroll
    for (int i = 0; i < 2; i++)
#pragma unroll
        for (int j = 0; j < 4; j++)
#pragma unroll
            for (int q = 0; q < 4; q++) acc[i][j][q] = 0.f;

    const uint32_t uAh = smem_to_u32(sAh);
    const uint32_t uAl = smem_to_u32(sAl);
    const uint32_t uBh = smem_to_u32(sBh);
    const uint32_t uBl = smem_to_u32(sBl);
    const int a_row_l = lane & 15;
    const int a_kh = (lane >> 4) << 3;
    const int b_n_off = (lane & 7) + ((lane >> 4) << 3);
    const int b_k_off = ((lane >> 3) & 1) << 3;

#pragma unroll 1
    for (int c = 0; c < 4; c++) {
#pragma unroll
        for (int s = 0; s < 2; s++) {
            const __half* ap = s ? Alo : Ahi;
            uint32_t ud = s ? uAl : uAh;
#pragma unroll
            for (int j = 0; j < 4; j++) {
                int i = tid + j * 256;
                int row = i >> 3, seg = i & 7;
                int gr = rBase + row;
                int grc = gr < M ? gr : 0;
                unsigned sz = gr < M ? 16u : 0u;
                CP16(ud + (uint32_t)(row * ASTRIDE + seg * 8) * 2,
                     ap + (size_t)grc * 256 + c * 64 + seg * 8, sz);
            }
            const __half* wp = s ? Wl : Wh;
            uint32_t wd = s ? uBl : uBh;
#pragma unroll
            for (int j = 0; j < 2; j++) {
                int i = tid + j * 256;
                int row = i >> 3, seg = i & 7;
                CP16(wd + (uint32_t)(row * ASTRIDE + seg * 8) * 2,
                     wp + (size_t)row * 256 + c * 64 + seg * 8, 16u);
            }
        }
        CP_COMMIT();
        CP_WAIT0();
        __syncthreads();
#pragma unroll
        for (int k = 0; k < 4; k++) {
            const int k0 = k << 4;
            const uint32_t aoff = (uint32_t)(((wm << 5) + a_row_l) * ASTRIDE + k0 + a_kh) * 2;
            const uint32_t boff0 = (uint32_t)(((wn << 5) + b_n_off) * ASTRIDE + k0 + b_k_off) * 2;
            const uint32_t boff1 = boff0 + (uint32_t)(16 * ASTRIDE) * 2;
            uint32_t ah[2][4], al[2][4], bh[2][4], bl[2][4];
#pragma unroll
            for (int mi = 0; mi < 2; mi++) {
                LDMATRIX_X4(ah[mi][0], ah[mi][1], ah[mi][2], ah[mi][3],
                            uAh + aoff + (uint32_t)((mi << 4) * ASTRIDE) * 2);
                LDMATRIX_X4(al[mi][0], al[mi][1], al[mi][2], al[mi][3],
                            uAl + aoff + (uint32_t)((mi << 4) * ASTRIDE) * 2);
            }
            LDMATRIX_X4(bh[0][0], bh[0][1], bh[0][2], bh[0][3], uBh + boff0);
            LDMATRIX_X4(bh[1][0], bh[1][1], bh[1][2], bh[1][3], uBh + boff1);
            LDMATRIX_X4(bl[0][0], bl[0][1], bl[0][2], bl[0][3], uBl + boff0);
            LDMATRIX_X4(bl[1][0], bl[1][1], bl[1][2], bl[1][3], uBl + boff1);
#pragma unroll
            for (int mi = 0; mi < 2; mi++)
#pragma unroll
                for (int ni = 0; ni < 4; ni++) {
                    uint32_t b0h = bh[ni >> 1][(ni & 1) * 2], b1h = bh[ni >> 1][(ni & 1) * 2 + 1];
                    uint32_t b0l = bl[ni >> 1][(ni & 1) * 2], b1l = bl[ni >> 1][(ni & 1) * 2 + 1];
                    MMAF16(acc[mi][ni], ah[mi], b0h, b1h);
                    MMAF16(acc[mi][ni], ah[mi], b0l, b1l);
                    MMAF16(acc[mi][ni], al[mi], b0h, b1h);
                }
        }
        __syncthreads();
    }

    if (MODE == 1) {
#pragma unroll
        for (int mi = 0; mi < 2; mi++)
#pragma unroll
            for (int hf2 = 0; hf2 < 2; hf2++) {
                int gr = rBase + (wm << 5) + (mi << 4) + (lane >> 2) + hf2 * 8;
                if (gr >= M) continue;
#pragma unroll
                for (int ni = 0; ni < 4; ni++) {
                    int col = (wn << 5) + (ni << 3) + (lane & 3) * 2;
                    float o0 = acc[mi][ni][hf2 * 2] * scale;
                    float o1 = acc[mi][ni][hf2 * 2 + 1] * scale;
                    *(float2*)&C[(size_t)gr * 64 + col] = make_float2(o0, o1);
                }
            }
    } else {
        float rv[4]; int ridx[4];
#pragma unroll
        for (int mi = 0; mi < 2; mi++)
#pragma unroll
            for (int hf2 = 0; hf2 < 2; hf2++) {
                float v = -3.4e38f; int idx = 0;
#pragma unroll
                for (int ni = 0; ni < 4; ni++) {
                    int col = (wn << 5) + (ni << 3) + (lane & 3) * 2;
                    float o0 = acc[mi][ni][hf2 * 2] + bias[col];
                    float o1 = acc[mi][ni][hf2 * 2 + 1] + bias[col + 1];
                    if (o0 > v) { v = o0; idx = col; }
                    if (o1 > v) { v = o1; idx = col + 1; }
                }
#pragma unroll
                for (int o = 1; o <= 2; o <<= 1) {
                    float ov = __shfl_xor_sync(0xffffffffu, v, o);
                    int oi = __shfl_xor_sync(0xffffffffu, idx, o);
                    if (ov > v || (ov == v && oi < idx)) { v = ov; idx = oi; }
                }
                int lr = (wm << 5) + (mi << 4) + hf2 * 8 + (lane >> 2);
                if (wn == 0 && (lane & 3) == 0) { sval[lr] = v; sidx[lr] = idx; }
                rv[mi * 2 + hf2] = v; ridx[mi * 2 + hf2] = idx;
            }
        __syncthreads();
        if (wn == 1 && (lane & 3) == 0) {
#pragma unroll
            for (int mi = 0; mi < 2; mi++)
#pragma unroll
                for (int hf2 = 0; hf2 < 2; hf2++) {
                    int lr = (wm << 5) + (mi << 4) + hf2 * 8 + (lane >> 2);
                    int gr = rBase + lr;
                    if (gr >= M) continue;
                    float v0 = sval[lr]; int i0 = sidx[lr];
                    float v1 = rv[mi * 2 + hf2]; int i1 = ridx[mi * 2 + hf2];
                    g_cls[gr] = (v1 > v0) ? i1 : i0;
                }
        }
    }
}

__device__ __forceinline__ float dot8(float4 f0, float4 f1, float4 a, float4 b) {
    return f0.x * a.x + f0.y * a.y + f0.z * a.z + f0.w * a.w +
           f1.x * b.x + f1.y * b.y + f1.z * b.z + f1.w * b.w;
}

__global__ void k_ocount(const int* __restrict__ ei) {
    int i = blockIdx.x * blockDim.x + threadIdx.x;
    if (i < N_EDGES) atomicAdd(&g_odeg[ei[N_EDGES + i]], 1);
}

__global__ void k_ofill(const int* __restrict__ ei) {
    int i = blockIdx.x * blockDim.x + threadIdx.x;
    if (i >= N_EDGES) return;
    int d = ei[N_EDGES + i];
    int pos = g_orow[d] + atomicAdd(&g_ocur[d], 1);
    g_oedge[pos] = i;
}

// per-edge best replica; rows reconstructed from buf2 splits; invn from sumsq
__global__ void k_edge_sim2(const int* __restrict__ ei) {
    int d = (blockIdx.x * blockDim.x + threadIdx.x) >> 5;
    if (d >= N_NODES) return;
    int lane = threadIdx.x & 31;
    int len = g_odeg[d];
    if (len == 0) return;
    int start = g_orow[d];
    float4 a0, b0, a1, b1, a2, b2, a3, b3;
    rec8(g_Ahi2 + ((size_t)1 * N_NODES + d) * 256, g_Alo2 + ((size_t)1 * N_NODES + d) * 256, lane, a0, b0);
    rec8(g_Ahi2 + ((size_t)2 * N_NODES + d) * 256, g_Alo2 + ((size_t)2 * N_NODES + d) * 256, lane, a1, b1);
    rec8(g_Ahi2 + ((size_t)3 * N_NODES + d) * 256, g_Alo2 + ((size_t)3 * N_NODES + d) * 256, lane, a2, b2);
    rec8(g_Ahi2 + ((size_t)4 * N_NODES + d) * 256, g_Alo2 + ((size_t)4 * N_NODES + d) * 256, lane, a3, b3);
    float i0 = 1.f / fmaxf(sqrtf(g_invn[d]), 1e-8f);
    float i1 = 1.f / fmaxf(sqrtf(g_invn[N_NODES + d]), 1e-8f);
    float i2 = 1.f / fmaxf(sqrtf(g_invn[2 * N_NODES + d]), 1e-8f);
    float i3 = 1.f / fmaxf(sqrtf(g_invn[3 * N_NODES + d]), 1e-8f);
    int j = 0;
    for (; j + 2 <= len; j += 2) {
        int e0 = g_oedge[start + j], e1 = g_oedge[start + j + 1];
        int s0 = __ldg(ei + e0), s1 = __ldg(ei + e1);
        float4 fA, fB, gA, gB;
        rec8(g_Ahi2 + (size_t)s0 * 256, g_Alo2 + (size_t)s0 * 256, lane, fA, fB);
        rec8(g_Ahi2 + (size_t)s1 * 256, g_Alo2 + (size_t)s1 * 256, lane, gA, gB);
        float p0 = dot8(fA, fB, a0, b0), q0 = dot8(gA, gB, a0, b0);
        float p1 = dot8(fA, fB, a1, b1), q1 = dot8(gA, gB, a1, b1);
        float p2 = dot8(fA, fB, a2, b2), q2 = dot8(gA, gB, a2, b2);
        float p3 = dot8(fA, fB, a3, b3), q3 = dot8(gA, gB, a3, b3);
#pragma unroll
        for (int o = 16; o; o >>= 1) {
            p0 += __shfl_xor_sync(0xffffffffu, p0, o);
            p1 += __shfl_xor_sync(0xffffffffu, p1, o);
            p2 += __shfl_xor_sync(0xffffffffu, p2, o);
            p3 += __shfl_xor_sync(0xffffffffu, p3, o);
            q0 += __shfl_xor_sync(0xffffffffu, q0, o);
            q1 += __shfl_xor_sync(0xffffffffu, q1, o);
            q2 += __shfl_xor_sync(0xffffffffu, q2, o);
            q3 += __shfl_xor_sync(0xffffffffu, q3, o);
        }
        if (lane == 0) {
            float s0v = p0 * i0, s1v = p1 * i1, s2v = p2 * i2, s3v = p3 * i3;
            float bv = s0v; int bi = 0;
            if (s1v > bv) { bv = s1v; bi = 1; }
            if (s2v > bv) { bv = s2v; bi = 2; }
            if (s3v > bv) { bv = s3v; bi = 3; }
            g_best[e0] = bi;
            float u0v = q0 * i0, u1v = q1 * i1, u2v = q2 * i2, u3v = q3 * i3;
            float cv = u0v; int ci = 0;
            if (u1v > cv) { cv = u1v; ci = 1; }
            if (u2v > cv) { cv = u2v; ci = 2; }
            if (u3v > cv) { cv = u3v; ci = 3; }
            g_best[e1] = ci;
        }
    }
    if (j < len) {
        int e = g_oedge[start + j];
        int s = __ldg(ei + e);
        float4 f0, f1;
        rec8(g_Ahi2 + (size_t)s * 256, g_Alo2 + (size_t)s * 256, lane, f0, f1);
        float p0 = dot8(f0, f1, a0, b0);
        float p1 = dot8(f0, f1, a1, b1);
        float p2 = dot8(f0, f1, a2, b2);
        float p3 = dot8(f0, f1, a3, b3);
#pragma unroll
        for (int o = 16; o; o >>= 1) {
            p0 += __shfl_xor_sync(0xffffffffu, p0, o);
            p1 += __shfl_xor_sync(0xffffffffu, p1, o);
            p2 += __shfl_xor_sync(0xffffffffu, p2, o);
            p3 += __shfl_xor_sync(0xffffffffu, p3, o);
        }
        if (lane == 0) {
            float s0v = p0 * i0, s1v = p1 * i1, s2v = p2 * i2, s3v = p3 * i3;
            float bv = s0v; int bi = 0;
            if (s1v > bv) { bv = s1v; bi = 1; }
            if (s2v > bv) { bv = s2v; bi = 2; }
            if (s3v > bv) { bv = s3v; bi = 3; }
            g_best[e] = bi;
        }
    }
}

__device__ __forceinline__ void decode_edge(const int* __restrict__ ei, int i, int& s, int& d) {
    if (i < N_EDGES) {
        s = ei[i]; d = ei[N_EDGES + i];
    } else if (i < 2 * N_EDGES) {
        int e = i - N_EDGES;
        s = ei[e]; d = ei[N_EDGES + e] + g_best[e] * N_NODES;
    } else {
        int r = i - 2 * N_EDGES;
        int rep = r / N_NODES + 1;
        int n = r - (rep - 1) * N_NODES;
        s = n; d = n + rep * N_NODES;
    }
}

__global__ void k_count(const int* __restrict__ ei) {
    int i = blockIdx.x * blockDim.x + threadIdx.x;
    if (i >= NE_TOT) return;
    int s, d;
    decode_edge(ei, i, s, d);
    if (s != d) atomicAdd(&g_deg[d], 1);
}

// exclusive scan; DODINV: also write g_dinv[i] = rsqrt(in[i]+1)
template<int DODINV>
__global__ void k_scan1(const int* __restrict__ in, int* __restrict__ out, int n) {
    __shared__ int sm[256];
    int tid = threadIdx.x;
    int base = blockIdx.x * SCAN_BLK;
    int loc[4]; int sum = 0;
#pragma unroll
    for (int u = 0; u < 4; u++) {
        int i = base + tid * 4 + u;
        int v = (i < n) ? in[i] : 0;
        if (DODINV && i < n) g_dinv[i] = rsqrtf((float)(v + 1));
        loc[u] = sum; sum += v;
    }
    sm[tid] = sum;
    __syncthreads();
    for (int o = 1; o < 256; o <<= 1) {
        int t = (tid >= o) ? sm[tid - o] : 0;
        __syncthreads();
        sm[tid] += t;
        __syncthreads();
    }
    int pre = tid ? sm[tid - 1] : 0;
#pragma unroll
    for (int u = 0; u < 4; u++) {
        int i = base + tid * 4 + u;
        if (i < n) out[i] = pre + loc[u];
    }
    if (tid == 255) g_blocksum[blockIdx.x] = sm[255];
}

__global__ void k_scan2(int nb) {
    __shared__ int sm[256];
    int tid = threadIdx.x;
    sm[tid] = (tid < nb) ? g_blocksum[tid] : 0;
    __syncthreads();
    for (int o = 1; o < 256; o <<= 1) {
        int t = (tid >= o) ? sm[tid - o] : 0;
        __syncthreads();
        sm[tid] += t;
        __syncthreads();
    }
    if (tid < nb) g_blocksum[tid] = tid ? sm[tid - 1] : 0;
}

__global__ void k_scan3(int* __restrict__ out, int n) {
    int i = blockIdx.x * blockDim.x + threadIdx.x;
    if (i < n) out[i] += g_blocksum[i >> 10];
}

__global__ void k_fill(const int* __restrict__ ei) {
    int i = blockIdx.x * blockDim.x + threadIdx.x;
    if (i >= NE_TOT) return;
    int s, d;
    decode_edge(ei, i, s, d);
    if (s == d) return;
    int pos = g_rowptr[d] + atomicAdd(&g_cursor[d], 1);
    g_csr_src[pos] = s;
}

// OUT: 0 = skip fp32 store; 1 = store rows < N_NODES only; 2 = store all
// edge weight computed inline: dinv[s] * dinv[d]
template<int WS, int OUT>
__global__ void k_aggregate(const float* __restrict__ X, const float* __restrict__ bias,
                            float* __restrict__ Out) {
    int w = (blockIdx.x * blockDim.x + threadIdx.x) >> 5;
    if (w >= N_TOT) return;
    int lane = threadIdx.x & 31;
    int start = g_rowptr[w];
    int len = g_deg[w];
    float dv = g_dinv[w];
    float ws = dv * dv;
    const float4* xd = (const float4*)(X + (size_t)w * 256);
    float4 sa = xd[lane * 2], sb = xd[lane * 2 + 1];
    float acc0 = ws * sa.x, acc1 = ws * sa.y, acc2 = ws * sa.z, acc3 = ws * sa.w;
    float acc4 = ws * sb.x, acc5 = ws * sb.y, acc6 = ws * sb.z, acc7 = ws * sb.w;
    int j = 0;
    for (; j + 4 <= len; j += 4) {
        int s0 = g_csr_src[start + j];
        int s1 = g_csr_src[start + j + 1];
        int s2 = g_csr_src[start + j + 2];
        int s3 = g_csr_src[start + j + 3];
        float w0 = __ldg(g_dinv + s0) * dv;
        float w1 = __ldg(g_dinv + s1) * dv;
        float w2 = __ldg(g_dinv + s2) * dv;
        float w3 = __ldg(g_dinv + s3) * dv;
        const float4* x0 = (const float4*)(X + (size_t)s0 * 256);
        const float4* x1 = (const float4*)(X + (size_t)s1 * 256);
        const float4* x2 = (const float4*)(X + (size_t)s2 * 256);
        const float4* x3 = (const float4*)(X + (size_t)s3 * 256);
        float4 u0 = x0[lane * 2], v0 = x0[lane * 2 + 1];
        float4 u1 = x1[lane * 2], v1 = x1[lane * 2 + 1];
        float4 u2 = x2[lane * 2], v2 = x2[lane * 2 + 1];
        float4 u3 = x3[lane * 2], v3 = x3[lane * 2 + 1];
        acc0 = fmaf(w0, u0.x, acc0); acc1 = fmaf(w0, u0.y, acc1);
        acc2 = fmaf(w0, u0.z, acc2); acc3 = fmaf(w0, u0.w, acc3);
        acc4 = fmaf(w0, v0.x, acc4); acc5 = fmaf(w0, v0.y, acc5);
        acc6 = fmaf(w0, v0.z, acc6); acc7 = fmaf(w0, v0.w, acc7);
        acc0 = fmaf(w1, u1.x, acc0); acc1 = fmaf(w1, u1.y, acc1);
        acc2 = fmaf(w1, u1.z, acc2); acc3 = fmaf(w1, u1.w, acc3);
        acc4 = fmaf(w1, v1.x, acc4); acc5 = fmaf(w1, v1.y, acc5);
        acc6 = fmaf(w1, v1.z, acc6); acc7 = fmaf(w1, v1.w, acc7);
        acc0 = fmaf(w2, u2.x, acc0); acc1 = fmaf(w2, u2.y, acc1);
        acc2 = fmaf(w2, u2.z, acc2); acc3 = fmaf(w2, u2.w, acc3);
        acc4 = fmaf(w2, v2.x, acc4); acc5 = fmaf(w2, v2.y, acc5);
        acc6 = fmaf(w2, v2.z, acc6); acc7 = fmaf(w2, v2.w, acc7);
        acc0 = fmaf(w3, u3.x, acc0); acc1 = fmaf(w3, u3.y, acc1);
        acc2 = fmaf(w3, u3.z, acc2); acc3 = fmaf(w3, u3.w, acc3);
        acc4 = fmaf(w3, v3.x, acc4); acc5 = fmaf(w3, v3.y, acc5);
        acc6 = fmaf(w3, v3.z, acc6); acc7 = fmaf(w3, v3.w, acc7);
    }
    for (; j < len; j++) {
        int s0 = g_csr_src[start + j];
        float w0 = __ldg(g_dinv + s0) * dv;
        const float4* x0 = (const float4*)(X + (size_t)s0 * 256);
        float4 u0 = x0[lane * 2], v0 = x0[lane * 2 + 1];
        acc0 = fmaf(w0, u0.x, acc0); acc1 = fmaf(w0, u0.y, acc1);
        acc2 = fmaf(w0, u0.z, acc2); acc3 = fmaf(w0, u0.w, acc3);
        acc4 = fmaf(w0, v0.x, acc4); acc5 = fmaf(w0, v0.y, acc5);
        acc6 = fmaf(w0, v0.z, acc6); acc7 = fmaf(w0, v0.w, acc7);
    }
    const float4* b4 = (const float4*)bias;
    float4 bb0 = b4[lane * 2], bb1 = b4[lane * 2 + 1];
    float o[8] = {acc0 + bb0.x, acc1 + bb0.y, acc2 + bb0.z, acc3 + bb0.w,
                  acc4 + bb1.x, acc5 + bb1.y, acc6 + bb1.z, acc7 + bb1.w};
    if (OUT == 2 || (OUT == 1 && w < N_NODES)) {
        float4* od = (float4*)(Out + (size_t)w * 256);
        od[lane * 2] = make_float4(o[0], o[1], o[2], o[3]);
        od[lane * 2 + 1] = make_float4(o[4], o[5], o[6], o[7]);
    }
    if (WS) {
        uint32_t hw[4], lw[4];
#pragma unroll
        for (int q = 0; q < 4; q++) {
            __half h0, l0, h1, l1;
            split2(fmaxf(o[q * 2], 0.f), h0, l0);
            split2(fmaxf(o[q * 2 + 1], 0.f), h1, l1);
            hw[q] = hpack2(h0, h1); lw[q] = hpack2(l0, l1);
        }
        size_t so = (size_t)w * 256 + lane * 8;
        *(uint4*)(g_Ahi + so) = make_uint4(hw[0], hw[1], hw[2], hw[3]);
        *(uint4*)(g_Alo + so) = make_uint4(lw[0], lw[1], lw[2], lw[3]);
    }
}

// hyperedge features + H output, reading classes directly
__global__ void k_hyperedge(float* __restrict__ Hout, float* __restrict__ hf) {
    extern __shared__ float acc[];
    int tid = threadIdx.x;
    for (int i = tid; i < 16384; i += 256) acc[i] = 0.f;
    __syncthreads();
    int warp = tid >> 5, lane = tid & 31;
    for (int n = blockIdx.x * 8 + warp; n < N_NODES; n += gridDim.x * 8) {
        int c0 = __ldg(g_cls + n);
        int c1 = __ldg(g_cls + N_NODES + n);
        int c2 = __ldg(g_cls + 2 * N_NODES + n);
        int c3 = __ldg(g_cls + 3 * N_NODES + n);
        int c4 = __ldg(g_cls + 4 * N_NODES + n);
        int h0 = (c0 == lane) + (c1 == lane) + (c2 == lane) + (c3 == lane) + (c4 == lane);
        int l2 = lane + 32;
        int h1 = (c0 == l2) + (c1 == l2) + (c2 == l2) + (c3 == l2) + (c4 == l2);
        Hout[(size_t)n * 64 + lane] = (float)h0;
        Hout[(size_t)n * 64 + lane + 32] = (float)h1;
        unsigned m0 = __ballot_sync(0xffffffffu, h0 > 0);
        unsigned m1 = __ballot_sync(0xffffffffu, h1 > 0);
        const float4* xr = (const float4*)(g_B + (size_t)n * 256);
        float4 a = xr[lane * 2], b = xr[lane * 2 + 1];
        unsigned mm = m0;
        while (mm) {
            int c = __ffs(mm) - 1; mm &= mm - 1;
            float* p = acc + c * 256 + lane * 8;
            atomicAdd(p + 0, a.x); atomicAdd(p + 1, a.y); atomicAdd(p + 2, a.z); atomicAdd(p + 3, a.w);
            atomicAdd(p + 4, b.x); atomicAdd(p + 5, b.y); atomicAdd(p + 6, b.z); atomicAdd(p + 7, b.w);
        }
        mm = m1;
        while (mm) {
            int c = (__ffs(mm) - 1) + 32; mm &= mm - 1;
            float* p = acc + c * 256 + lane * 8;
            atomicAdd(p + 0, a.x); atomicAdd(p + 1, a.y); atomicAdd(p + 2, a.z); atomicAdd(p + 3, a.w);
            atomicAdd(p + 4, b.x); atomicAdd(p + 5, b.y); atomicAdd(p + 6, b.z); atomicAdd(p + 7, b.w);
        }
    }
    __syncthreads();
    for (int i = tid; i < 16384; i += 256) atomicAdd(&hf[i], acc[i]);
}

// ---------------- launch ----------------
extern "C" void kernel_launch(void* const* d_in, const int* in_sizes, int n_in,
                              void* d_out, int out_size) {
    const int*   ei       = (const int*)d_in[0];
    const float* features = (const float*)d_in[1];
    const float* lin_w    = (const float*)d_in[2];
    const float* lin_b    = (const float*)d_in[3];
    const float* gcn0_w   = (const float*)d_in[4];
    const float* gcn0_b   = (const float*)d_in[5];
    const float* gcn1_w   = (const float*)d_in[6];
    const float* gcn1_b   = (const float*)d_in[7];
    const float* lin1_w   = (const float*)d_in[8];
    const float* lin1_b   = (const float*)d_in[9];

    float* out      = (float*)d_out;
    float* H_out    = out;
    float* hf_out   = out + (size_t)N_NODES * NS;
    float* dots_out = hf_out + NS * D;

    float *X, *B, *ZB;
    int *DEG, *ROWPTR, *ODEG, *OROW;
    __half *AH, *AL, *AH2, *AL2, *WH, *WL;
    cudaGetSymbolAddress((void**)&X,  g_X);
    cudaGetSymbolAddress((void**)&B,  g_B);
    cudaGetSymbolAddress((void**)&ZB, g_zerobias);
    cudaGetSymbolAddress((void**)&DEG, g_deg);
    cudaGetSymbolAddress((void**)&ROWPTR, g_rowptr);
    cudaGetSymbolAddress((void**)&ODEG, g_odeg);
    cudaGetSymbolAddress((void**)&OROW, g_orow);
    cudaGetSymbolAddress((void**)&AH, g_Ahi);
    cudaGetSymbolAddress((void**)&AL, g_Alo);
    cudaGetSymbolAddress((void**)&AH2, g_Ahi2);
    cudaGetSymbolAddress((void**)&AL2, g_Alo2);
    cudaGetSymbolAddress((void**)&WH, g_Whi);
    cudaGetSymbolAddress((void**)&WL, g_Wlo);

    cudaFuncSetAttribute(k_hyperedge,  cudaFuncAttributeMaxDynamicSharedMemorySize, 65536);
    cudaFuncSetAttribute(k_mmagemm<0>, cudaFuncAttributeMaxDynamicSharedMemorySize, SMG_BYTES);
    cudaFuncSetAttribute(k_mmagemm<1>, cudaFuncAttributeMaxDynamicSharedMemorySize, SMG_BYTES);
    cudaFuncSetAttribute(k_mmagemm64<0>, cudaFuncAttributeMaxDynamicSharedMemorySize, SM64_BYTES);
    cudaFuncSetAttribute(k_mmagemm64<1>, cudaFuncAttributeMaxDynamicSharedMemorySize, SM64_BYTES);

    const int nb_tot  = (N_TOT + SCAN_BLK - 1) / SCAN_BLK;
    const int nb_node = (N_NODES + SCAN_BLK - 1) / SCAN_BLK;

    // 1: head weight splits, 2: gcn0 split, 3: feature split, 4 (PROFILED): heads GEMM
    k_wsplit<<<dim3(256, 4), 256>>>(lin_w, 0, 256, 65536);
    k_wsplit<<<dim3(256, 1), 256>>>(gcn0_w, 4, 256, 0);
    k_split_both<<<(N_NODES * 64 + 255) / 256, 256>>>((const float4*)features, N_NODES * 64);
    k_mmagemm<1><<<dim3(2, (N_NODES + 127) / 128, 4), 256, SMG_BYTES>>>(
        AH2, AL2, WH, WL, lin_b, X /*unused*/, N_NODES, 65536, 0, 256);

    // remaining weight splits
    k_wsplit<<<dim3(256, 1), 256>>>(gcn1_w, 5, 256, 0);
    k_wsplit<<<dim3(64, 1), 256>>>(lin1_w, 6, 64, 0);

    // original-edge CSR
    k_ocount<<<(N_EDGES + 255) / 256, 256>>>(ei);
    k_scan1<0><<<nb_node, 256>>>(ODEG, OROW, N_NODES);
    k_scan2<<<1, 256>>>(nb_node);
    k_scan3<<<(N_NODES + 255) / 256, 256>>>(OROW, N_NODES);
    k_ofill<<<(N_EDGES + 255) / 256, 256>>>(ei);

    // per-edge best replica (invn rsqrt inline)
    k_edge_sim2<<<(N_NODES * 32 + 255) / 256, 256>>>(ei);

    // augmented-graph CSR (dinv fused into scan1; weights computed in aggregate)
    k_count<<<(NE_TOT + 255) / 256, 256>>>(ei);
    k_scan1<1><<<nb_tot, 256>>>(DEG, ROWPTR, N_TOT);
    k_scan2<<<1, 256>>>(nb_tot);
    k_scan3<<<(N_TOT + 255) / 256, 256>>>(ROWPTR, N_TOT);
    k_fill<<<(NE_TOT + 255) / 256, 256>>>(ei);

    // GCN layer 0 (aggregate fp32 output dead -> OUT=0)
    k_mmagemm<0><<<dim3(2, (N_TOT + 127) / 128, 1), 256, SMG_BYTES>>>(
        AH, AL, WH + 4 * 65536, WL + 4 * 65536, ZB, X, N_TOT, 0, 0, 0);
    k_aggregate<1, 0><<<(N_TOT * 32 + 255) / 256, 256>>>(X, gcn0_b, B);

    // GCN layer 1 (fp32 out only base rows -> OUT=1)
    k_mmagemm<0><<<dim3(2, (N_TOT + 127) / 128, 1), 256, SMG_BYTES>>>(
        AH, AL, WH + 5 * 65536, WL + 5 * 65536, ZB, X, N_TOT, 0, 0, 0);
    k_aggregate<1, 1><<<(N_TOT * 32 + 255) / 256, 256>>>(X, gcn1_b, B);

    // logits mma with fused argmax -> g_cls
    k_mmagemm64<0><<<(N_TOT + 127) / 128, 256, SM64_BYTES>>>(
        AH, AL, WH + 6 * 65536, WL + 6 * 65536, lin1_b, X, N_TOT, 0.f);

    // hyperedge features + H output; split hf to slot 7
    cudaMemsetAsync(hf_out, 0, (size_t)NS * D * sizeof(float));
    k_hyperedge<<<160, 256, 65536>>>(H_out, hf_out);
    k_wsplit_dir<<<64, 256>>>(hf_out, 7, NS * D);

    // dots via mma on raw splits (buf2)
    k_mmagemm64<1><<<(N_TOT + 127) / 128, 256, SM64_BYTES>>>(
        AH2, AL2, WH + 7 * 65536, WL + 7 * 65536, ZB, dots_out, N_TOT, 0.0625f);
}